// round 5
// baseline (speedup 1.0000x reference)
#include <cuda_runtime.h>
#include <math.h>

#define NQ    128
#define ED    256
#define DFFD  512
#define CAMSN 6
#define TSTEP 2
#define CFCH  256
#define HGT   64
#define WID   160
#define PLANE (HGT*WID)           /* 10240 */
#define NPTS  150
#define NTAPS (NPTS*CAMSN*TSTEP)  /* 1800 */
#define NB    128                 /* grid blocks == NQ */
#define NT    256                 /* threads per block */

// ---------------- device scratch ----------------
__device__ float g_q    [NQ*ED];
__device__ float g_h    [NQ*DFFD];
__device__ float g_agg  [NQ*ED];
__device__ float g_mem  [NQ*ED];
__device__ float g_qh   [NQ*ED];
__device__ float g_kT   [ED*NQ];     // transposed K: [256 dims][128 queries]
__device__ float g_vh   [NQ*ED];
__device__ float g_tmp  [NQ*ED];
__device__ float g_featT[(size_t)CAMSN*TSTEP*PLANE*CFCH];  // 126 MB pixel-major

__device__ unsigned g_bar_arrive;
__device__ unsigned g_bar_gen;

// ---------------- shared memory union ----------------
struct SmemGemm   { float As[16][36]; float Ws[16][68]; };
struct SmemSample { float tp[11]; int swarp[8]; int row[NTAPS]; float4 w[NTAPS]; };
struct SmemAttn   { float q[256]; float Ps[8*128]; float ao[256]; float tmpv[256]; float red[8]; };
struct SmemTrans  { float tile[32][33]; };
union Smem {
    SmemGemm   g;
    SmemSample s;
    SmemAttn   a;
    SmemTrans  t;
};

// ---------------- software grid barrier (all 128 CTAs co-resident) ----------------
__device__ __forceinline__ void grid_sync()
{
    __syncthreads();
    if (threadIdx.x == 0) {
        __threadfence();
        unsigned gen = *((volatile unsigned*)&g_bar_gen);
        unsigned t = atomicAdd(&g_bar_arrive, 1u);
        if (t == (unsigned)(gridDim.x - 1)) {
            g_bar_arrive = 0u;
            __threadfence();
            *((volatile unsigned*)&g_bar_gen) = gen + 1u;
        } else {
            while (*((volatile unsigned*)&g_bar_gen) == gen) { }
        }
        __threadfence();
    }
    __syncthreads();
}

// ---------------- tiled GEMM stage: C = act(A @ W^T + b), tiles over blocks ----------------
// QKVMODE=1 routes output: cols<256 -> g_qh (normal), 256..511 -> g_kT (transposed), >=512 -> g_vh
template <int ACT, int QKVMODE>
__device__ void gemm_stage(Smem* sm, const float* __restrict__ A, const float* __restrict__ A2,
                           const float* __restrict__ W, const float* __restrict__ Bb,
                           float* __restrict__ C, int M, int N, int K)
{
    int tilesM = M >> 5, tilesN = N >> 6;
    int nt = tilesM * tilesN;
    int t  = threadIdx.x;
    int tx = t & 15;
    int ty = t >> 4;

    for (int tile = blockIdx.x; tile < nt; tile += gridDim.x) {
        int m0 = (tile % tilesM) << 5;
        int n0 = (tile / tilesM) << 6;
        const float* Asrc = (A2 != nullptr && n0 >= 256) ? A2 : A;

        float acc[2][4] = {{0.f,0.f,0.f,0.f},{0.f,0.f,0.f,0.f}};

        for (int k0 = 0; k0 < K; k0 += 16) {
            if (t < 128) {
                int r = t >> 2, kq = t & 3;
                float4 v = *(const float4*)&Asrc[(m0 + r) * K + k0 + kq * 4];
                sm->g.As[kq*4+0][r] = v.x; sm->g.As[kq*4+1][r] = v.y;
                sm->g.As[kq*4+2][r] = v.z; sm->g.As[kq*4+3][r] = v.w;
            }
            {
                int r = t >> 2, kq = t & 3;
                float4 v = *(const float4*)&W[(n0 + r) * K + k0 + kq * 4];
                sm->g.Ws[kq*4+0][r] = v.x; sm->g.Ws[kq*4+1][r] = v.y;
                sm->g.Ws[kq*4+2][r] = v.z; sm->g.Ws[kq*4+3][r] = v.w;
            }
            __syncthreads();
            #pragma unroll
            for (int k = 0; k < 16; k++) {
                float a0 = sm->g.As[k][ty*2+0];
                float a1 = sm->g.As[k][ty*2+1];
                float4 w = *(const float4*)&sm->g.Ws[k][tx*4];
                acc[0][0] = fmaf(a0, w.x, acc[0][0]);
                acc[0][1] = fmaf(a0, w.y, acc[0][1]);
                acc[0][2] = fmaf(a0, w.z, acc[0][2]);
                acc[0][3] = fmaf(a0, w.w, acc[0][3]);
                acc[1][0] = fmaf(a1, w.x, acc[1][0]);
                acc[1][1] = fmaf(a1, w.y, acc[1][1]);
                acc[1][2] = fmaf(a1, w.z, acc[1][2]);
                acc[1][3] = fmaf(a1, w.w, acc[1][3]);
            }
            __syncthreads();
        }

        int col = n0 + tx * 4;
        float4 bv = *(const float4*)&Bb[col];
        #pragma unroll
        for (int i = 0; i < 2; i++) {
            int row = m0 + ty * 2 + i;
            float4 r;
            r.x = acc[i][0] + bv.x;
            r.y = acc[i][1] + bv.y;
            r.z = acc[i][2] + bv.z;
            r.w = acc[i][3] + bv.w;
            if (ACT) {
                r.x = fmaxf(r.x, 0.f); r.y = fmaxf(r.y, 0.f);
                r.z = fmaxf(r.z, 0.f); r.w = fmaxf(r.w, 0.f);
            }
            if (QKVMODE) {
                if (col < 256) {
                    *(float4*)&g_qh[row * 256 + col] = r;
                } else if (col < 512) {
                    int kd = col - 256;
                    g_kT[(kd+0)*NQ + row] = r.x;
                    g_kT[(kd+1)*NQ + row] = r.y;
                    g_kT[(kd+2)*NQ + row] = r.z;
                    g_kT[(kd+3)*NQ + row] = r.w;
                } else {
                    *(float4*)&g_vh[row * 256 + (col - 512)] = r;
                }
            } else {
                *(float4*)&C[row * N + col] = r;
            }
        }
    }
}

// ---------------- traj head stage 2 (per query, block m): tp = h @ w2^T + b2 ----------------
__device__ void traj2_stage(Smem* sm, int m, const float* __restrict__ w2,
                            const float* __restrict__ b2, float* __restrict__ outp)
{
    int t = threadIdx.x, lane = t & 31, w = t >> 5;
    const float* hr = g_h + m * 512;
    for (int k = w; k < 11; k += 8) {
        float s = 0.f;
        for (int d = lane; d < 512; d += 32)
            s = fmaf(hr[d], w2[k * 512 + d], s);
        #pragma unroll
        for (int o = 16; o; o >>= 1) s += __shfl_xor_sync(0xffffffffu, s, o);
        if (lane == 0) {
            float v = s + b2[k];
            sm->s.tp[k]     = v;
            outp[m * 11 + k] = v;
        }
    }
    __syncthreads();
}

// ---------------- sampling stage (per query, block m); reads sm->s.tp ----------------
__device__ void sample_stage(Smem* sm, int m, const float* __restrict__ calib,
                             const float* __restrict__ ego)
{
    int t = threadIdx.x, lane = t & 31, w = t >> 5;

    // Phase A: project all 1800 taps
    for (int idx = t; idx < NTAPS; idx += NT) {
        int pt  = idx % NPTS;
        int ctc = idx / NPTS;
        int ci  = ctc % CAMSN;
        int tt  = ctc / CAMSN;

        float dt   = ego[tt * 4 + 3] - ego[1 * 4 + 3];
        float ex   = ego[tt * 4 + 0];
        float ey   = ego[tt * 4 + 1];
        float eyaw = ego[tt * 4 + 2];
        float ce = cosf(eyaw), se = sinf(eyaw);

        int face = pt / 25, sub = pt % 25, dim = face >> 1;
        float sign = (face & 1) ? 1.0f : -1.0f;
        float a = -1.0f + 0.5f * (float)(sub / 5);
        float b = -1.0f + 0.5f * (float)(sub % 5);
        float ux, uy, uz;
        if (dim == 0)      { ux = sign; uy = a;    uz = b; }
        else if (dim == 1) { ux = a;    uy = sign; uz = b; }
        else               { ux = a;    uy = b;    uz = sign; }

        float lx = ux * sm->s.tp[8], ly = uy * sm->s.tp[9], lz = uz * sm->s.tp[10];
        float yaw = sm->s.tp[7];
        float cyw = cosf(yaw), syw = sinf(yaw);
        float rx = lx * cyw - ly * syw;
        float ry = lx * syw + ly * cyw;
        float cx = sm->s.tp[0] + sm->s.tp[3] * dt + 0.5f * sm->s.tp[5] * dt * dt;
        float cy = sm->s.tp[1] + sm->s.tp[4] * dt + 0.5f * sm->s.tp[6] * dt * dt;
        float wx = rx + cx, wy = ry + cy, wz = lz + sm->s.tp[2];
        float pxr = wx - ex, pyr = wy - ey;
        float gx =  pxr * ce + pyr * se;
        float gy = -pxr * se + pyr * ce;

        const float* cal = calib + ci * 8;
        float fx = cal[0], fy = cal[1], cx0 = cal[2], cy0 = cal[3];
        float txc = cal[4], tyc = cal[5], tzc = cal[6], cyaw = cal[7];
        float px = gx - txc, py = gy - tyc, pz = wz - tzc;
        float cc = cosf(cyaw), sc = sinf(cyaw);
        float fwd  =  px * cc + py * sc;
        float left = -px * sc + py * cc;
        float zc = fwd, xc = -left, yc = -pz;
        float zs = fmaxf(zc, 0.1f);
        float u = fx * xc / zs + cx0;
        float v = fy * yc / zs + cy0;
        bool valid = (zc > 0.1f) && (u >= 0.f) && (u < 1.f) && (v >= 0.f) && (v < 1.f);

        if (valid) {
            float pxi = u * 159.0f;
            float pyi = v * 63.0f;
            float x0f = floorf(pxi), y0f = floorf(pyi);
            int x0 = (int)x0f, y0 = (int)y0f;
            float wxk = pxi - x0f, wyk = pyi - y0f;
            sm->s.row[idx] = (ci * TSTEP + tt) * PLANE + y0 * WID + x0;
            sm->s.w[idx] = make_float4((1.f - wxk) * (1.f - wyk),
                                       wxk * (1.f - wyk),
                                       (1.f - wxk) * wyk,
                                       wxk * wyk);
        } else {
            sm->s.row[idx] = -1;
        }
    }
    __syncthreads();

    // Phase A2: deterministic order-preserving compaction of valid taps.
    // Thread t owns contiguous chunk [t*8, t*8+8) (2048 >= 1800).
    int base = t * 8;
    int rloc[8];
    float4 wloc[8];
    unsigned cnt = 0;
    #pragma unroll
    for (int j = 0; j < 8; j++) {
        int idx = base + j;
        int rv = (idx < NTAPS) ? sm->s.row[idx] : -1;
        rloc[j] = rv;
        if (rv >= 0) { wloc[j] = sm->s.w[idx]; cnt++; }
    }
    // warp inclusive scan of counts
    unsigned incl = cnt;
    #pragma unroll
    for (int o = 1; o < 32; o <<= 1) {
        unsigned n = __shfl_up_sync(0xffffffffu, incl, o);
        if (lane >= o) incl += n;
    }
    if (lane == 31) sm->s.swarp[w] = (int)incl;
    __syncthreads();
    unsigned wbase = 0, nvalid = 0;
    #pragma unroll
    for (int ww = 0; ww < 8; ww++) {
        unsigned c = (unsigned)sm->s.swarp[ww];
        if (ww < w) wbase += c;
        nvalid += c;
    }
    unsigned off = wbase + incl - cnt;
    __syncthreads();   // everyone staged their chunk; safe to overwrite
    #pragma unroll
    for (int j = 0; j < 8; j++) {
        if (rloc[j] >= 0) {
            sm->s.row[off] = rloc[j];
            sm->s.w[off]   = wloc[j];
            off++;
        }
    }
    __syncthreads();

    // Phase B: branch-free accumulation over compacted taps; thread = channel.
    float acc = 0.f;
    int nv = (int)nvalid;
    #pragma unroll 4
    for (int i = 0; i < nv; i++) {
        int row = sm->s.row[i];
        float4 w4 = sm->s.w[i];
        const float* p = g_featT + (size_t)row * CFCH + t;
        float f00 = p[0];
        float f01 = p[CFCH];
        float f10 = p[WID * CFCH];
        float f11 = p[WID * CFCH + CFCH];
        acc = fmaf(f00, w4.x, acc);
        acc = fmaf(f01, w4.y, acc);
        acc = fmaf(f10, w4.z, acc);
        acc = fmaf(f11, w4.w, acc);
    }
    g_agg[m * ED + t] = acc * (1.0f / 1800.0f);
}

// ---------------- LayerNorm helper (block = one row of 256) ----------------
__device__ __forceinline__ float ln_norm(Smem* sm, float x, float gg, float bb)
{
    int t = threadIdx.x, lane = t & 31, w = t >> 5;
    float v = x;
    #pragma unroll
    for (int o = 16; o; o >>= 1) v += __shfl_xor_sync(0xffffffffu, v, o);
    if (lane == 0) sm->a.red[w] = v;
    __syncthreads();
    float tot = 0.f;
    #pragma unroll
    for (int kk = 0; kk < 8; kk++) tot += sm->a.red[kk];
    float mean = tot * (1.0f / 256.0f);
    float xm = x - mean;
    __syncthreads();
    float v2 = xm * xm;
    #pragma unroll
    for (int o = 16; o; o >>= 1) v2 += __shfl_xor_sync(0xffffffffu, v2, o);
    if (lane == 0) sm->a.red[w] = v2;
    __syncthreads();
    float tv = 0.f;
    #pragma unroll
    for (int kk = 0; kk < 8; kk++) tv += sm->a.red[kk];
    float var = tv * (1.0f / 256.0f);
    return xm * rsqrtf(var + 1e-5f) * gg + bb;
}

// ---------------- attention + out-proj + residual-LN (per query, block m) ----------------
__device__ void attn_stage(Smem* sm, int m,
                           const float* __restrict__ Wo, const float* __restrict__ bo,
                           const float* __restrict__ lng, const float* __restrict__ lnb)
{
    int t = threadIdx.x, lane = t & 31, w = t >> 5;

    sm->a.q[t] = g_qh[m * 256 + t];
    __syncthreads();

    // scores: warp w = head; K transposed [dim][query] -> lane-coalesced
    const float* kTh = g_kT + (w * 32) * NQ;
    float s[4];
    #pragma unroll
    for (int jj = 0; jj < 4; jj++) {
        int j = jj * 32 + lane;
        float a = 0.f;
        #pragma unroll
        for (int d = 0; d < 32; d++)
            a = fmaf(sm->a.q[w * 32 + d], kTh[d * NQ + j], a);
        s[jj] = a * 0.17677669529663687f;   // 1/sqrt(32)
    }
    float mx = fmaxf(fmaxf(s[0], s[1]), fmaxf(s[2], s[3]));
    #pragma unroll
    for (int o = 16; o; o >>= 1) mx = fmaxf(mx, __shfl_xor_sync(0xffffffffu, mx, o));
    float ssum = 0.f;
    #pragma unroll
    for (int jj = 0; jj < 4; jj++) { s[jj] = expf(s[jj] - mx); ssum += s[jj]; }
    #pragma unroll
    for (int o = 16; o; o >>= 1) ssum += __shfl_xor_sync(0xffffffffu, ssum, o);
    float inv = 1.0f / ssum;
    #pragma unroll
    for (int jj = 0; jj < 4; jj++) sm->a.Ps[w * 128 + jj * 32 + lane] = s[jj] * inv;
    __syncwarp();

    // AV: lane = channel within head; V row-major -> lane-coalesced
    float ov = 0.f;
    for (int j = 0; j < 128; j++)
        ov = fmaf(sm->a.Ps[w * 128 + j], g_vh[j * 256 + w * 32 + lane], ov);
    sm->a.ao[w * 32 + lane] = ov;
    __syncthreads();

    // out-projection: warp w computes 32 output cols via lane-strided dots
    for (int ci = 0; ci < 32; ci++) {
        int c = w * 32 + ci;
        const float* wr = Wo + c * 256;
        float acc = 0.f;
        #pragma unroll
        for (int kk = lane; kk < 256; kk += 32)
            acc = fmaf(sm->a.ao[kk], wr[kk], acc);
        #pragma unroll
        for (int o = 16; o; o >>= 1) acc += __shfl_xor_sync(0xffffffffu, acc, o);
        if (lane == 0) sm->a.tmpv[c] = acc + bo[c];
    }
    __syncthreads();

    float x = g_q[m * 256 + t] + sm->a.tmpv[t];
    float r = ln_norm(sm, x, lng[t], lnb[t]);
    g_q[m * 256 + t] = r;
}

// ---------------- standalone residual-LN (per query) ----------------
__device__ void resln_stage(Smem* sm, int m, const float* __restrict__ add,
                            const float* __restrict__ lng, const float* __restrict__ lnb)
{
    int t = threadIdx.x;
    float x = g_q[m * 256 + t] + add[m * 256 + t];
    float r = ln_norm(sm, x, lng[t], lnb[t]);
    g_q[m * 256 + t] = r;
}

// ---------------- the persistent mega-kernel ----------------
__global__ void __launch_bounds__(NT, 1)
decoder_kernel(const float* __restrict__ features, const float* __restrict__ calib,
               const float* __restrict__ ego, const float* __restrict__ queries,
               const float* __restrict__ tw1, const float* __restrict__ tb1,
               const float* __restrict__ tw2, const float* __restrict__ tb2,
               const float* __restrict__ fmw1, const float* __restrict__ fmb1,
               const float* __restrict__ fmw2, const float* __restrict__ fmb2,
               const float* __restrict__ saiw, const float* __restrict__ saib,
               const float* __restrict__ saow, const float* __restrict__ saob,
               const float* __restrict__ caiw, const float* __restrict__ caib,
               const float* __restrict__ caow, const float* __restrict__ caob,
               const float* __restrict__ l1w,  const float* __restrict__ l1b,
               const float* __restrict__ l2w,  const float* __restrict__ l2b,
               const float* __restrict__ n1g,  const float* __restrict__ n1b,
               const float* __restrict__ n2g,  const float* __restrict__ n2b,
               const float* __restrict__ n3g,  const float* __restrict__ n3b,
               float* __restrict__ out)
{
    __shared__ Smem sm;
    int m = blockIdx.x;
    int t = threadIdx.x;

    // init: copy queries -> q
    g_q[m * 256 + t] = queries[m * 256 + t];

    // transpose features [ct][C][pix] -> featT [ct][pix][C], tiles over blocks
    {
        const int PT = PLANE / 32;           // 320
        const int CT = CFCH / 32;            // 8
        const int NTILE = CAMSN * TSTEP * PT * CT;  // 30720
        int tx = t & 31, ty = t >> 5;        // 32 x 8
        for (int tile = blockIdx.x; tile < NTILE; tile += gridDim.x) {
            int ct = tile / (PT * CT);
            int rem = tile % (PT * CT);
            int p0 = (rem % PT) * 32;
            int c0 = (rem / PT) * 32;
            const float* in  = features + (size_t)ct * CFCH * PLANE;
            float*       op  = g_featT  + (size_t)ct * CFCH * PLANE;
            #pragma unroll
            for (int i = 0; i < 32; i += 8)
                sm.t.tile[ty + i][tx] = in[(size_t)(c0 + ty + i) * PLANE + p0 + tx];
            __syncthreads();
            #pragma unroll
            for (int i = 0; i < 32; i += 8)
                op[(size_t)(p0 + ty + i) * CFCH + c0 + tx] = sm.t.tile[tx][ty + i];
            __syncthreads();
        }
    }
    grid_sync();

    for (int li = 0; li < 6; li++) {
        // traj head stage 1
        gemm_stage<1,0>(&sm, g_q, nullptr, tw1, tb1, g_h, 128, 512, 256);
        grid_sync();
        // per-query: traj head stage 2 + sampling
        traj2_stage(&sm, m, tw2, tb2, out + li * 1408);
        sample_stage(&sm, m, calib, ego);
        grid_sync();
        // feature MLP
        gemm_stage<1,0>(&sm, g_agg, nullptr, fmw1, fmb1, g_h, 128, 512, 256);
        grid_sync();
        gemm_stage<0,0>(&sm, g_h, nullptr, fmw2, fmb2, g_mem, 128, 256, 512);
        grid_sync();
        // self-attention
        gemm_stage<0,1>(&sm, g_q, nullptr, saiw + li * 768 * 256, saib + li * 768,
                        nullptr, 128, 768, 256);
        grid_sync();
        attn_stage(&sm, m, saow + li * 256 * 256, saob + li * 256,
                   n1g + li * 256, n1b + li * 256);
        grid_sync();
        // cross-attention (k/v from mem via A2 switch at col>=256)
        gemm_stage<0,1>(&sm, g_q, g_mem, caiw + li * 768 * 256, caib + li * 768,
                        nullptr, 128, 768, 256);
        grid_sync();
        attn_stage(&sm, m, caow + li * 256 * 256, caob + li * 256,
                   n2g + li * 256, n2b + li * 256);
        grid_sync();
        // FFN
        gemm_stage<1,0>(&sm, g_q, nullptr, l1w + li * 512 * 256, l1b + li * 512,
                        g_h, 128, 512, 256);
        grid_sync();
        gemm_stage<0,0>(&sm, g_h, nullptr, l2w + li * 256 * 512, l2b + li * 256,
                        g_tmp, 128, 256, 512);
        grid_sync();
        resln_stage(&sm, m, g_tmp, n3g + li * 256, n3b + li * 256);
        grid_sync();
    }

    // final traj head
    gemm_stage<1,0>(&sm, g_q, nullptr, tw1, tb1, g_h, 128, 512, 256);
    grid_sync();
    traj2_stage(&sm, m, tw2, tb2, out + 6 * 1408);
}

// ---------------- host orchestration: one launch ----------------
extern "C" void kernel_launch(void* const* d_in, const int* in_sizes, int n_in,
                              void* d_out, int out_size)
{
    const float* features = (const float*)d_in[0];
    const float* calib    = (const float*)d_in[1];
    const float* ego      = (const float*)d_in[2];
    const float* queries  = (const float*)d_in[3];
    const float* tw1  = (const float*)d_in[5];
    const float* tb1  = (const float*)d_in[6];
    const float* tw2  = (const float*)d_in[7];
    const float* tb2  = (const float*)d_in[8];
    const float* fmw1 = (const float*)d_in[9];
    const float* fmb1 = (const float*)d_in[10];
    const float* fmw2 = (const float*)d_in[11];
    const float* fmb2 = (const float*)d_in[12];
    const float* saiw = (const float*)d_in[13];
    const float* saib = (const float*)d_in[14];
    const float* saow = (const float*)d_in[15];
    const float* saob = (const float*)d_in[16];
    const float* caiw = (const float*)d_in[17];
    const float* caib = (const float*)d_in[18];
    const float* caow = (const float*)d_in[19];
    const float* caob = (const float*)d_in[20];
    const float* l1w  = (const float*)d_in[21];
    const float* l1b  = (const float*)d_in[22];
    const float* l2w  = (const float*)d_in[23];
    const float* l2b  = (const float*)d_in[24];
    const float* n1g  = (const float*)d_in[25];
    const float* n1b  = (const float*)d_in[26];
    const float* n2g  = (const float*)d_in[27];
    const float* n2b  = (const float*)d_in[28];
    const float* n3g  = (const float*)d_in[29];
    const float* n3b  = (const float*)d_in[30];
    float* out = (float*)d_out;

    decoder_kernel<<<NB, NT>>>(features, calib, ego, queries,
                               tw1, tb1, tw2, tb2,
                               fmw1, fmb1, fmw2, fmb2,
                               saiw, saib, saow, saob,
                               caiw, caib, caow, caob,
                               l1w, l1b, l2w, l2b,
                               n1g, n1b, n2g, n2b, n3g, n3b,
                               out);
}

// round 6
// speedup vs baseline: 1.2464x; 1.2464x over previous
#include <cuda_runtime.h>
#include <cuda_fp16.h>
#include <math.h>

#define NQ    128
#define ED    256
#define DFFD  512
#define CAMSN 6
#define TSTEP 2
#define CFCH  256
#define HGT   64
#define WID   160
#define PLANE (HGT*WID)           /* 10240 */
#define NPTS  150
#define NTAPS (NPTS*CAMSN*TSTEP)  /* 1800 */
#define NB    128
#define NT    256

// ---------------- device scratch ----------------
__device__ float  g_q    [NQ*ED];
__device__ float  g_h    [NQ*DFFD];
__device__ float  g_agg  [NQ*ED];
__device__ float  g_mem  [NQ*ED];
__device__ float  g_qh   [NQ*ED];
__device__ float  g_kT   [ED*NQ];     // transposed K: [256 dims][128 queries]
__device__ float  g_vh   [NQ*ED];
__device__ float  g_attno[NQ*ED];
__device__ float  g_tmp  [NQ*ED];
__device__ __half g_featT[(size_t)CAMSN*TSTEP*PLANE*CFCH];  // 63 MB pixel-major fp16

__device__ unsigned g_bar_arrive;
__device__ unsigned g_bar_gen;

// ---------------- shared memory union ----------------
struct SmemGemm   { float As[2][32][20]; float Ws[2][32][68]; };
struct SmemSample { float tp[11]; int row[NTAPS]; float4 w[NTAPS]; float2 buf[128]; };
struct SmemAttn   { float q[256]; float Ps[8*128]; float red[8]; };
struct SmemTrans  { float tile[32][33]; };
union Smem {
    SmemGemm   g;
    SmemSample s;
    SmemAttn   a;
    SmemTrans  t;
};

// ---------------- software grid barrier (128 CTAs co-resident) ----------------
__device__ __forceinline__ void grid_sync()
{
    __syncthreads();
    if (threadIdx.x == 0) {
        __threadfence();
        unsigned gen = *((volatile unsigned*)&g_bar_gen);
        unsigned t = atomicAdd(&g_bar_arrive, 1u);
        if (t == (unsigned)(gridDim.x - 1)) {
            g_bar_arrive = 0u;
            __threadfence();
            *((volatile unsigned*)&g_bar_gen) = gen + 1u;
        } else {
            while (*((volatile unsigned*)&g_bar_gen) == gen) { }
        }
        __threadfence();
    }
    __syncthreads();
}

// ---------------- one 16x64 GEMM tile, double-buffered K-chunks of 32 ----------------
// C[m0..m0+16, n0..n0+64] = act(A[m0:,:K] @ W[n0:,:K]^T + Bb)
// QKV=1 routes: col<256 -> g_qh, col<512 -> g_kT (transposed), else -> g_vh
template <int ACT, int QKV>
__device__ void gemm_tile(Smem* sm, const float* __restrict__ A,
                          const float* __restrict__ W, const float* __restrict__ Bb,
                          float* __restrict__ C, int K, int ldc, int m0, int n0)
{
    int t  = threadIdx.x;
    int tx = t & 15;
    int ty = t >> 4;
    float acc[4] = {0.f, 0.f, 0.f, 0.f};

#define LOAD_CHUNK(k0, b) do {                                                  \
        if (t < 128) {                                                          \
            int r = t >> 3, kq = t & 7;                                         \
            float4 v = *(const float4*)&A[(m0 + r) * K + (k0) + kq * 4];        \
            sm->g.As[b][kq*4+0][r] = v.x; sm->g.As[b][kq*4+1][r] = v.y;         \
            sm->g.As[b][kq*4+2][r] = v.z; sm->g.As[b][kq*4+3][r] = v.w;         \
        }                                                                        \
        {                                                                        \
            int r = t >> 2, kq = t & 3;                                         \
            float4 v0 = *(const float4*)&W[(n0 + r) * K + (k0) + kq * 4];       \
            float4 v1 = *(const float4*)&W[(n0 + r) * K + (k0) + 16 + kq * 4];  \
            sm->g.Ws[b][kq*4+0][r] = v0.x; sm->g.Ws[b][kq*4+1][r] = v0.y;       \
            sm->g.Ws[b][kq*4+2][r] = v0.z; sm->g.Ws[b][kq*4+3][r] = v0.w;       \
            sm->g.Ws[b][16+kq*4+0][r] = v1.x; sm->g.Ws[b][16+kq*4+1][r] = v1.y; \
            sm->g.Ws[b][16+kq*4+2][r] = v1.z; sm->g.Ws[b][16+kq*4+3][r] = v1.w; \
        }                                                                        \
    } while (0)

    LOAD_CHUNK(0, 0);
    __syncthreads();
    int p = 0;
    for (int k0 = 0; k0 < K; k0 += 32) {
        if (k0 + 32 < K) LOAD_CHUNK(k0 + 32, p ^ 1);
        #pragma unroll
        for (int k = 0; k < 32; k++) {
            float a  = sm->g.As[p][k][ty];
            float4 w = *(const float4*)&sm->g.Ws[p][k][tx*4];
            acc[0] = fmaf(a, w.x, acc[0]);
            acc[1] = fmaf(a, w.y, acc[1]);
            acc[2] = fmaf(a, w.z, acc[2]);
            acc[3] = fmaf(a, w.w, acc[3]);
        }
        __syncthreads();
        p ^= 1;
    }
#undef LOAD_CHUNK

    int row = m0 + ty;
    int col = n0 + tx * 4;
    float4 bv = *(const float4*)&Bb[col];
    float4 r;
    r.x = acc[0] + bv.x;
    r.y = acc[1] + bv.y;
    r.z = acc[2] + bv.z;
    r.w = acc[3] + bv.w;
    if (ACT) {
        r.x = fmaxf(r.x, 0.f); r.y = fmaxf(r.y, 0.f);
        r.z = fmaxf(r.z, 0.f); r.w = fmaxf(r.w, 0.f);
    }
    if (QKV) {
        if (col < 256) {
            *(float4*)&g_qh[row * 256 + col] = r;
        } else if (col < 512) {
            int kd = col - 256;
            g_kT[(kd+0)*NQ + row] = r.x;
            g_kT[(kd+1)*NQ + row] = r.y;
            g_kT[(kd+2)*NQ + row] = r.z;
            g_kT[(kd+3)*NQ + row] = r.w;
        } else {
            *(float4*)&g_vh[row * 256 + (col - 512)] = r;
        }
    } else {
        *(float4*)&C[row * ldc + col] = r;
    }
}

// ---------------- attention core (per query m): scores+softmax+AV -> g_attno ----------------
__device__ void attn_core(Smem* sm, int m)
{
    int t = threadIdx.x, lane = t & 31, w = t >> 5;

    sm->a.q[t] = g_qh[m * 256 + t];
    __syncthreads();

    const float* kTh = g_kT + (w * 32) * NQ;
    float s[4];
    #pragma unroll
    for (int jj = 0; jj < 4; jj++) {
        int j = jj * 32 + lane;
        float a = 0.f;
        #pragma unroll
        for (int d = 0; d < 32; d++)
            a = fmaf(sm->a.q[w * 32 + d], kTh[d * NQ + j], a);
        s[jj] = a * 0.17677669529663687f;   // 1/sqrt(32)
    }
    float mx = fmaxf(fmaxf(s[0], s[1]), fmaxf(s[2], s[3]));
    #pragma unroll
    for (int o = 16; o; o >>= 1) mx = fmaxf(mx, __shfl_xor_sync(0xffffffffu, mx, o));
    float ssum = 0.f;
    #pragma unroll
    for (int jj = 0; jj < 4; jj++) { s[jj] = expf(s[jj] - mx); ssum += s[jj]; }
    #pragma unroll
    for (int o = 16; o; o >>= 1) ssum += __shfl_xor_sync(0xffffffffu, ssum, o);
    float inv = 1.0f / ssum;
    #pragma unroll
    for (int jj = 0; jj < 4; jj++) sm->a.Ps[w * 128 + jj * 32 + lane] = s[jj] * inv;
    __syncwarp();

    float ov = 0.f;
    for (int j = 0; j < 128; j++)
        ov = fmaf(sm->a.Ps[w * 128 + j], g_vh[j * 256 + w * 32 + lane], ov);
    g_attno[m * 256 + w * 32 + lane] = ov;
    __syncthreads();
}

// ---------------- traj head stage 2 (per query m) ----------------
__device__ void traj2_stage(Smem* sm, int m, const float* __restrict__ w2,
                            const float* __restrict__ b2, float* __restrict__ outp)
{
    int t = threadIdx.x, lane = t & 31, w = t >> 5;
    const float* hr = g_h + m * 512;
    for (int k = w; k < 11; k += 8) {
        float s = 0.f;
        for (int d = lane; d < 512; d += 32)
            s = fmaf(hr[d], w2[k * 512 + d], s);
        #pragma unroll
        for (int o = 16; o; o >>= 1) s += __shfl_xor_sync(0xffffffffu, s, o);
        if (lane == 0) {
            float v = s + b2[k];
            sm->s.tp[k]      = v;
            outp[m * 11 + k] = v;
        }
    }
    __syncthreads();
}

// ---------------- sampling (per query m); fp16 features, 2 taps in parallel ----------------
__device__ void sample_stage(Smem* sm, int m, const float* __restrict__ calib,
                             const float* __restrict__ ego)
{
    int t = threadIdx.x;

    // Phase A: project all 1800 taps (invalid -> row 0, weight 0: branch-free Phase B)
    for (int idx = t; idx < NTAPS; idx += NT) {
        int pt  = idx % NPTS;
        int ctc = idx / NPTS;
        int ci  = ctc % CAMSN;
        int tt  = ctc / CAMSN;

        float dt   = ego[tt * 4 + 3] - ego[1 * 4 + 3];
        float ex   = ego[tt * 4 + 0];
        float ey   = ego[tt * 4 + 1];
        float eyaw = ego[tt * 4 + 2];
        float ce = cosf(eyaw), se = sinf(eyaw);

        int face = pt / 25, sub = pt % 25, dim = face >> 1;
        float sign = (face & 1) ? 1.0f : -1.0f;
        float a = -1.0f + 0.5f * (float)(sub / 5);
        float b = -1.0f + 0.5f * (float)(sub % 5);
        float ux, uy, uz;
        if (dim == 0)      { ux = sign; uy = a;    uz = b; }
        else if (dim == 1) { ux = a;    uy = sign; uz = b; }
        else               { ux = a;    uy = b;    uz = sign; }

        float lx = ux * sm->s.tp[8], ly = uy * sm->s.tp[9], lz = uz * sm->s.tp[10];
        float yaw = sm->s.tp[7];
        float cyw = cosf(yaw), syw = sinf(yaw);
        float rx = lx * cyw - ly * syw;
        float ry = lx * syw + ly * cyw;
        float cx = sm->s.tp[0] + sm->s.tp[3] * dt + 0.5f * sm->s.tp[5] * dt * dt;
        float cy = sm->s.tp[1] + sm->s.tp[4] * dt + 0.5f * sm->s.tp[6] * dt * dt;
        float wx = rx + cx, wy = ry + cy, wz = lz + sm->s.tp[2];
        float pxr = wx - ex, pyr = wy - ey;
        float gx =  pxr * ce + pyr * se;
        float gy = -pxr * se + pyr * ce;

        const float* cal = calib + ci * 8;
        float fx = cal[0], fy = cal[1], cx0 = cal[2], cy0 = cal[3];
        float txc = cal[4], tyc = cal[5], tzc = cal[6], cyaw = cal[7];
        float px = gx - txc, py = gy - tyc, pz = wz - tzc;
        float cc = cosf(cyaw), sc = sinf(cyaw);
        float fwd  =  px * cc + py * sc;
        float left = -px * sc + py * cc;
        float zc = fwd, xc = -left, yc = -pz;
        float zs = fmaxf(zc, 0.1f);
        float u = fx * xc / zs + cx0;
        float v = fy * yc / zs + cy0;
        bool valid = (zc > 0.1f) && (u >= 0.f) && (u < 1.f) && (v >= 0.f) && (v < 1.f);

        if (valid) {
            float pxi = u * 159.0f;
            float pyi = v * 63.0f;
            float x0f = floorf(pxi), y0f = floorf(pyi);
            int x0 = (int)x0f, y0 = (int)y0f;
            float wxk = pxi - x0f, wyk = pyi - y0f;
            sm->s.row[idx] = (ci * TSTEP + tt) * PLANE + y0 * WID + x0;
            sm->s.w[idx] = make_float4((1.f - wxk) * (1.f - wyk),
                                       wxk * (1.f - wyk),
                                       (1.f - wxk) * wyk,
                                       wxk * wyk);
        } else {
            sm->s.row[idx] = 0;
            sm->s.w[idx]   = make_float4(0.f, 0.f, 0.f, 0.f);
        }
    }
    __syncthreads();

    // Phase B: two 128-thread halves each take alternate taps; thread = channel pair
    int hfl = t >> 7;          // 0 or 1
    int j   = t & 127;         // channel-pair index (channels 2j, 2j+1)
    float accx = 0.f, accy = 0.f;
    const __half2* fb = (const __half2*)g_featT;
    #pragma unroll 2
    for (int i = hfl; i < NTAPS; i += 2) {
        int row = sm->s.row[i];
        float4 w4 = sm->s.w[i];
        const __half2* p = fb + (size_t)row * 128 + j;
        float2 f00 = __half22float2(p[0]);
        float2 f01 = __half22float2(p[128]);
        float2 f10 = __half22float2(p[WID * 128]);
        float2 f11 = __half22float2(p[(WID + 1) * 128]);
        accx = fmaf(f00.x, w4.x, accx);
        accx = fmaf(f01.x, w4.y, accx);
        accx = fmaf(f10.x, w4.z, accx);
        accx = fmaf(f11.x, w4.w, accx);
        accy = fmaf(f00.y, w4.x, accy);
        accy = fmaf(f01.y, w4.y, accy);
        accy = fmaf(f10.y, w4.z, accy);
        accy = fmaf(f11.y, w4.w, accy);
    }
    if (hfl == 0) sm->s.buf[j] = make_float2(accx, accy);
    __syncthreads();
    if (hfl == 1) {
        float2 r = sm->s.buf[j];
        g_agg[m * 256 + 2*j]     = (r.x + accx) * (1.0f / 1800.0f);
        g_agg[m * 256 + 2*j + 1] = (r.y + accy) * (1.0f / 1800.0f);
    }
    __syncthreads();
}

// ---------------- residual add + LayerNorm (per query m, in-place on g_q) ----------------
__device__ void resln_stage(Smem* sm, int m, const float* __restrict__ add,
                            const float* __restrict__ lng, const float* __restrict__ lnb)
{
    int t = threadIdx.x, lane = t & 31, w = t >> 5;
    float x = g_q[m * 256 + t] + add[m * 256 + t];

    float v = x;
    #pragma unroll
    for (int o = 16; o; o >>= 1) v += __shfl_xor_sync(0xffffffffu, v, o);
    if (lane == 0) sm->a.red[w] = v;
    __syncthreads();
    float tot = 0.f;
    #pragma unroll
    for (int kk = 0; kk < 8; kk++) tot += sm->a.red[kk];
    float mean = tot * (1.0f / 256.0f);
    float xm = x - mean;
    __syncthreads();
    float v2 = xm * xm;
    #pragma unroll
    for (int o = 16; o; o >>= 1) v2 += __shfl_xor_sync(0xffffffffu, v2, o);
    if (lane == 0) sm->a.red[w] = v2;
    __syncthreads();
    float tv = 0.f;
    #pragma unroll
    for (int kk = 0; kk < 8; kk++) tv += sm->a.red[kk];
    float var = tv * (1.0f / 256.0f);
    g_q[m * 256 + t] = xm * rsqrtf(var + 1e-5f) * lng[t] + lnb[t];
    __syncthreads();
}

// ---------------- persistent mega-kernel ----------------
__global__ void __launch_bounds__(NT, 1)
decoder_kernel(const float* __restrict__ features, const float* __restrict__ calib,
               const float* __restrict__ ego, const float* __restrict__ queries,
               const float* __restrict__ tw1, const float* __restrict__ tb1,
               const float* __restrict__ tw2, const float* __restrict__ tb2,
               const float* __restrict__ fmw1, const float* __restrict__ fmb1,
               const float* __restrict__ fmw2, const float* __restrict__ fmb2,
               const float* __restrict__ saiw, const float* __restrict__ saib,
               const float* __restrict__ saow, const float* __restrict__ saob,
               const float* __restrict__ caiw, const float* __restrict__ caib,
               const float* __restrict__ caow, const float* __restrict__ caob,
               const float* __restrict__ l1w,  const float* __restrict__ l1b,
               const float* __restrict__ l2w,  const float* __restrict__ l2b,
               const float* __restrict__ n1g,  const float* __restrict__ n1b,
               const float* __restrict__ n2g,  const float* __restrict__ n2b,
               const float* __restrict__ n3g,  const float* __restrict__ n3b,
               float* __restrict__ out)
{
    __shared__ Smem sm;
    int m = blockIdx.x;
    int t = threadIdx.x;

    // prologue: copy queries; transpose features -> fp16 pixel-major
    g_q[m * 256 + t] = queries[m * 256 + t];
    {
        const int PT = PLANE / 32;                   // 320
        const int CT = CFCH / 32;                    // 8
        const int NTILE = CAMSN * TSTEP * PT * CT;   // 30720
        int tx = t & 31, ty = t >> 5;
        for (int tile = blockIdx.x; tile < NTILE; tile += gridDim.x) {
            int ct  = tile / (PT * CT);
            int rem = tile % (PT * CT);
            int p0 = (rem % PT) * 32;
            int c0 = (rem / PT) * 32;
            const float* in = features + (size_t)ct * CFCH * PLANE;
            __half*      op = g_featT  + (size_t)ct * CFCH * PLANE;
            #pragma unroll
            for (int i = 0; i < 32; i += 8)
                sm.t.tile[ty + i][tx] = in[(size_t)(c0 + ty + i) * PLANE + p0 + tx];
            __syncthreads();
            #pragma unroll
            for (int i = 0; i < 32; i += 8)
                op[(size_t)(p0 + ty + i) * CFCH + c0 + tx] = __float2half_rn(sm.t.tile[tx][ty + i]);
            __syncthreads();
        }
    }
    grid_sync();

    for (int li = 0; li < 6; li++) {
        const float* saiw_l = saiw + li * 768 * 256;
        const float* saib_l = saib + li * 768;
        const float* caiw_l = caiw + li * 768 * 256;
        const float* caib_l = caib + li * 768;

        // S1: traj1 (64 tiles) + self-attn QKV (96 tiles) — both read only g_q
        for (int tile = blockIdx.x; tile < 160; tile += NB) {
            if (tile < 64)
                gemm_tile<1,0>(&sm, g_q, tw1, tb1, g_h, 256, 512, (tile & 7) * 16, (tile >> 3) * 64);
            else {
                int u = tile - 64;
                gemm_tile<0,1>(&sm, g_q, saiw_l, saib_l, nullptr, 256, 768, (u & 7) * 16, (u >> 3) * 64);
            }
        }
        grid_sync();

        // S2 (per-query): self-attn core, then traj2, then sampling
        attn_core(&sm, m);
        traj2_stage(&sm, m, tw2, tb2, out + li * 1408);
        sample_stage(&sm, m, calib, ego);
        grid_sync();

        // S3: feature-MLP-1 (64 tiles) + self-attn out-proj (32 tiles)
        for (int tile = blockIdx.x; tile < 96; tile += NB) {
            if (tile < 64)
                gemm_tile<1,0>(&sm, g_agg, fmw1, fmb1, g_h, 256, 512, (tile & 7) * 16, (tile >> 3) * 64);
            else {
                int u = tile - 64;
                gemm_tile<0,0>(&sm, g_attno, saow + li * 256 * 256, saob + li * 256,
                               g_tmp, 256, 256, (u & 7) * 16, (u >> 3) * 64);
            }
        }
        grid_sync();

        // S4: resln1 (per-query, q += sa_out) + feature-MLP-2 (32 tiles -> g_mem)
        resln_stage(&sm, m, g_tmp, n1g + li * 256, n1b + li * 256);
        for (int tile = blockIdx.x; tile < 32; tile += NB)
            gemm_tile<0,0>(&sm, g_h, fmw2, fmb2, g_mem, 512, 256, (tile & 7) * 16, (tile >> 3) * 64);
        grid_sync();

        // S5: cross-attn QKV (96 tiles; q for queries, mem for k/v)
        for (int tile = blockIdx.x; tile < 96; tile += NB) {
            int m0 = (tile & 7) * 16, n0 = (tile >> 3) * 64;
            const float* Asrc = (n0 >= 256) ? g_mem : g_q;
            gemm_tile<0,1>(&sm, Asrc, caiw_l, caib_l, nullptr, 256, 768, m0, n0);
        }
        grid_sync();

        // S6: cross-attn core (per-query)
        attn_core(&sm, m);
        grid_sync();

        // S7: cross-attn out-proj (32 tiles)
        for (int tile = blockIdx.x; tile < 32; tile += NB)
            gemm_tile<0,0>(&sm, g_attno, caow + li * 256 * 256, caob + li * 256,
                           g_tmp, 256, 256, (tile & 7) * 16, (tile >> 3) * 64);
        grid_sync();

        // S8: resln2 (per-query)
        resln_stage(&sm, m, g_tmp, n2g + li * 256, n2b + li * 256);
        grid_sync();

        // S9: FFN1 (64 tiles)
        for (int tile = blockIdx.x; tile < 64; tile += NB)
            gemm_tile<1,0>(&sm, g_q, l1w + li * 512 * 256, l1b + li * 512,
                           g_h, 256, 512, (tile & 7) * 16, (tile >> 3) * 64);
        grid_sync();

        // S10: FFN2 (32 tiles)
        for (int tile = blockIdx.x; tile < 32; tile += NB)
            gemm_tile<0,0>(&sm, g_h, l2w + li * 256 * 512, l2b + li * 256,
                           g_tmp, 512, 256, (tile & 7) * 16, (tile >> 3) * 64);
        grid_sync();

        // S11: resln3 (per-query)
        resln_stage(&sm, m, g_tmp, n3g + li * 256, n3b + li * 256);
        grid_sync();
    }

    // epilogue: final traj head
    for (int tile = blockIdx.x; tile < 64; tile += NB)
        gemm_tile<1,0>(&sm, g_q, tw1, tb1, g_h, 256, 512, (tile & 7) * 16, (tile >> 3) * 64);
    grid_sync();
    traj2_stage(&sm, m, tw2, tb2, out + 6 * 1408);
}

// ---------------- host: one launch ----------------
extern "C" void kernel_launch(void* const* d_in, const int* in_sizes, int n_in,
                              void* d_out, int out_size)
{
    const float* features = (const float*)d_in[0];
    const float* calib    = (const float*)d_in[1];
    const float* ego      = (const float*)d_in[2];
    const float* queries  = (const float*)d_in[3];
    const float* tw1  = (const float*)d_in[5];
    const float* tb1  = (const float*)d_in[6];
    const float* tw2  = (const float*)d_in[7];
    const float* tb2  = (const float*)d_in[8];
    const float* fmw1 = (const float*)d_in[9];
    const float* fmb1 = (const float*)d_in[10];
    const float* fmw2 = (const float*)d_in[11];
    const float* fmb2 = (const float*)d_in[12];
    const float* saiw = (const float*)d_in[13];
    const float* saib = (const float*)d_in[14];
    const float* saow = (const float*)d_in[15];
    const float* saob = (const float*)d_in[16];
    const float* caiw = (const float*)d_in[17];
    const float* caib = (const float*)d_in[18];
    const float* caow = (const float*)d_in[19];
    const float* caob = (const float*)d_in[20];
    const float* l1w  = (const float*)d_in[21];
    const float* l1b  = (const float*)d_in[22];
    const float* l2w  = (const float*)d_in[23];
    const float* l2b  = (const float*)d_in[24];
    const float* n1g  = (const float*)d_in[25];
    const float* n1b  = (const float*)d_in[26];
    const float* n2g  = (const float*)d_in[27];
    const float* n2b  = (const float*)d_in[28];
    const float* n3g  = (const float*)d_in[29];
    const float* n3b  = (const float*)d_in[30];
    float* out = (float*)d_out;

    decoder_kernel<<<NB, NT>>>(features, calib, ego, queries,
                               tw1, tb1, tw2, tb2,
                               fmw1, fmb1, fmw2, fmb2,
                               saiw, saib, saow, saob,
                               caiw, caib, caow, caob,
                               l1w, l1b, l2w, l2b,
                               n1g, n1b, n2g, n2b, n3g, n3b,
                               out);
}

// round 7
// speedup vs baseline: 1.5179x; 1.2178x over previous
#include <cuda_runtime.h>
#include <cuda_fp16.h>
#include <math.h>

#define NQ    128
#define ED    256
#define DFFD  512
#define CAMSN 6
#define TSTEP 2
#define CFCH  256
#define HGT   64
#define WID   160
#define PLANE (HGT*WID)           /* 10240 */
#define NPTS  150
#define NTAPS (NPTS*CAMSN*TSTEP)  /* 1800 */
#define NB    128
#define NT    512

// ---------------- device scratch ----------------
__device__ float  g_q    [NQ*ED];
__device__ float  g_h    [NQ*DFFD];
__device__ float  g_agg  [NQ*ED];
__device__ float  g_mem  [NQ*ED];
__device__ float  g_qh   [NQ*ED];
__device__ float  g_kT   [ED*NQ];     // transposed K: [256 dims][128 queries]
__device__ float  g_vh   [NQ*ED];
__device__ __half g_featT[(size_t)CAMSN*TSTEP*PLANE*CFCH];  // 63 MB pixel-major fp16

__device__ unsigned g_bar_arrive;
__device__ unsigned g_bar_gen;

// ---------------- shared memory union ----------------
struct SmemGemm   { float As[2][32][20]; float Ws[2][32][68]; };   // 22528 B
struct SmemGemm2  { SmemGemm h[2]; };                              // 45056 B
struct SmemSample {
    float  tp[11];
    float  cs[2];          // cos/sin of query yaw
    float  ctc[12][14];    // per (cam,t) constants
    int    row[NTAPS];
    float4 w[NTAPS];
    float2 buf[3][128];
};
struct SmemAttn {
    float q[256];
    float Ps[8*128];       // also reused as h-row buffer (512) in ffn2
    float mxp[16];
    float sump[16];
    float ovp[256];
    float ao[256];
    float tmpv[256];
    float red[16];
};
struct SmemTrans  { float tile[32][33]; };
union Smem {
    SmemGemm2  g2;
    SmemSample s;
    SmemAttn   a;
    SmemTrans  t;
};

// ---------------- named barrier for 256-thread half-CTA ----------------
__device__ __forceinline__ void half_bar(int id)
{
    asm volatile("bar.sync %0, 256;" :: "r"(id) : "memory");
}

// ---------------- software grid barrier (128 CTAs co-resident) ----------------
__device__ __forceinline__ void grid_sync()
{
    __syncthreads();
    if (threadIdx.x == 0) {
        __threadfence();
        unsigned gen = *((volatile unsigned*)&g_bar_gen);
        unsigned t = atomicAdd(&g_bar_arrive, 1u);
        if (t == (unsigned)(gridDim.x - 1)) {
            g_bar_arrive = 0u;
            __threadfence();
            *((volatile unsigned*)&g_bar_gen) = gen + 1u;
        } else {
            while (*((volatile unsigned*)&g_bar_gen) == gen) { }
        }
        __threadfence();
    }
    __syncthreads();
}

// ---------------- one 16x64 GEMM tile on a 256-thread half, dbuf K=32 ----------------
// QKV=1 routes: col<256 -> g_qh, col<512 -> g_kT (transposed), else -> g_vh
template <int ACT, int QKV>
__device__ void gemm_tile(SmemGemm* sg, int tl, int barid,
                          const float* __restrict__ A,
                          const float* __restrict__ W, const float* __restrict__ Bb,
                          float* __restrict__ C, int K, int ldc, int m0, int n0)
{
    int tx = tl & 15;
    int ty = tl >> 4;
    float acc[4] = {0.f, 0.f, 0.f, 0.f};

#define LOAD_CHUNK(k0, b) do {                                                  \
        if (tl < 128) {                                                         \
            int r = tl >> 3, kq = tl & 7;                                       \
            float4 v = *(const float4*)&A[(m0 + r) * K + (k0) + kq * 4];        \
            sg->As[b][kq*4+0][r] = v.x; sg->As[b][kq*4+1][r] = v.y;             \
            sg->As[b][kq*4+2][r] = v.z; sg->As[b][kq*4+3][r] = v.w;             \
        }                                                                        \
        {                                                                        \
            int r = tl >> 2, kq = tl & 3;                                       \
            float4 v0 = *(const float4*)&W[(n0 + r) * K + (k0) + kq * 4];       \
            float4 v1 = *(const float4*)&W[(n0 + r) * K + (k0) + 16 + kq * 4];  \
            sg->Ws[b][kq*4+0][r] = v0.x; sg->Ws[b][kq*4+1][r] = v0.y;           \
            sg->Ws[b][kq*4+2][r] = v0.z; sg->Ws[b][kq*4+3][r] = v0.w;           \
            sg->Ws[b][16+kq*4+0][r] = v1.x; sg->Ws[b][16+kq*4+1][r] = v1.y;     \
            sg->Ws[b][16+kq*4+2][r] = v1.z; sg->Ws[b][16+kq*4+3][r] = v1.w;     \
        }                                                                        \
    } while (0)

    LOAD_CHUNK(0, 0);
    half_bar(barid);
    int p = 0;
    for (int k0 = 0; k0 < K; k0 += 32) {
        if (k0 + 32 < K) LOAD_CHUNK(k0 + 32, p ^ 1);
        #pragma unroll
        for (int k = 0; k < 32; k++) {
            float a  = sg->As[p][k][ty];
            float4 w = *(const float4*)&sg->Ws[p][k][tx*4];
            acc[0] = fmaf(a, w.x, acc[0]);
            acc[1] = fmaf(a, w.y, acc[1]);
            acc[2] = fmaf(a, w.z, acc[2]);
            acc[3] = fmaf(a, w.w, acc[3]);
        }
        half_bar(barid);
        p ^= 1;
    }
#undef LOAD_CHUNK

    int row = m0 + ty;
    int col = n0 + tx * 4;
    float4 bv = *(const float4*)&Bb[col];
    float4 r;
    r.x = acc[0] + bv.x;
    r.y = acc[1] + bv.y;
    r.z = acc[2] + bv.z;
    r.w = acc[3] + bv.w;
    if (ACT) {
        r.x = fmaxf(r.x, 0.f); r.y = fmaxf(r.y, 0.f);
        r.z = fmaxf(r.z, 0.f); r.w = fmaxf(r.w, 0.f);
    }
    if (QKV) {
        if (col < 256) {
            *(float4*)&g_qh[row * 256 + col] = r;
        } else if (col < 512) {
            int kd = col - 256;
            g_kT[(kd+0)*NQ + row] = r.x;
            g_kT[(kd+1)*NQ + row] = r.y;
            g_kT[(kd+2)*NQ + row] = r.z;
            g_kT[(kd+3)*NQ + row] = r.w;
        } else {
            *(float4*)&g_vh[row * 256 + (col - 512)] = r;
        }
    } else {
        *(float4*)&C[row * ldc + col] = r;
    }
}

// ---------------- residual add + LayerNorm, add from smem tmpv ----------------
__device__ void resln_inblock(Smem* sm, int m, const float* __restrict__ lng,
                              const float* __restrict__ lnb)
{
    int t = threadIdx.x, lane = t & 31, w = t >> 5;
    float x = 0.f;
    if (t < 256) x = g_q[m * 256 + t] + sm->a.tmpv[t];

    float v = x;
    #pragma unroll
    for (int o = 16; o; o >>= 1) v += __shfl_xor_sync(0xffffffffu, v, o);
    if (lane == 0) sm->a.red[w] = v;
    __syncthreads();
    float tot = 0.f;
    #pragma unroll
    for (int kk = 0; kk < 8; kk++) tot += sm->a.red[kk];
    float mean = tot * (1.0f / 256.0f);
    float xm = x - mean;
    __syncthreads();
    float v2 = (t < 256) ? xm * xm : 0.f;
    #pragma unroll
    for (int o = 16; o; o >>= 1) v2 += __shfl_xor_sync(0xffffffffu, v2, o);
    if (lane == 0) sm->a.red[w] = v2;
    __syncthreads();
    float tv = 0.f;
    #pragma unroll
    for (int kk = 0; kk < 8; kk++) tv += sm->a.red[kk];
    float var = tv * (1.0f / 256.0f);
    if (t < 256)
        g_q[m * 256 + t] = xm * rsqrtf(var + 1e-5f) * lng[t] + lnb[t];
    __syncthreads();
}

// ---------------- full attention for query m: core + out-proj + resln ----------------
__device__ void attn_full(Smem* sm, int m,
                          const float* __restrict__ Wo, const float* __restrict__ bo,
                          const float* __restrict__ lng, const float* __restrict__ lnb)
{
    int t = threadIdx.x, lane = t & 31, w = t >> 5;
    int h = w >> 1, part = w & 1;
    int jb = part * 64;

    if (t < 256) sm->a.q[t] = g_qh[m * 256 + t];
    __syncthreads();

    // scores: 2 warps per head, each covers 64 keys
    const float* kTh = g_kT + (h * 32) * NQ;
    float s0 = 0.f, s1 = 0.f;
    #pragma unroll
    for (int d = 0; d < 32; d++) {
        float qd = sm->a.q[h * 32 + d];
        s0 = fmaf(qd, kTh[d * NQ + jb + lane], s0);
        s1 = fmaf(qd, kTh[d * NQ + jb + 32 + lane], s1);
    }
    s0 *= 0.17677669529663687f;   // 1/sqrt(32)
    s1 *= 0.17677669529663687f;

    float mx = fmaxf(s0, s1);
    #pragma unroll
    for (int o = 16; o; o >>= 1) mx = fmaxf(mx, __shfl_xor_sync(0xffffffffu, mx, o));
    if (lane == 0) sm->a.mxp[w] = mx;
    __syncthreads();
    mx = fmaxf(sm->a.mxp[h * 2], sm->a.mxp[h * 2 + 1]);

    float e0 = expf(s0 - mx), e1 = expf(s1 - mx);
    float ps = e0 + e1;
    #pragma unroll
    for (int o = 16; o; o >>= 1) ps += __shfl_xor_sync(0xffffffffu, ps, o);
    if (lane == 0) sm->a.sump[w] = ps;
    __syncthreads();
    float inv = 1.0f / (sm->a.sump[h * 2] + sm->a.sump[h * 2 + 1]);

    sm->a.Ps[h * 128 + jb + lane]      = e0 * inv;
    sm->a.Ps[h * 128 + jb + 32 + lane] = e1 * inv;
    __syncthreads();

    // AV: each warp sums its 64 keys; fixed-order cross-part combine
    float ov = 0.f;
    for (int j = jb; j < jb + 64; j++)
        ov = fmaf(sm->a.Ps[h * 128 + j], g_vh[j * 256 + h * 32 + lane], ov);
    if (part == 1) sm->a.ovp[h * 32 + lane] = ov;
    __syncthreads();
    if (part == 0) sm->a.ao[h * 32 + lane] = ov + sm->a.ovp[h * 32 + lane];
    __syncthreads();

    // out-projection: 16 warps x 16 cols
    #pragma unroll 1
    for (int ci = 0; ci < 16; ci++) {
        int c = w * 16 + ci;
        const float* wr = Wo + c * 256;
        float acc = 0.f;
        #pragma unroll
        for (int kk = lane; kk < 256; kk += 32)
            acc = fmaf(sm->a.ao[kk], wr[kk], acc);
        #pragma unroll
        for (int o = 16; o; o >>= 1) acc += __shfl_xor_sync(0xffffffffu, acc, o);
        if (lane == 0) sm->a.tmpv[c] = acc + bo[c];
    }
    __syncthreads();

    resln_inblock(sm, m, lng, lnb);
}

// ---------------- FFN2 per-query matvec + resln3 ----------------
__device__ void ffn2_resln(Smem* sm, int m,
                           const float* __restrict__ W2, const float* __restrict__ b2,
                           const float* __restrict__ lng, const float* __restrict__ lnb)
{
    int t = threadIdx.x, lane = t & 31, w = t >> 5;
    sm->a.Ps[t] = g_h[m * 512 + t];   // h row (512 floats) into Ps buffer
    __syncthreads();
    #pragma unroll 1
    for (int ci = 0; ci < 16; ci++) {
        int c = w * 16 + ci;
        const float* wr = W2 + c * 512;
        float acc = 0.f;
        #pragma unroll
        for (int kk = lane; kk < 512; kk += 32)
            acc = fmaf(sm->a.Ps[kk], wr[kk], acc);
        #pragma unroll
        for (int o = 16; o; o >>= 1) acc += __shfl_xor_sync(0xffffffffu, acc, o);
        if (lane == 0) sm->a.tmpv[c] = acc + b2[c];
    }
    __syncthreads();
    resln_inblock(sm, m, lng, lnb);
}

// ---------------- traj head stage 2 ----------------
__device__ void traj2_stage(Smem* sm, int m, const float* __restrict__ w2,
                            const float* __restrict__ b2, float* __restrict__ outp)
{
    int t = threadIdx.x, lane = t & 31, w = t >> 5;
    const float* hr = g_h + m * 512;
    if (w < 11) {
        float s = 0.f;
        #pragma unroll
        for (int d = lane; d < 512; d += 32)
            s = fmaf(hr[d], w2[w * 512 + d], s);
        #pragma unroll
        for (int o = 16; o; o >>= 1) s += __shfl_xor_sync(0xffffffffu, s, o);
        if (lane == 0) {
            float v = s + b2[w];
            sm->s.tp[w]      = v;
            outp[m * 11 + w] = v;
        }
    }
    __syncthreads();
}

// ---------------- sampling for query m ----------------
__device__ void sample_stage(Smem* sm, int m, const float* __restrict__ calib,
                             const float* __restrict__ ego)
{
    int t = threadIdx.x;

    // per-(cam,t) constants + per-query yaw trig
    if (t < 12) {
        int ci = t % CAMSN, tt = t / CAMSN;
        float* d = sm->s.ctc[t];
        d[0] = ego[tt * 4 + 3] - ego[1 * 4 + 3];
        d[1] = ego[tt * 4 + 0];
        d[2] = ego[tt * 4 + 1];
        float eyaw = ego[tt * 4 + 2];
        d[3] = cosf(eyaw);
        d[4] = sinf(eyaw);
        const float* cal = calib + ci * 8;
        d[5]  = cal[0]; d[6]  = cal[1]; d[7]  = cal[2]; d[8] = cal[3];
        d[9]  = cal[4]; d[10] = cal[5]; d[11] = cal[6];
        d[12] = cosf(cal[7]);
        d[13] = sinf(cal[7]);
    } else if (t == 12) {
        float yaw = sm->s.tp[7];
        sm->s.cs[0] = cosf(yaw);
        sm->s.cs[1] = sinf(yaw);
    }
    __syncthreads();

    // Phase A: project 1800 taps (invalid -> row 0, weight 0)
    for (int idx = t; idx < NTAPS; idx += NT) {
        int pt  = idx % NPTS;
        int ctc = idx / NPTS;
        int ci  = ctc % CAMSN;
        int tt  = ctc / CAMSN;
        const float* d = sm->s.ctc[tt * CAMSN + ci];
        float dt = d[0], ex = d[1], ey = d[2], ce = d[3], se = d[4];
        float fx = d[5], fy = d[6], cx0 = d[7], cy0 = d[8];
        float txc = d[9], tyc = d[10], tzc = d[11], cc = d[12], sc = d[13];

        int face = pt / 25, sub = pt % 25, dim = face >> 1;
        float sign = (face & 1) ? 1.0f : -1.0f;
        float a = -1.0f + 0.5f * (float)(sub / 5);
        float b = -1.0f + 0.5f * (float)(sub % 5);
        float ux, uy, uz;
        if (dim == 0)      { ux = sign; uy = a;    uz = b; }
        else if (dim == 1) { ux = a;    uy = sign; uz = b; }
        else               { ux = a;    uy = b;    uz = sign; }

        float lx = ux * sm->s.tp[8], ly = uy * sm->s.tp[9], lz = uz * sm->s.tp[10];
        float cyw = sm->s.cs[0], syw = sm->s.cs[1];
        float rx = lx * cyw - ly * syw;
        float ry = lx * syw + ly * cyw;
        float cx = sm->s.tp[0] + sm->s.tp[3] * dt + 0.5f * sm->s.tp[5] * dt * dt;
        float cy = sm->s.tp[1] + sm->s.tp[4] * dt + 0.5f * sm->s.tp[6] * dt * dt;
        float wx = rx + cx, wy = ry + cy, wz = lz + sm->s.tp[2];
        float pxr = wx - ex, pyr = wy - ey;
        float gx =  pxr * ce + pyr * se;
        float gy = -pxr * se + pyr * ce;

        float px = gx - txc, py = gy - tyc, pz = wz - tzc;
        float fwd  =  px * cc + py * sc;
        float left = -px * sc + py * cc;
        float zc = fwd, xc = -left, yc = -pz;
        float zs = fmaxf(zc, 0.1f);
        float u = fx * xc / zs + cx0;
        float v = fy * yc / zs + cy0;
        bool valid = (zc > 0.1f) && (u >= 0.f) && (u < 1.f) && (v >= 0.f) && (v < 1.f);

        if (valid) {
            float pxi = u * 159.0f;
            float pyi = v * 63.0f;
            float x0f = floorf(pxi), y0f = floorf(pyi);
            int x0 = (int)x0f, y0 = (int)y0f;
            float wxk = pxi - x0f, wyk = pyi - y0f;
            sm->s.row[idx] = (ci * TSTEP + tt) * PLANE + y0 * WID + x0;
            sm->s.w[idx] = make_float4((1.f - wxk) * (1.f - wyk),
                                       wxk * (1.f - wyk),
                                       (1.f - wxk) * wyk,
                                       wxk * wyk);
        } else {
            sm->s.row[idx] = 0;
            sm->s.w[idx]   = make_float4(0.f, 0.f, 0.f, 0.f);
        }
    }
    __syncthreads();

    // Phase B: 4 groups of 128 threads, each takes every 4th tap; thread = channel pair
    int g = t >> 7;            // 0..3
    int j = t & 127;           // channel pair (channels 2j, 2j+1)
    float accx = 0.f, accy = 0.f;
    const __half2* fb = (const __half2*)g_featT;
    #pragma unroll 2
    for (int i = g; i < NTAPS; i += 4) {
        int row = sm->s.row[i];
        float4 w4 = sm->s.w[i];
        const __half2* p = fb + (size_t)row * 128 + j;
        float2 f00 = __half22float2(p[0]);
        float2 f01 = __half22float2(p[128]);
        float2 f10 = __half22float2(p[WID * 128]);
        float2 f11 = __half22float2(p[(WID + 1) * 128]);
        accx = fmaf(f00.x, w4.x, accx);
        accx = fmaf(f01.x, w4.y, accx);
        accx = fmaf(f10.x, w4.z, accx);
        accx = fmaf(f11.x, w4.w, accx);
        accy = fmaf(f00.y, w4.x, accy);
        accy = fmaf(f01.y, w4.y, accy);
        accy = fmaf(f10.y, w4.z, accy);
        accy = fmaf(f11.y, w4.w, accy);
    }
    if (g > 0) sm->s.buf[g - 1][j] = make_float2(accx, accy);
    __syncthreads();
    if (g == 0) {
        float2 b0 = sm->s.buf[0][j];
        float2 b1 = sm->s.buf[1][j];
        float2 b2 = sm->s.buf[2][j];
        float sx = ((accx + b0.x) + b1.x) + b2.x;
        float sy = ((accy + b0.y) + b1.y) + b2.y;
        g_agg[m * 256 + 2 * j]     = sx * (1.0f / 1800.0f);
        g_agg[m * 256 + 2 * j + 1] = sy * (1.0f / 1800.0f);
    }
    __syncthreads();
}

// ---------------- persistent mega-kernel ----------------
__global__ void __launch_bounds__(NT, 1)
decoder_kernel(const float* __restrict__ features, const float* __restrict__ calib,
               const float* __restrict__ ego, const float* __restrict__ queries,
               const float* __restrict__ tw1, const float* __restrict__ tb1,
               const float* __restrict__ tw2, const float* __restrict__ tb2,
               const float* __restrict__ fmw1, const float* __restrict__ fmb1,
               const float* __restrict__ fmw2, const float* __restrict__ fmb2,
               const float* __restrict__ saiw, const float* __restrict__ saib,
               const float* __restrict__ saow, const float* __restrict__ saob,
               const float* __restrict__ caiw, const float* __restrict__ caib,
               const float* __restrict__ caow, const float* __restrict__ caob,
               const float* __restrict__ l1w,  const float* __restrict__ l1b,
               const float* __restrict__ l2w,  const float* __restrict__ l2b,
               const float* __restrict__ n1g,  const float* __restrict__ n1b,
               const float* __restrict__ n2g,  const float* __restrict__ n2b,
               const float* __restrict__ n3g,  const float* __restrict__ n3b,
               float* __restrict__ out)
{
    __shared__ Smem sm;
    int m = blockIdx.x;
    int t = threadIdx.x;
    int half = t >> 8;           // 0/1
    int tl   = t & 255;
    int barid = half + 1;
    SmemGemm* sg = &sm.g2.h[half];

    // prologue: copy queries; transpose features -> fp16 pixel-major
    if (t < 256) g_q[m * 256 + t] = queries[m * 256 + t];
    {
        const int PT = PLANE / 32;                   // 320
        const int CT = CFCH / 32;                    // 8
        const int NTILE = CAMSN * TSTEP * PT * CT;   // 30720
        int tx = t & 31, ty = t >> 5;                // 32 x 16
        for (int tile = blockIdx.x; tile < NTILE; tile += NB) {
            int ct  = tile / (PT * CT);
            int rem = tile % (PT * CT);
            int p0 = (rem % PT) * 32;
            int c0 = (rem / PT) * 32;
            const float* in = features + (size_t)ct * CFCH * PLANE;
            __half*      op = g_featT  + (size_t)ct * CFCH * PLANE;
            #pragma unroll
            for (int i = 0; i < 32; i += 16)
                sm.t.tile[ty + i][tx] = in[(size_t)(c0 + ty + i) * PLANE + p0 + tx];
            __syncthreads();
            #pragma unroll
            for (int i = 0; i < 32; i += 16)
                op[(size_t)(p0 + ty + i) * CFCH + c0 + tx] = __float2half_rn(sm.t.tile[tx][ty + i]);
            __syncthreads();
        }
    }
    grid_sync();

    for (int li = 0; li < 6; li++) {
        const float* saiw_l = saiw + li * 768 * 256;
        const float* saib_l = saib + li * 768;
        const float* caiw_l = caiw + li * 768 * 256;
        const float* caib_l = caib + li * 768;

        // S1: traj1 (64 tiles) + SA QKV (96 tiles) — both read g_q
        for (int tile = blockIdx.x * 2 + half; tile < 160; tile += 256) {
            if (tile < 64)
                gemm_tile<1,0>(sg, tl, barid, g_q, tw1, tb1, g_h, 256, 512,
                               (tile & 7) * 16, (tile >> 3) * 64);
            else {
                int u = tile - 64;
                gemm_tile<0,1>(sg, tl, barid, g_q, saiw_l, saib_l, nullptr, 256, 768,
                               (u & 7) * 16, (u >> 3) * 64);
            }
        }
        grid_sync();

        // S2 per-query: SA attn+outproj+resln1, traj2, sampling
        attn_full(&sm, m, saow + li * 256 * 256, saob + li * 256,
                  n1g + li * 256, n1b + li * 256);
        traj2_stage(&sm, m, tw2, tb2, out + li * 1408);
        sample_stage(&sm, m, calib, ego);
        grid_sync();

        // S3: fm1 (64 tiles, reads g_agg) + CA q-proj (32 tiles, reads updated g_q)
        for (int tile = blockIdx.x * 2 + half; tile < 96; tile += 256) {
            if (tile < 64)
                gemm_tile<1,0>(sg, tl, barid, g_agg, fmw1, fmb1, g_h, 256, 512,
                               (tile & 7) * 16, (tile >> 3) * 64);
            else {
                int u = tile - 64;
                gemm_tile<0,1>(sg, tl, barid, g_q, caiw_l, caib_l, nullptr, 256, 768,
                               (u & 7) * 16, (u >> 3) * 64);
            }
        }
        grid_sync();

        // S4: fm2 (32 tiles -> g_mem)
        for (int tile = blockIdx.x * 2 + half; tile < 32; tile += 256)
            gemm_tile<0,0>(sg, tl, barid, g_h, fmw2, fmb2, g_mem, 512, 256,
                           (tile & 7) * 16, (tile >> 3) * 64);
        grid_sync();

        // S5: CA kv-proj (64 tiles, A = g_mem, cols 256..767)
        for (int tile = blockIdx.x * 2 + half; tile < 64; tile += 256)
            gemm_tile<0,1>(sg, tl, barid, g_mem, caiw_l, caib_l, nullptr, 256, 768,
                           (tile & 7) * 16, 256 + (tile >> 3) * 64);
        grid_sync();

        // S6 per-query: CA attn+outproj+resln2
        attn_full(&sm, m, caow + li * 256 * 256, caob + li * 256,
                  n2g + li * 256, n2b + li * 256);
        grid_sync();

        // S7: FFN1 (64 tiles)
        for (int tile = blockIdx.x * 2 + half; tile < 64; tile += 256)
            gemm_tile<1,0>(sg, tl, barid, g_q, l1w + li * 512 * 256, l1b + li * 512,
                           g_h, 256, 512, (tile & 7) * 16, (tile >> 3) * 64);
        grid_sync();

        // S8 per-query: FFN2 matvec + resln3
        ffn2_resln(&sm, m, l2w + li * 256 * 512, l2b + li * 256,
                   n3g + li * 256, n3b + li * 256);
        grid_sync();
    }

    // epilogue: final traj head
    for (int tile = blockIdx.x * 2 + half; tile < 64; tile += 256)
        gemm_tile<1,0>(sg, tl, barid, g_q, tw1, tb1, g_h, 256, 512,
                       (tile & 7) * 16, (tile >> 3) * 64);
    grid_sync();
    traj2_stage(&sm, m, tw2, tb2, out + 6 * 1408);
}

// ---------------- host: one launch ----------------
extern "C" void kernel_launch(void* const* d_in, const int* in_sizes, int n_in,
                              void* d_out, int out_size)
{
    const float* features = (const float*)d_in[0];
    const float* calib    = (const float*)d_in[1];
    const float* ego      = (const float*)d_in[2];
    const float* queries  = (const float*)d_in[3];
    const float* tw1  = (const float*)d_in[5];
    const float* tb1  = (const float*)d_in[6];
    const float* tw2  = (const float*)d_in[7];
    const float* tb2  = (const float*)d_in[8];
    const float* fmw1 = (const float*)d_in[9];
    const float* fmb1 = (const float*)d_in[10];
    const float* fmw2 = (const float*)d_in[11];
    const float* fmb2 = (const float*)d_in[12];
    const float* saiw = (const float*)d_in[13];
    const float* saib = (const float*)d_in[14];
    const float* saow = (const float*)d_in[15];
    const float* saob = (const float*)d_in[16];
    const float* caiw = (const float*)d_in[17];
    const float* caib = (const float*)d_in[18];
    const float* caow = (const float*)d_in[19];
    const float* caob = (const float*)d_in[20];
    const float* l1w  = (const float*)d_in[21];
    const float* l1b  = (const float*)d_in[22];
    const float* l2w  = (const float*)d_in[23];
    const float* l2b  = (const float*)d_in[24];
    const float* n1g  = (const float*)d_in[25];
    const float* n1b  = (const float*)d_in[26];
    const float* n2g  = (const float*)d_in[27];
    const float* n2b  = (const float*)d_in[28];
    const float* n3g  = (const float*)d_in[29];
    const float* n3b  = (const float*)d_in[30];
    float* out = (float*)d_out;

    decoder_kernel<<<NB, NT>>>(features, calib, ego, queries,
                               tw1, tb1, tw2, tb2,
                               fmw1, fmb1, fmw2, fmb2,
                               saiw, saib, saow, saob,
                               caiw, caib, caow, caob,
                               l1w, l1b, l2w, l2b,
                               n1g, n1b, n2g, n2b, n3g, n3b,
                               out);
}

// round 8
// speedup vs baseline: 2.3886x; 1.5736x over previous
#include <cuda_runtime.h>
#include <cuda_fp16.h>
#include <math.h>

#define NQ    128
#define ED    256
#define DFFD  512
#define CAMSN 6
#define TSTEP 2
#define CFCH  256
#define HGT   64
#define WID   160
#define PLANE (HGT*WID)           /* 10240 */
#define NPTS  150
#define NTAPS (NPTS*CAMSN*TSTEP)  /* 1800 */
#define NB    128
#define NT    512

// ---------------- device scratch ----------------
__device__ float  g_q    [NQ*ED];
__device__ float  g_h    [NQ*DFFD];
__device__ float  g_mem  [NQ*ED];
__device__ float  g_qh   [NQ*ED];
__device__ float  g_kT   [ED*NQ];     // transposed K: [256 dims][128 queries]
__device__ float  g_vh   [NQ*ED];
__device__ __half g_featT[(size_t)CAMSN*TSTEP*PLANE*CFCH];  // 63 MB pixel-major fp16

__device__ unsigned g_bar_arrive;
__device__ unsigned g_bar_gen;

// ---------------- shared memory union ----------------
struct SmemGemm   { float As[2][32][20]; float Ws[2][32][68]; };   // 22528 B
struct SmemGemm2  { SmemGemm h[2]; };                              // 45056 B
struct SmemS2 {                       // per-query stage scratch
    float4 w[NTAPS];                  // 28800 B
    float4 buf[7][64];                // 7168 B (sample partials)
    int    row[NTAPS];                // 7200 B
    float  agg[256];                  // sampled agg / qrow save
    float  h[512];                    // MLP hidden
    float  tp[11];
    float  cs[2];
    float  ctc[12][14];
};                                    // ~46.9 KB
struct SmemAttn {                     // aliases low part of SmemS2 (used before sample writes)
    float q[256];
    float Ps[8*128];
    float mxp[16];
    float sump[16];
    float ovp[256];
    float ao[256];
    float tmpv[256];
    float red[16];
};
struct SmemTrans  { float tile[32][33]; };
union __align__(16) Smem {
    SmemGemm2  g2;
    SmemS2     s;
    SmemAttn   a;
    SmemTrans  t;
};

// ---------------- named barrier for 256-thread half-CTA ----------------
__device__ __forceinline__ void half_bar(int id)
{
    asm volatile("bar.sync %0, 256;" :: "r"(id) : "memory");
}

// ---------------- software grid barrier (128 CTAs co-resident) ----------------
__device__ __forceinline__ void grid_sync()
{
    __syncthreads();
    if (threadIdx.x == 0) {
        __threadfence();
        unsigned gen = *((volatile unsigned*)&g_bar_gen);
        unsigned t = atomicAdd(&g_bar_arrive, 1u);
        if (t == (unsigned)(gridDim.x - 1)) {
            g_bar_arrive = 0u;
            __threadfence();
            *((volatile unsigned*)&g_bar_gen) = gen + 1u;
        } else {
            while (*((volatile unsigned*)&g_bar_gen) == gen) { }
        }
        __threadfence();
    }
    __syncthreads();
}

__device__ __forceinline__ float warp_red(float v)
{
    #pragma unroll
    for (int o = 16; o; o >>= 1) v += __shfl_xor_sync(0xffffffffu, v, o);
    return v;
}

__device__ __forceinline__ float dot4(float4 a, float4 b)
{
    return fmaf(a.x, b.x, fmaf(a.y, b.y, fmaf(a.z, b.z, a.w * b.w)));
}

// ---------------- one 16x64 GEMM tile on a 256-thread half, dbuf K=32 ----------------
template <int ACT, int QKV>
__device__ void gemm_tile(SmemGemm* sg, int tl, int barid,
                          const float* __restrict__ A,
                          const float* __restrict__ W, const float* __restrict__ Bb,
                          float* __restrict__ C, int K, int ldc, int m0, int n0)
{
    int tx = tl & 15;
    int ty = tl >> 4;
    float acc[4] = {0.f, 0.f, 0.f, 0.f};

#define LOAD_CHUNK(k0, b) do {                                                  \
        if (tl < 128) {                                                         \
            int r = tl >> 3, kq = tl & 7;                                       \
            float4 v = *(const float4*)&A[(m0 + r) * K + (k0) + kq * 4];        \
            sg->As[b][kq*4+0][r] = v.x; sg->As[b][kq*4+1][r] = v.y;             \
            sg->As[b][kq*4+2][r] = v.z; sg->As[b][kq*4+3][r] = v.w;             \
        }                                                                        \
        {                                                                        \
            int r = tl >> 2, kq = tl & 3;                                       \
            float4 v0 = *(const float4*)&W[(n0 + r) * K + (k0) + kq * 4];       \
            float4 v1 = *(const float4*)&W[(n0 + r) * K + (k0) + 16 + kq * 4];  \
            sg->Ws[b][kq*4+0][r] = v0.x; sg->Ws[b][kq*4+1][r] = v0.y;           \
            sg->Ws[b][kq*4+2][r] = v0.z; sg->Ws[b][kq*4+3][r] = v0.w;           \
            sg->Ws[b][16+kq*4+0][r] = v1.x; sg->Ws[b][16+kq*4+1][r] = v1.y;     \
            sg->Ws[b][16+kq*4+2][r] = v1.z; sg->Ws[b][16+kq*4+3][r] = v1.w;     \
        }                                                                        \
    } while (0)

    LOAD_CHUNK(0, 0);
    half_bar(barid);
    int p = 0;
    for (int k0 = 0; k0 < K; k0 += 32) {
        if (k0 + 32 < K) LOAD_CHUNK(k0 + 32, p ^ 1);
        #pragma unroll
        for (int k = 0; k < 32; k++) {
            float a  = sg->As[p][k][ty];
            float4 w = *(const float4*)&sg->Ws[p][k][tx*4];
            acc[0] = fmaf(a, w.x, acc[0]);
            acc[1] = fmaf(a, w.y, acc[1]);
            acc[2] = fmaf(a, w.z, acc[2]);
            acc[3] = fmaf(a, w.w, acc[3]);
        }
        half_bar(barid);
        p ^= 1;
    }
#undef LOAD_CHUNK

    int row = m0 + ty;
    int col = n0 + tx * 4;
    float4 bv = *(const float4*)&Bb[col];
    float4 r;
    r.x = acc[0] + bv.x;
    r.y = acc[1] + bv.y;
    r.z = acc[2] + bv.z;
    r.w = acc[3] + bv.w;
    if (ACT) {
        r.x = fmaxf(r.x, 0.f); r.y = fmaxf(r.y, 0.f);
        r.z = fmaxf(r.z, 0.f); r.w = fmaxf(r.w, 0.f);
    }
    if (QKV) {
        if (col < 256) {
            *(float4*)&g_qh[row * 256 + col] = r;
        } else if (col < 512) {
            int kd = col - 256;
            g_kT[(kd+0)*NQ + row] = r.x;
            g_kT[(kd+1)*NQ + row] = r.y;
            g_kT[(kd+2)*NQ + row] = r.z;
            g_kT[(kd+3)*NQ + row] = r.w;
        } else {
            *(float4*)&g_vh[row * 256 + (col - 512)] = r;
        }
    } else {
        *(float4*)&C[row * ldc + col] = r;
    }
}

// ---------------- matvec: out[512] = act(W[512,256] @ xs[256] + b) ----------------
__device__ void mv256to512(Smem* sm, const float* __restrict__ xs,
                           const float* __restrict__ W, const float* __restrict__ Bb,
                           float* __restrict__ hs)
{
    int t = threadIdx.x, lane = t & 31, w = t >> 5;
    float4 x0 = ((const float4*)xs)[lane];
    float4 x1 = ((const float4*)xs)[lane + 32];
    #pragma unroll 1
    for (int ci = 0; ci < 32; ci += 2) {
        int c0 = w * 32 + ci;
        const float4* w0 = (const float4*)(W + (size_t)c0 * 256);
        const float4* w1 = (const float4*)(W + (size_t)(c0 + 1) * 256);
        float4 p00 = w0[lane], p01 = w0[lane + 32];
        float4 p10 = w1[lane], p11 = w1[lane + 32];
        float a0 = dot4(x0, p00) + dot4(x1, p01);
        float a1 = dot4(x0, p10) + dot4(x1, p11);
        a0 = warp_red(a0);
        a1 = warp_red(a1);
        if (lane == 0) {
            hs[c0]     = fmaxf(a0 + Bb[c0], 0.f);
            hs[c0 + 1] = fmaxf(a1 + Bb[c0 + 1], 0.f);
        }
    }
    __syncthreads();
}

// ---------------- matvec: out[256] = W[256,512] @ xs[512] + b ----------------
__device__ void mv512to256(Smem* sm, const float* __restrict__ xs,
                           const float* __restrict__ W, const float* __restrict__ Bb,
                           float* __restrict__ outv)
{
    int t = threadIdx.x, lane = t & 31, w = t >> 5;
    const float4* xs4 = (const float4*)xs;
    float4 x0 = xs4[lane], x1 = xs4[lane + 32], x2 = xs4[lane + 64], x3 = xs4[lane + 96];
    #pragma unroll 1
    for (int ci = 0; ci < 16; ci += 2) {
        int c0 = w * 16 + ci;
        const float4* w0 = (const float4*)(W + (size_t)c0 * 512);
        const float4* w1 = (const float4*)(W + (size_t)(c0 + 1) * 512);
        float4 p00 = w0[lane], p01 = w0[lane + 32], p02 = w0[lane + 64], p03 = w0[lane + 96];
        float4 p10 = w1[lane], p11 = w1[lane + 32], p12 = w1[lane + 64], p13 = w1[lane + 96];
        float a0 = (dot4(x0, p00) + dot4(x1, p01)) + (dot4(x2, p02) + dot4(x3, p03));
        float a1 = (dot4(x0, p10) + dot4(x1, p11)) + (dot4(x2, p12) + dot4(x3, p13));
        a0 = warp_red(a0);
        a1 = warp_red(a1);
        if (lane == 0) {
            outv[c0]     = a0 + Bb[c0];
            outv[c0 + 1] = a1 + Bb[c0 + 1];
        }
    }
    __syncthreads();
}

// ---------------- residual add + LayerNorm (tmpv in smem); optional smem save ----------------
__device__ void resln_inblock(Smem* sm, int m, const float* __restrict__ lng,
                              const float* __restrict__ lnb, float* qsave)
{
    int t = threadIdx.x, lane = t & 31, w = t >> 5;
    float x = 0.f;
    if (t < 256) x = g_q[m * 256 + t] + sm->a.tmpv[t];

    float v = warp_red(x);
    if (lane == 0) sm->a.red[w] = v;
    __syncthreads();
    float tot = 0.f;
    #pragma unroll
    for (int kk = 0; kk < 8; kk++) tot += sm->a.red[kk];
    float mean = tot * (1.0f / 256.0f);
    float xm = x - mean;
    __syncthreads();
    float v2 = warp_red((t < 256) ? xm * xm : 0.f);
    if (lane == 0) sm->a.red[w] = v2;
    __syncthreads();
    float tv = 0.f;
    #pragma unroll
    for (int kk = 0; kk < 8; kk++) tv += sm->a.red[kk];
    float var = tv * (1.0f / 256.0f);
    if (t < 256) {
        float r = xm * rsqrtf(var + 1e-5f) * lng[t] + lnb[t];
        g_q[m * 256 + t] = r;
        if (qsave) qsave[t] = r;
    }
    __syncthreads();
}

// ---------------- full attention for query m ----------------
__device__ void attn_full(Smem* sm, int m,
                          const float* __restrict__ Wo, const float* __restrict__ bo,
                          const float* __restrict__ lng, const float* __restrict__ lnb,
                          float* qsave)
{
    int t = threadIdx.x, lane = t & 31, w = t >> 5;
    int h = w >> 1, part = w & 1;
    int jb = part * 64;

    if (t < 256) sm->a.q[t] = g_qh[m * 256 + t];
    __syncthreads();

    const float* kTh = g_kT + (h * 32) * NQ;
    float s0 = 0.f, s1 = 0.f;
    #pragma unroll
    for (int d = 0; d < 32; d++) {
        float qd = sm->a.q[h * 32 + d];
        s0 = fmaf(qd, kTh[d * NQ + jb + lane], s0);
        s1 = fmaf(qd, kTh[d * NQ + jb + 32 + lane], s1);
    }
    s0 *= 0.17677669529663687f;   // 1/sqrt(32)
    s1 *= 0.17677669529663687f;

    float mx = fmaxf(s0, s1);
    #pragma unroll
    for (int o = 16; o; o >>= 1) mx = fmaxf(mx, __shfl_xor_sync(0xffffffffu, mx, o));
    if (lane == 0) sm->a.mxp[w] = mx;
    __syncthreads();
    mx = fmaxf(sm->a.mxp[h * 2], sm->a.mxp[h * 2 + 1]);

    float e0 = expf(s0 - mx), e1 = expf(s1 - mx);
    float ps = warp_red(e0 + e1);
    if (lane == 0) sm->a.sump[w] = ps;
    __syncthreads();
    float inv = 1.0f / (sm->a.sump[h * 2] + sm->a.sump[h * 2 + 1]);

    sm->a.Ps[h * 128 + jb + lane]      = e0 * inv;
    sm->a.Ps[h * 128 + jb + 32 + lane] = e1 * inv;
    __syncthreads();

    float ov = 0.f;
    for (int j = jb; j < jb + 64; j++)
        ov = fmaf(sm->a.Ps[h * 128 + j], g_vh[j * 256 + h * 32 + lane], ov);
    if (part == 1) sm->a.ovp[h * 32 + lane] = ov;
    __syncthreads();
    if (part == 0) sm->a.ao[h * 32 + lane] = ov + sm->a.ovp[h * 32 + lane];
    __syncthreads();

    // out-projection: 16 warps x 16 cols, paired for ILP
    {
        const float4* av = (const float4*)sm->a.ao;
        float4 x0 = av[lane], x1 = av[lane + 32];
        #pragma unroll 1
        for (int ci = 0; ci < 16; ci += 2) {
            int c0 = w * 16 + ci;
            const float4* w0 = (const float4*)(Wo + (size_t)c0 * 256);
            const float4* w1 = (const float4*)(Wo + (size_t)(c0 + 1) * 256);
            float4 p00 = w0[lane], p01 = w0[lane + 32];
            float4 p10 = w1[lane], p11 = w1[lane + 32];
            float a0 = dot4(x0, p00) + dot4(x1, p01);
            float a1 = dot4(x0, p10) + dot4(x1, p11);
            a0 = warp_red(a0);
            a1 = warp_red(a1);
            if (lane == 0) {
                sm->a.tmpv[c0]     = a0 + bo[c0];
                sm->a.tmpv[c0 + 1] = a1 + bo[c0 + 1];
            }
        }
    }
    __syncthreads();

    resln_inblock(sm, m, lng, lnb, qsave);
}

// ---------------- traj head stage 2 ----------------
__device__ void traj2_stage(Smem* sm, int m, const float* __restrict__ w2,
                            const float* __restrict__ b2, float* __restrict__ outp)
{
    int t = threadIdx.x, lane = t & 31, w = t >> 5;
    const float* hr = g_h + m * 512;
    if (w < 11) {
        const float4* h4 = (const float4*)hr;
        const float4* w4 = (const float4*)(w2 + w * 512);
        float s = dot4(h4[lane], w4[lane]) + dot4(h4[lane + 32], w4[lane + 32]) +
                  dot4(h4[lane + 64], w4[lane + 64]) + dot4(h4[lane + 96], w4[lane + 96]);
        s = warp_red(s);
        if (lane == 0) {
            float v = s + b2[w];
            sm->s.tp[w]      = v;
            outp[m * 11 + w] = v;
        }
    }
    __syncthreads();
}

// ---------------- sampling for query m -> sm->s.agg ----------------
__device__ void sample_stage(Smem* sm, int m, const float* __restrict__ calib,
                             const float* __restrict__ ego)
{
    int t = threadIdx.x;

    if (t < 12) {
        int ci = t % CAMSN, tt = t / CAMSN;
        float* d = sm->s.ctc[t];
        d[0] = ego[tt * 4 + 3] - ego[1 * 4 + 3];
        d[1] = ego[tt * 4 + 0];
        d[2] = ego[tt * 4 + 1];
        float eyaw = ego[tt * 4 + 2];
        d[3] = cosf(eyaw);
        d[4] = sinf(eyaw);
        const float* cal = calib + ci * 8;
        d[5]  = cal[0]; d[6]  = cal[1]; d[7]  = cal[2]; d[8] = cal[3];
        d[9]  = cal[4]; d[10] = cal[5]; d[11] = cal[6];
        d[12] = cosf(cal[7]);
        d[13] = sinf(cal[7]);
    } else if (t == 12) {
        float yaw = sm->s.tp[7];
        sm->s.cs[0] = cosf(yaw);
        sm->s.cs[1] = sinf(yaw);
    }
    __syncthreads();

    // Phase A: project 1800 taps (invalid -> row 0, weight 0)
    for (int idx = t; idx < NTAPS; idx += NT) {
        int pt  = idx % NPTS;
        int ctc = idx / NPTS;
        int ci  = ctc % CAMSN;
        int tt  = ctc / CAMSN;
        const float* d = sm->s.ctc[tt * CAMSN + ci];
        float dt = d[0], ex = d[1], ey = d[2], ce = d[3], se = d[4];
        float fx = d[5], fy = d[6], cx0 = d[7], cy0 = d[8];
        float txc = d[9], tyc = d[10], tzc = d[11], cc = d[12], sc = d[13];

        int face = pt / 25, sub = pt % 25, dim = face >> 1;
        float sign = (face & 1) ? 1.0f : -1.0f;
        float a = -1.0f + 0.5f * (float)(sub / 5);
        float b = -1.0f + 0.5f * (float)(sub % 5);
        float ux, uy, uz;
        if (dim == 0)      { ux = sign; uy = a;    uz = b; }
        else if (dim == 1) { ux = a;    uy = sign; uz = b; }
        else               { ux = a;    uy = b;    uz = sign; }

        float lx = ux * sm->s.tp[8], ly = uy * sm->s.tp[9], lz = uz * sm->s.tp[10];
        float cyw = sm->s.cs[0], syw = sm->s.cs[1];
        float rx = lx * cyw - ly * syw;
        float ry = lx * syw + ly * cyw;
        float cx = sm->s.tp[0] + sm->s.tp[3] * dt + 0.5f * sm->s.tp[5] * dt * dt;
        float cy = sm->s.tp[1] + sm->s.tp[4] * dt + 0.5f * sm->s.tp[6] * dt * dt;
        float wx = rx + cx, wy = ry + cy, wz = lz + sm->s.tp[2];
        float pxr = wx - ex, pyr = wy - ey;
        float gx =  pxr * ce + pyr * se;
        float gy = -pxr * se + pyr * ce;

        float px = gx - txc, py = gy - tyc, pz = wz - tzc;
        float fwd  =  px * cc + py * sc;
        float left = -px * sc + py * cc;
        float zc = fwd, xc = -left, yc = -pz;
        float zs = fmaxf(zc, 0.1f);
        float u = fx * xc / zs + cx0;
        float v = fy * yc / zs + cy0;
        bool valid = (zc > 0.1f) && (u >= 0.f) && (u < 1.f) && (v >= 0.f) && (v < 1.f);

        if (valid) {
            float pxi = u * 159.0f;
            float pyi = v * 63.0f;
            float x0f = floorf(pxi), y0f = floorf(pyi);
            int x0 = (int)x0f, y0 = (int)y0f;
            float wxk = pxi - x0f, wyk = pyi - y0f;
            sm->s.row[idx] = (ci * TSTEP + tt) * PLANE + y0 * WID + x0;
            sm->s.w[idx] = make_float4((1.f - wxk) * (1.f - wyk),
                                       wxk * (1.f - wyk),
                                       (1.f - wxk) * wyk,
                                       wxk * wyk);
        } else {
            sm->s.row[idx] = 0;
            sm->s.w[idx]   = make_float4(0.f, 0.f, 0.f, 0.f);
        }
    }
    __syncthreads();

    // Phase B: 8 groups of 64 threads; thread = 4 channels via uint2 (LDG.64)
    int g = t >> 6;            // 0..7
    int j = t & 63;            // channel quad (channels 4j..4j+3)
    float a0 = 0.f, a1 = 0.f, a2 = 0.f, a3 = 0.f;
    const uint2* fb = (const uint2*)g_featT;
    #pragma unroll 2
    for (int i = g; i < NTAPS; i += 8) {
        int row = sm->s.row[i];
        float4 w4 = sm->s.w[i];
        const uint2* p = fb + (size_t)row * 64 + j;
        uint2 q00 = p[0];
        uint2 q01 = p[64];
        uint2 q10 = p[WID * 64];
        uint2 q11 = p[WID * 64 + 64];
        float2 f00a = __half22float2(*(const __half2*)&q00.x);
        float2 f00b = __half22float2(*(const __half2*)&q00.y);
        float2 f01a = __half22float2(*(const __half2*)&q01.x);
        float2 f01b = __half22float2(*(const __half2*)&q01.y);
        float2 f10a = __half22float2(*(const __half2*)&q10.x);
        float2 f10b = __half22float2(*(const __half2*)&q10.y);
        float2 f11a = __half22float2(*(const __half2*)&q11.x);
        float2 f11b = __half22float2(*(const __half2*)&q11.y);
        a0 = fmaf(f00a.x, w4.x, a0); a1 = fmaf(f00a.y, w4.x, a1);
        a2 = fmaf(f00b.x, w4.x, a2); a3 = fmaf(f00b.y, w4.x, a3);
        a0 = fmaf(f01a.x, w4.y, a0); a1 = fmaf(f01a.y, w4.y, a1);
        a2 = fmaf(f01b.x, w4.y, a2); a3 = fmaf(f01b.y, w4.y, a3);
        a0 = fmaf(f10a.x, w4.z, a0); a1 = fmaf(f10a.y, w4.z, a1);
        a2 = fmaf(f10b.x, w4.z, a2); a3 = fmaf(f10b.y, w4.z, a3);
        a0 = fmaf(f11a.x, w4.w, a0); a1 = fmaf(f11a.y, w4.w, a1);
        a2 = fmaf(f11b.x, w4.w, a2); a3 = fmaf(f11b.y, w4.w, a3);
    }
    if (g > 0) sm->s.buf[g - 1][j] = make_float4(a0, a1, a2, a3);
    __syncthreads();
    if (g == 0) {
        #pragma unroll
        for (int gg = 0; gg < 7; gg++) {
            float4 b = sm->s.buf[gg][j];
            a0 += b.x; a1 += b.y; a2 += b.z; a3 += b.w;
        }
        float4 r = make_float4(a0 * (1.0f / 1800.0f), a1 * (1.0f / 1800.0f),
                               a2 * (1.0f / 1800.0f), a3 * (1.0f / 1800.0f));
        *(float4*)&sm->s.agg[4 * j] = r;
    }
    __syncthreads();
}

// ---------------- persistent mega-kernel ----------------
__global__ void __launch_bounds__(NT, 1)
decoder_kernel(const float* __restrict__ features, const float* __restrict__ calib,
               const float* __restrict__ ego, const float* __restrict__ queries,
               const float* __restrict__ tw1, const float* __restrict__ tb1,
               const float* __restrict__ tw2, const float* __restrict__ tb2,
               const float* __restrict__ fmw1, const float* __restrict__ fmb1,
               const float* __restrict__ fmw2, const float* __restrict__ fmb2,
               const float* __restrict__ saiw, const float* __restrict__ saib,
               const float* __restrict__ saow, const float* __restrict__ saob,
               const float* __restrict__ caiw, const float* __restrict__ caib,
               const float* __restrict__ caow, const float* __restrict__ caob,
               const float* __restrict__ l1w,  const float* __restrict__ l1b,
               const float* __restrict__ l2w,  const float* __restrict__ l2b,
               const float* __restrict__ n1g,  const float* __restrict__ n1b,
               const float* __restrict__ n2g,  const float* __restrict__ n2b,
               const float* __restrict__ n3g,  const float* __restrict__ n3b,
               float* __restrict__ out)
{
    __shared__ Smem sm;
    int m = blockIdx.x;
    int t = threadIdx.x;
    int half = t >> 8;
    int tl   = t & 255;
    int barid = half + 1;
    SmemGemm* sg = &sm.g2.h[half];

    // prologue: copy queries; transpose features -> fp16 pixel-major
    if (t < 256) g_q[m * 256 + t] = queries[m * 256 + t];
    {
        const int PT = PLANE / 32;                   // 320
        const int CT = CFCH / 32;                    // 8
        const int NTILE = CAMSN * TSTEP * PT * CT;   // 30720
        int tx = t & 31, ty = t >> 5;                // 32 x 16
        for (int tile = blockIdx.x; tile < NTILE; tile += NB) {
            int ct  = tile / (PT * CT);
            int rem = tile % (PT * CT);
            int p0 = (rem % PT) * 32;
            int c0 = (rem / PT) * 32;
            const float* in = features + (size_t)ct * CFCH * PLANE;
            __half*      op = g_featT  + (size_t)ct * CFCH * PLANE;
            #pragma unroll
            for (int i = 0; i < 32; i += 16)
                sm.t.tile[ty + i][tx] = in[(size_t)(c0 + ty + i) * PLANE + p0 + tx];
            __syncthreads();
            #pragma unroll
            for (int i = 0; i < 32; i += 16)
                op[(size_t)(p0 + ty + i) * CFCH + c0 + tx] = __float2half_rn(sm.t.tile[tx][ty + i]);
            __syncthreads();
        }
    }
    grid_sync();

    for (int li = 0; li < 6; li++) {
        const float* saiw_l = saiw + li * 768 * 256;
        const float* saib_l = saib + li * 768;
        const float* caiw_l = caiw + li * 768 * 256;
        const float* caib_l = caib + li * 768;

        // ---- S1: GEMM: traj1 (64 tiles) + SA QKV (96 tiles), both read pre-SA g_q
        for (int tile = blockIdx.x * 2 + half; tile < 160; tile += 256) {
            if (tile < 64)
                gemm_tile<1,0>(sg, tl, barid, g_q, tw1, tb1, g_h, 256, 512,
                               (tile & 7) * 16, (tile >> 3) * 64);
            else {
                int u = tile - 64;
                gemm_tile<0,1>(sg, tl, barid, g_q, saiw_l, saib_l, nullptr, 256, 768,
                               (u & 7) * 16, (u >> 3) * 64);
            }
        }
        grid_sync();

        // ---- S2 per-query: SA attn + traj2 + sampling + feature MLP -> g_mem[m]
        attn_full(&sm, m, saow + li * 256 * 256, saob + li * 256,
                  n1g + li * 256, n1b + li * 256, nullptr);
        traj2_stage(&sm, m, tw2, tb2, out + li * 1408);
        sample_stage(&sm, m, calib, ego);
        mv256to512(&sm, sm.s.agg, fmw1, fmb1, sm.s.h);
        mv512to256(&sm, sm.s.h, fmw2, fmb2, g_mem + m * 256);
        grid_sync();

        // ---- S3: GEMM: CA q-proj (32 tiles, g_q) + CA kv-proj (64 tiles, g_mem)
        for (int tile = blockIdx.x * 2 + half; tile < 96; tile += 256) {
            if (tile < 32)
                gemm_tile<0,1>(sg, tl, barid, g_q, caiw_l, caib_l, nullptr, 256, 768,
                               (tile & 7) * 16, (tile >> 3) * 64);
            else {
                int u = tile - 32;
                gemm_tile<0,1>(sg, tl, barid, g_mem, caiw_l, caib_l, nullptr, 256, 768,
                               (u & 7) * 16, 256 + (u >> 3) * 64);
            }
        }
        grid_sync();

        // ---- S4 per-query: CA attn (+resln2, save qrow) + FFN + resln3
        attn_full(&sm, m, caow + li * 256 * 256, caob + li * 256,
                  n2g + li * 256, n2b + li * 256, sm.s.agg);
        mv256to512(&sm, sm.s.agg, l1w + li * 512 * 256, l1b + li * 512, sm.s.h);
        mv512to256(&sm, sm.s.h, l2w + li * 256 * 512, l2b + li * 256, sm.a.tmpv);
        resln_inblock(&sm, m, n3g + li * 256, n3b + li * 256, nullptr);
        grid_sync();
    }

    // epilogue: final traj head
    for (int tile = blockIdx.x * 2 + half; tile < 64; tile += 256)
        gemm_tile<1,0>(sg, tl, barid, g_q, tw1, tb1, g_h, 256, 512,
                       (tile & 7) * 16, (tile >> 3) * 64);
    grid_sync();
    traj2_stage(&sm, m, tw2, tb2, out + 6 * 1408);
}

// ---------------- host: one launch ----------------
extern "C" void kernel_launch(void* const* d_in, const int* in_sizes, int n_in,
                              void* d_out, int out_size)
{
    const float* features = (const float*)d_in[0];
    const float* calib    = (const float*)d_in[1];
    const float* ego      = (const float*)d_in[2];
    const float* queries  = (const float*)d_in[3];
    const float* tw1  = (const float*)d_in[5];
    const float* tb1  = (const float*)d_in[6];
    const float* tw2  = (const float*)d_in[7];
    const float* tb2  = (const float*)d_in[8];
    const float* fmw1 = (const float*)d_in[9];
    const float* fmb1 = (const float*)d_in[10];
    const float* fmw2 = (const float*)d_in[11];
    const float* fmb2 = (const float*)d_in[12];
    const float* saiw = (const float*)d_in[13];
    const float* saib = (const float*)d_in[14];
    const float* saow = (const float*)d_in[15];
    const float* saob = (const float*)d_in[16];
    const float* caiw = (const float*)d_in[17];
    const float* caib = (const float*)d_in[18];
    const float* caow = (const float*)d_in[19];
    const float* caob = (const float*)d_in[20];
    const float* l1w  = (const float*)d_in[21];
    const float* l1b  = (const float*)d_in[22];
    const float* l2w  = (const float*)d_in[23];
    const float* l2b  = (const float*)d_in[24];
    const float* n1g  = (const float*)d_in[25];
    const float* n1b  = (const float*)d_in[26];
    const float* n2g  = (const float*)d_in[27];
    const float* n2b  = (const float*)d_in[28];
    const float* n3g  = (const float*)d_in[29];
    const float* n3b  = (const float*)d_in[30];
    float* out = (float*)d_out;

    decoder_kernel<<<NB, NT>>>(features, calib, ego, queries,
                               tw1, tb1, tw2, tb2,
                               fmw1, fmb1, fmw2, fmb2,
                               saiw, saib, saow, saob,
                               caiw, caib, caow, caob,
                               l1w, l1b, l2w, l2b,
                               n1g, n1b, n2g, n2b, n3g, n3b,
                               out);
}

// round 9
// speedup vs baseline: 2.7515x; 1.1520x over previous
#include <cuda_runtime.h>
#include <cuda_fp16.h>
#include <math.h>

#define NQ    128
#define ED    256
#define DFFD  512
#define CAMSN 6
#define TSTEP 2
#define CFCH  256
#define HGT   64
#define WID   160
#define PLANE (HGT*WID)           /* 10240 */
#define NPTS  150
#define NTAPS (NPTS*CAMSN*TSTEP)  /* 1800 */
#define NB    128
#define NT    512

// ---------------- device scratch ----------------
__device__ float  g_q    [NQ*ED];
__device__ float  g_h    [NQ*DFFD];
__device__ float  g_mem  [NQ*ED];
__device__ float  g_qh   [NQ*ED];
__device__ float  g_kT   [ED*NQ];     // transposed K: [256 dims][128 queries]
__device__ float  g_vh   [NQ*ED];
__device__ __half g_featT[(size_t)CAMSN*TSTEP*PLANE*CFCH];  // 63 MB pixel-major fp16

__device__ unsigned g_bar_arrive;
__device__ unsigned g_bar_gen;

// ---------------- shared memory union ----------------
struct SmemGemm   { float As[2][32][20]; float Ws[2][32][68]; };   // 22528 B
struct SmemGemm2  { SmemGemm h[2]; };                              // 45056 B
struct SmemS2 {                       // per-query stage scratch (< 48 KB)
    float4 w[NTAPS];                  // 28800 B
    float4 buf[8][64];                // 8192 B (sample partials, 2-step reduce)
    int    row[NTAPS];                // 7200 B
    float  agg[256];                  // 1024 B (sampled agg / qrow save)
    float  h[512];                    // 2048 B (MLP hidden)
    float  tp[11];
    float  cs[2];
    float  ctc[12][14];
};
struct SmemAttn {
    float q[256];
    float Ps[8*128];
    float mxp[16];
    float sump[16];
    float ovp[256];
    float ao[256];
    float tmpv[256];
    float red[16];
};
struct SmemTrans  { float tile[32][33]; };
union __align__(16) Smem {
    SmemGemm2  g2;
    SmemS2     s;
    SmemAttn   a;
    SmemTrans  t;
};

// ---------------- named barrier for 256-thread half-CTA ----------------
__device__ __forceinline__ void half_bar(int id)
{
    asm volatile("bar.sync %0, 256;" :: "r"(id) : "memory");
}

// ---------------- software grid barrier (128 CTAs co-resident) ----------------
__device__ __forceinline__ void grid_sync()
{
    __syncthreads();
    if (threadIdx.x == 0) {
        __threadfence();
        unsigned gen = *((volatile unsigned*)&g_bar_gen);
        unsigned t = atomicAdd(&g_bar_arrive, 1u);
        if (t == (unsigned)(gridDim.x - 1)) {
            g_bar_arrive = 0u;
            __threadfence();
            *((volatile unsigned*)&g_bar_gen) = gen + 1u;
        } else {
            while (*((volatile unsigned*)&g_bar_gen) == gen) { }
        }
        __threadfence();
    }
    __syncthreads();
}

__device__ __forceinline__ float warp_red(float v)
{
    #pragma unroll
    for (int o = 16; o; o >>= 1) v += __shfl_xor_sync(0xffffffffu, v, o);
    return v;
}

__device__ __forceinline__ float dot4(float4 a, float4 b)
{
    return fmaf(a.x, b.x, fmaf(a.y, b.y, fmaf(a.z, b.z, a.w * b.w)));
}

// accumulate 8 fp16 channels (uint4) * weight into 4 float2 accumulators
__device__ __forceinline__ void acc8(float2 a[4], uint4 q, float wt)
{
    float2 f;
    f = __half22float2(*(const __half2*)&q.x);
    a[0].x = fmaf(f.x, wt, a[0].x); a[0].y = fmaf(f.y, wt, a[0].y);
    f = __half22float2(*(const __half2*)&q.y);
    a[1].x = fmaf(f.x, wt, a[1].x); a[1].y = fmaf(f.y, wt, a[1].y);
    f = __half22float2(*(const __half2*)&q.z);
    a[2].x = fmaf(f.x, wt, a[2].x); a[2].y = fmaf(f.y, wt, a[2].y);
    f = __half22float2(*(const __half2*)&q.w);
    a[3].x = fmaf(f.x, wt, a[3].x); a[3].y = fmaf(f.y, wt, a[3].y);
}

// ---------------- one 16x64 GEMM tile on a 256-thread half, dbuf K=32 ----------------
template <int ACT, int QKV>
__device__ void gemm_tile(SmemGemm* sg, int tl, int barid,
                          const float* __restrict__ A,
                          const float* __restrict__ W, const float* __restrict__ Bb,
                          float* __restrict__ C, int K, int ldc, int m0, int n0)
{
    int tx = tl & 15;
    int ty = tl >> 4;
    float acc[4] = {0.f, 0.f, 0.f, 0.f};

#define LOAD_CHUNK(k0, b) do {                                                  \
        if (tl < 128) {                                                         \
            int r = tl >> 3, kq = tl & 7;                                       \
            float4 v = *(const float4*)&A[(m0 + r) * K + (k0) + kq * 4];        \
            sg->As[b][kq*4+0][r] = v.x; sg->As[b][kq*4+1][r] = v.y;             \
            sg->As[b][kq*4+2][r] = v.z; sg->As[b][kq*4+3][r] = v.w;             \
        }                                                                        \
        {                                                                        \
            int r = tl >> 2, kq = tl & 3;                                       \
            float4 v0 = *(const float4*)&W[(n0 + r) * K + (k0) + kq * 4];       \
            float4 v1 = *(const float4*)&W[(n0 + r) * K + (k0) + 16 + kq * 4];  \
            sg->Ws[b][kq*4+0][r] = v0.x; sg->Ws[b][kq*4+1][r] = v0.y;           \
            sg->Ws[b][kq*4+2][r] = v0.z; sg->Ws[b][kq*4+3][r] = v0.w;           \
            sg->Ws[b][16+kq*4+0][r] = v1.x; sg->Ws[b][16+kq*4+1][r] = v1.y;     \
            sg->Ws[b][16+kq*4+2][r] = v1.z; sg->Ws[b][16+kq*4+3][r] = v1.w;     \
        }                                                                        \
    } while (0)

    LOAD_CHUNK(0, 0);
    half_bar(barid);
    int p = 0;
    for (int k0 = 0; k0 < K; k0 += 32) {
        if (k0 + 32 < K) LOAD_CHUNK(k0 + 32, p ^ 1);
        #pragma unroll
        for (int k = 0; k < 32; k++) {
            float a  = sg->As[p][k][ty];
            float4 w = *(const float4*)&sg->Ws[p][k][tx*4];
            acc[0] = fmaf(a, w.x, acc[0]);
            acc[1] = fmaf(a, w.y, acc[1]);
            acc[2] = fmaf(a, w.z, acc[2]);
            acc[3] = fmaf(a, w.w, acc[3]);
        }
        half_bar(barid);
        p ^= 1;
    }
#undef LOAD_CHUNK

    int row = m0 + ty;
    int col = n0 + tx * 4;
    float4 bv = *(const float4*)&Bb[col];
    float4 r;
    r.x = acc[0] + bv.x;
    r.y = acc[1] + bv.y;
    r.z = acc[2] + bv.z;
    r.w = acc[3] + bv.w;
    if (ACT) {
        r.x = fmaxf(r.x, 0.f); r.y = fmaxf(r.y, 0.f);
        r.z = fmaxf(r.z, 0.f); r.w = fmaxf(r.w, 0.f);
    }
    if (QKV) {
        if (col < 256) {
            *(float4*)&g_qh[row * 256 + col] = r;
        } else if (col < 512) {
            int kd = col - 256;
            g_kT[(kd+0)*NQ + row] = r.x;
            g_kT[(kd+1)*NQ + row] = r.y;
            g_kT[(kd+2)*NQ + row] = r.z;
            g_kT[(kd+3)*NQ + row] = r.w;
        } else {
            *(float4*)&g_vh[row * 256 + (col - 512)] = r;
        }
    } else {
        *(float4*)&C[row * ldc + col] = r;
    }
}

// ---------------- matvec: out[512] = relu(W[512,256] @ xs[256] + b) ----------------
__device__ void mv256to512(const float* __restrict__ xs,
                           const float* __restrict__ W, const float* __restrict__ Bb,
                           float* __restrict__ hs)
{
    int t = threadIdx.x, lane = t & 31, w = t >> 5;
    const float4* xs4 = (const float4*)xs;
    float4 x0 = xs4[lane], x1 = xs4[lane + 32];
    #pragma unroll 1
    for (int ci = 0; ci < 32; ci += 4) {
        int c0 = w * 32 + ci;
        const float4* w0 = (const float4*)(W + (size_t)(c0 + 0) * 256);
        const float4* w1 = (const float4*)(W + (size_t)(c0 + 1) * 256);
        const float4* w2 = (const float4*)(W + (size_t)(c0 + 2) * 256);
        const float4* w3 = (const float4*)(W + (size_t)(c0 + 3) * 256);
        float a0 = dot4(x0, w0[lane]) + dot4(x1, w0[lane + 32]);
        float a1 = dot4(x0, w1[lane]) + dot4(x1, w1[lane + 32]);
        float a2 = dot4(x0, w2[lane]) + dot4(x1, w2[lane + 32]);
        float a3 = dot4(x0, w3[lane]) + dot4(x1, w3[lane + 32]);
        #pragma unroll
        for (int o = 16; o; o >>= 1) {
            a0 += __shfl_xor_sync(0xffffffffu, a0, o);
            a1 += __shfl_xor_sync(0xffffffffu, a1, o);
            a2 += __shfl_xor_sync(0xffffffffu, a2, o);
            a3 += __shfl_xor_sync(0xffffffffu, a3, o);
        }
        if (lane == 0) {
            hs[c0 + 0] = fmaxf(a0 + Bb[c0 + 0], 0.f);
            hs[c0 + 1] = fmaxf(a1 + Bb[c0 + 1], 0.f);
            hs[c0 + 2] = fmaxf(a2 + Bb[c0 + 2], 0.f);
            hs[c0 + 3] = fmaxf(a3 + Bb[c0 + 3], 0.f);
        }
    }
    __syncthreads();
}

// ---------------- matvec: out[256] = W[256,512] @ xs[512] + b ----------------
__device__ void mv512to256(const float* __restrict__ xs,
                           const float* __restrict__ W, const float* __restrict__ Bb,
                           float* __restrict__ outv)
{
    int t = threadIdx.x, lane = t & 31, w = t >> 5;
    const float4* xs4 = (const float4*)xs;
    float4 x0 = xs4[lane], x1 = xs4[lane + 32], x2 = xs4[lane + 64], x3 = xs4[lane + 96];
    #pragma unroll 1
    for (int ci = 0; ci < 16; ci += 4) {
        int c0 = w * 16 + ci;
        const float4* w0 = (const float4*)(W + (size_t)(c0 + 0) * 512);
        const float4* w1 = (const float4*)(W + (size_t)(c0 + 1) * 512);
        const float4* w2 = (const float4*)(W + (size_t)(c0 + 2) * 512);
        const float4* w3 = (const float4*)(W + (size_t)(c0 + 3) * 512);
        float a0 = (dot4(x0, w0[lane]) + dot4(x1, w0[lane+32])) + (dot4(x2, w0[lane+64]) + dot4(x3, w0[lane+96]));
        float a1 = (dot4(x0, w1[lane]) + dot4(x1, w1[lane+32])) + (dot4(x2, w1[lane+64]) + dot4(x3, w1[lane+96]));
        float a2 = (dot4(x0, w2[lane]) + dot4(x1, w2[lane+32])) + (dot4(x2, w2[lane+64]) + dot4(x3, w2[lane+96]));
        float a3 = (dot4(x0, w3[lane]) + dot4(x1, w3[lane+32])) + (dot4(x2, w3[lane+64]) + dot4(x3, w3[lane+96]));
        #pragma unroll
        for (int o = 16; o; o >>= 1) {
            a0 += __shfl_xor_sync(0xffffffffu, a0, o);
            a1 += __shfl_xor_sync(0xffffffffu, a1, o);
            a2 += __shfl_xor_sync(0xffffffffu, a2, o);
            a3 += __shfl_xor_sync(0xffffffffu, a3, o);
        }
        if (lane == 0) {
            outv[c0 + 0] = a0 + Bb[c0 + 0];
            outv[c0 + 1] = a1 + Bb[c0 + 1];
            outv[c0 + 2] = a2 + Bb[c0 + 2];
            outv[c0 + 3] = a3 + Bb[c0 + 3];
        }
    }
    __syncthreads();
}

// ---------------- residual add + LayerNorm (tmpv in smem); optional smem save ----------------
__device__ void resln_inblock(Smem* sm, int m, const float* __restrict__ lng,
                              const float* __restrict__ lnb, float* qsave)
{
    int t = threadIdx.x, lane = t & 31, w = t >> 5;
    float x = 0.f;
    if (t < 256) x = g_q[m * 256 + t] + sm->a.tmpv[t];

    float v = warp_red(x);
    if (lane == 0) sm->a.red[w] = v;
    __syncthreads();
    float tot = 0.f;
    #pragma unroll
    for (int kk = 0; kk < 8; kk++) tot += sm->a.red[kk];
    float mean = tot * (1.0f / 256.0f);
    float xm = x - mean;
    __syncthreads();
    float v2 = warp_red((t < 256) ? xm * xm : 0.f);
    if (lane == 0) sm->a.red[w] = v2;
    __syncthreads();
    float tv = 0.f;
    #pragma unroll
    for (int kk = 0; kk < 8; kk++) tv += sm->a.red[kk];
    float var = tv * (1.0f / 256.0f);
    if (t < 256) {
        float r = xm * rsqrtf(var + 1e-5f) * lng[t] + lnb[t];
        g_q[m * 256 + t] = r;
        if (qsave) qsave[t] = r;
    }
    __syncthreads();
}

// ---------------- full attention for query m ----------------
__device__ void attn_full(Smem* sm, int m,
                          const float* __restrict__ Wo, const float* __restrict__ bo,
                          const float* __restrict__ lng, const float* __restrict__ lnb,
                          float* qsave)
{
    int t = threadIdx.x, lane = t & 31, w = t >> 5;
    int h = w >> 1, part = w & 1;
    int jb = part * 64;

    if (t < 256) sm->a.q[t] = g_qh[m * 256 + t];
    __syncthreads();

    const float* kTh = g_kT + (h * 32) * NQ;
    float s0 = 0.f, s1 = 0.f;
    #pragma unroll
    for (int d = 0; d < 32; d++) {
        float qd = sm->a.q[h * 32 + d];
        s0 = fmaf(qd, kTh[d * NQ + jb + lane], s0);
        s1 = fmaf(qd, kTh[d * NQ + jb + 32 + lane], s1);
    }
    s0 *= 0.17677669529663687f;   // 1/sqrt(32)
    s1 *= 0.17677669529663687f;

    float mx = fmaxf(s0, s1);
    #pragma unroll
    for (int o = 16; o; o >>= 1) mx = fmaxf(mx, __shfl_xor_sync(0xffffffffu, mx, o));
    if (lane == 0) sm->a.mxp[w] = mx;
    __syncthreads();
    mx = fmaxf(sm->a.mxp[h * 2], sm->a.mxp[h * 2 + 1]);

    float e0 = expf(s0 - mx), e1 = expf(s1 - mx);
    float ps = warp_red(e0 + e1);
    if (lane == 0) sm->a.sump[w] = ps;
    __syncthreads();
    float inv = 1.0f / (sm->a.sump[h * 2] + sm->a.sump[h * 2 + 1]);

    sm->a.Ps[h * 128 + jb + lane]      = e0 * inv;
    sm->a.Ps[h * 128 + jb + 32 + lane] = e1 * inv;
    __syncthreads();

    float ov = 0.f;
    for (int j = jb; j < jb + 64; j++)
        ov = fmaf(sm->a.Ps[h * 128 + j], g_vh[j * 256 + h * 32 + lane], ov);
    if (part == 1) sm->a.ovp[h * 32 + lane] = ov;
    __syncthreads();
    if (part == 0) sm->a.ao[h * 32 + lane] = ov + sm->a.ovp[h * 32 + lane];
    __syncthreads();

    // out-projection: 16 warps x 16 cols, 4-col groups for ILP
    {
        const float4* av = (const float4*)sm->a.ao;
        float4 x0 = av[lane], x1 = av[lane + 32];
        #pragma unroll 1
        for (int ci = 0; ci < 16; ci += 4) {
            int c0 = w * 16 + ci;
            const float4* w0 = (const float4*)(Wo + (size_t)(c0 + 0) * 256);
            const float4* w1 = (const float4*)(Wo + (size_t)(c0 + 1) * 256);
            const float4* w2 = (const float4*)(Wo + (size_t)(c0 + 2) * 256);
            const float4* w3 = (const float4*)(Wo + (size_t)(c0 + 3) * 256);
            float a0 = dot4(x0, w0[lane]) + dot4(x1, w0[lane + 32]);
            float a1 = dot4(x0, w1[lane]) + dot4(x1, w1[lane + 32]);
            float a2 = dot4(x0, w2[lane]) + dot4(x1, w2[lane + 32]);
            float a3 = dot4(x0, w3[lane]) + dot4(x1, w3[lane + 32]);
            #pragma unroll
            for (int o = 16; o; o >>= 1) {
                a0 += __shfl_xor_sync(0xffffffffu, a0, o);
                a1 += __shfl_xor_sync(0xffffffffu, a1, o);
                a2 += __shfl_xor_sync(0xffffffffu, a2, o);
                a3 += __shfl_xor_sync(0xffffffffu, a3, o);
            }
            if (lane == 0) {
                sm->a.tmpv[c0 + 0] = a0 + bo[c0 + 0];
                sm->a.tmpv[c0 + 1] = a1 + bo[c0 + 1];
                sm->a.tmpv[c0 + 2] = a2 + bo[c0 + 2];
                sm->a.tmpv[c0 + 3] = a3 + bo[c0 + 3];
            }
        }
    }
    __syncthreads();

    resln_inblock(sm, m, lng, lnb, qsave);
}

// ---------------- traj head stage 2 ----------------
__device__ void traj2_stage(Smem* sm, int m, const float* __restrict__ w2,
                            const float* __restrict__ b2, float* __restrict__ outp)
{
    int t = threadIdx.x, lane = t & 31, w = t >> 5;
    const float* hr = g_h + m * 512;
    if (w < 11) {
        const float4* h4 = (const float4*)hr;
        const float4* w4 = (const float4*)(w2 + w * 512);
        float s = dot4(h4[lane], w4[lane]) + dot4(h4[lane + 32], w4[lane + 32]) +
                  dot4(h4[lane + 64], w4[lane + 64]) + dot4(h4[lane + 96], w4[lane + 96]);
        s = warp_red(s);
        if (lane == 0) {
            float v = s + b2[w];
            sm->s.tp[w]      = v;
            outp[m * 11 + w] = v;
        }
    }
    __syncthreads();
}

// ---------------- sampling for query m -> sm->s.agg ----------------
__device__ void sample_stage(Smem* sm, int m, const float* __restrict__ calib,
                             const float* __restrict__ ego)
{
    int t = threadIdx.x;

    if (t < 12) {
        int ci = t % CAMSN, tt = t / CAMSN;
        float* d = sm->s.ctc[t];
        d[0] = ego[tt * 4 + 3] - ego[1 * 4 + 3];
        d[1] = ego[tt * 4 + 0];
        d[2] = ego[tt * 4 + 1];
        float eyaw = ego[tt * 4 + 2];
        d[3] = cosf(eyaw);
        d[4] = sinf(eyaw);
        const float* cal = calib + ci * 8;
        d[5]  = cal[0]; d[6]  = cal[1]; d[7]  = cal[2]; d[8] = cal[3];
        d[9]  = cal[4]; d[10] = cal[5]; d[11] = cal[6];
        d[12] = cosf(cal[7]);
        d[13] = sinf(cal[7]);
    } else if (t == 12) {
        float yaw = sm->s.tp[7];
        sm->s.cs[0] = cosf(yaw);
        sm->s.cs[1] = sinf(yaw);
    }
    __syncthreads();

    // Phase A: project 1800 taps (invalid -> row 0, weight 0)
    for (int idx = t; idx < NTAPS; idx += NT) {
        int pt  = idx % NPTS;
        int ctc = idx / NPTS;
        int ci  = ctc % CAMSN;
        int tt  = ctc / CAMSN;
        const float* d = sm->s.ctc[tt * CAMSN + ci];
        float dt = d[0], ex = d[1], ey = d[2], ce = d[3], se = d[4];
        float fx = d[5], fy = d[6], cx0 = d[7], cy0 = d[8];
        float txc = d[9], tyc = d[10], tzc = d[11], cc = d[12], sc = d[13];

        int face = pt / 25, sub = pt % 25, dim = face >> 1;
        float sign = (face & 1) ? 1.0f : -1.0f;
        float a = -1.0f + 0.5f * (float)(sub / 5);
        float b = -1.0f + 0.5f * (float)(sub % 5);
        float ux, uy, uz;
        if (dim == 0)      { ux = sign; uy = a;    uz = b; }
        else if (dim == 1) { ux = a;    uy = sign; uz = b; }
        else               { ux = a;    uy = b;    uz = sign; }

        float lx = ux * sm->s.tp[8], ly = uy * sm->s.tp[9], lz = uz * sm->s.tp[10];
        float cyw = sm->s.cs[0], syw = sm->s.cs[1];
        float rx = lx * cyw - ly * syw;
        float ry = lx * syw + ly * cyw;
        float cx = sm->s.tp[0] + sm->s.tp[3] * dt + 0.5f * sm->s.tp[5] * dt * dt;
        float cy = sm->s.tp[1] + sm->s.tp[4] * dt + 0.5f * sm->s.tp[6] * dt * dt;
        float wx = rx + cx, wy = ry + cy, wz = lz + sm->s.tp[2];
        float pxr = wx - ex, pyr = wy - ey;
        float gx =  pxr * ce + pyr * se;
        float gy = -pxr * se + pyr * ce;

        float px = gx - txc, py = gy - tyc, pz = wz - tzc;
        float fwd  =  px * cc + py * sc;
        float left = -px * sc + py * cc;
        float zc = fwd, xc = -left, yc = -pz;
        float zs = fmaxf(zc, 0.1f);
        float u = fx * xc / zs + cx0;
        float v = fy * yc / zs + cy0;
        bool valid = (zc > 0.1f) && (u >= 0.f) && (u < 1.f) && (v >= 0.f) && (v < 1.f);

        if (valid) {
            float pxi = u * 159.0f;
            float pyi = v * 63.0f;
            float x0f = floorf(pxi), y0f = floorf(pyi);
            int x0 = (int)x0f, y0 = (int)y0f;
            float wxk = pxi - x0f, wyk = pyi - y0f;
            sm->s.row[idx] = (ci * TSTEP + tt) * PLANE + y0 * WID + x0;
            sm->s.w[idx] = make_float4((1.f - wxk) * (1.f - wyk),
                                       wxk * (1.f - wyk),
                                       (1.f - wxk) * wyk,
                                       wxk * wyk);
        } else {
            sm->s.row[idx] = 0;
            sm->s.w[idx]   = make_float4(0.f, 0.f, 0.f, 0.f);
        }
    }
    __syncthreads();

    // Phase B: 16 groups of 32 threads; thread = 8 channels via uint4 (LDG.128)
    int g = t >> 5;            // 0..15
    int j = t & 31;            // channel octet: channels 8j..8j+7
    float2 a4[4] = {{0.f,0.f},{0.f,0.f},{0.f,0.f},{0.f,0.f}};
    const uint4* fb = (const uint4*)g_featT;   // row stride = 256ch*2B/16B = 32
    #pragma unroll 2
    for (int i = g; i < NTAPS; i += 16) {
        int row = sm->s.row[i];
        float4 w4 = sm->s.w[i];
        const uint4* p = fb + (size_t)row * 32 + j;
        uint4 q00 = p[0];
        uint4 q01 = p[32];
        uint4 q10 = p[WID * 32];
        uint4 q11 = p[WID * 32 + 32];
        acc8(a4, q00, w4.x);
        acc8(a4, q01, w4.y);
        acc8(a4, q10, w4.z);
        acc8(a4, q11, w4.w);
    }
    // two-step deterministic reduction: 16 -> 8 -> 1
    if (g >= 8) {
        sm->s.buf[g - 8][j * 2 + 0] = make_float4(a4[0].x, a4[0].y, a4[1].x, a4[1].y);
        sm->s.buf[g - 8][j * 2 + 1] = make_float4(a4[2].x, a4[2].y, a4[3].x, a4[3].y);
    }
    __syncthreads();
    if (g < 8) {
        float4 b0 = sm->s.buf[g][j * 2 + 0];
        float4 b1 = sm->s.buf[g][j * 2 + 1];
        a4[0].x += b0.x; a4[0].y += b0.y; a4[1].x += b0.z; a4[1].y += b0.w;
        a4[2].x += b1.x; a4[2].y += b1.y; a4[3].x += b1.z; a4[3].y += b1.w;
    }
    __syncthreads();
    if (g >= 1 && g < 8) {
        sm->s.buf[g - 1][j * 2 + 0] = make_float4(a4[0].x, a4[0].y, a4[1].x, a4[1].y);
        sm->s.buf[g - 1][j * 2 + 1] = make_float4(a4[2].x, a4[2].y, a4[3].x, a4[3].y);
    }
    __syncthreads();
    if (g == 0) {
        #pragma unroll
        for (int gg = 0; gg < 7; gg++) {
            float4 b0 = sm->s.buf[gg][j * 2 + 0];
            float4 b1 = sm->s.buf[gg][j * 2 + 1];
            a4[0].x += b0.x; a4[0].y += b0.y; a4[1].x += b0.z; a4[1].y += b0.w;
            a4[2].x += b1.x; a4[2].y += b1.y; a4[3].x += b1.z; a4[3].y += b1.w;
        }
        const float sc = 1.0f / 1800.0f;
        *(float4*)&sm->s.agg[8 * j]     = make_float4(a4[0].x * sc, a4[0].y * sc, a4[1].x * sc, a4[1].y * sc);
        *(float4*)&sm->s.agg[8 * j + 4] = make_float4(a4[2].x * sc, a4[2].y * sc, a4[3].x * sc, a4[3].y * sc);
    }
    __syncthreads();
}

// ---------------- persistent mega-kernel ----------------
__global__ void __launch_bounds__(NT, 1)
decoder_kernel(const float* __restrict__ features, const float* __restrict__ calib,
               const float* __restrict__ ego, const float* __restrict__ queries,
               const float* __restrict__ tw1, const float* __restrict__ tb1,
               const float* __restrict__ tw2, const float* __restrict__ tb2,
               const float* __restrict__ fmw1, const float* __restrict__ fmb1,
               const float* __restrict__ fmw2, const float* __restrict__ fmb2,
               const float* __restrict__ saiw, const float* __restrict__ saib,
               const float* __restrict__ saow, const float* __restrict__ saob,
               const float* __restrict__ caiw, const float* __restrict__ caib,
               const float* __restrict__ caow, const float* __restrict__ caob,
               const float* __restrict__ l1w,  const float* __restrict__ l1b,
               const float* __restrict__ l2w,  const float* __restrict__ l2b,
               const float* __restrict__ n1g,  const float* __restrict__ n1b,
               const float* __restrict__ n2g,  const float* __restrict__ n2b,
               const float* __restrict__ n3g,  const float* __restrict__ n3b,
               float* __restrict__ out)
{
    __shared__ Smem sm;
    int m = blockIdx.x;
    int t = threadIdx.x;
    int half = t >> 8;
    int tl   = t & 255;
    int barid = half + 1;
    SmemGemm* sg = &sm.g2.h[half];

    // prologue: copy queries; transpose features -> fp16 pixel-major
    if (t < 256) g_q[m * 256 + t] = queries[m * 256 + t];
    {
        const int PT = PLANE / 32;                   // 320
        const int CT = CFCH / 32;                    // 8
        const int NTILE = CAMSN * TSTEP * PT * CT;   // 30720
        int tx = t & 31, ty = t >> 5;                // 32 x 16
        for (int tile = blockIdx.x; tile < NTILE; tile += NB) {
            int ct  = tile / (PT * CT);
            int rem = tile % (PT * CT);
            int p0 = (rem % PT) * 32;
            int c0 = (rem / PT) * 32;
            const float* in = features + (size_t)ct * CFCH * PLANE;
            __half*      op = g_featT  + (size_t)ct * CFCH * PLANE;
            #pragma unroll
            for (int i = 0; i < 32; i += 16)
                sm.t.tile[ty + i][tx] = in[(size_t)(c0 + ty + i) * PLANE + p0 + tx];
            __syncthreads();
            #pragma unroll
            for (int i = 0; i < 32; i += 16)
                op[(size_t)(p0 + ty + i) * CFCH + c0 + tx] = __float2half_rn(sm.t.tile[tx][ty + i]);
            __syncthreads();
        }
    }
    grid_sync();

    for (int li = 0; li < 6; li++) {
        const float* saiw_l = saiw + li * 768 * 256;
        const float* saib_l = saib + li * 768;
        const float* caiw_l = caiw + li * 768 * 256;
        const float* caib_l = caib + li * 768;

        // ---- S1: GEMM: traj1 (64 tiles) + SA QKV (96 tiles), both read pre-SA g_q
        for (int tile = blockIdx.x * 2 + half; tile < 160; tile += 256) {
            if (tile < 64)
                gemm_tile<1,0>(sg, tl, barid, g_q, tw1, tb1, g_h, 256, 512,
                               (tile & 7) * 16, (tile >> 3) * 64);
            else {
                int u = tile - 64;
                gemm_tile<0,1>(sg, tl, barid, g_q, saiw_l, saib_l, nullptr, 256, 768,
                               (u & 7) * 16, (u >> 3) * 64);
            }
        }
        grid_sync();

        // ---- S2 per-query: SA attn + traj2 + sampling + feature MLP -> g_mem[m]
        attn_full(&sm, m, saow + li * 256 * 256, saob + li * 256,
                  n1g + li * 256, n1b + li * 256, nullptr);
        traj2_stage(&sm, m, tw2, tb2, out + li * 1408);
        sample_stage(&sm, m, calib, ego);
        mv256to512(sm.s.agg, fmw1, fmb1, sm.s.h);
        mv512to256(sm.s.h, fmw2, fmb2, g_mem + m * 256);
        grid_sync();

        // ---- S3: GEMM: CA q-proj (32 tiles, g_q) + CA kv-proj (64 tiles, g_mem)
        for (int tile = blockIdx.x * 2 + half; tile < 96; tile += 256) {
            if (tile < 32)
                gemm_tile<0,1>(sg, tl, barid, g_q, caiw_l, caib_l, nullptr, 256, 768,
                               (tile & 7) * 16, (tile >> 3) * 64);
            else {
                int u = tile - 32;
                gemm_tile<0,1>(sg, tl, barid, g_mem, caiw_l, caib_l, nullptr, 256, 768,
                               (u & 7) * 16, 256 + (u >> 3) * 64);
            }
        }
        grid_sync();

        // ---- S4 per-query: CA attn (+resln2, save qrow) + FFN + resln3
        attn_full(&sm, m, caow + li * 256 * 256, caob + li * 256,
                  n2g + li * 256, n2b + li * 256, sm.s.agg);
        mv256to512(sm.s.agg, l1w + li * 512 * 256, l1b + li * 512, sm.s.h);
        mv512to256(sm.s.h, l2w + li * 256 * 512, l2b + li * 256, sm.a.tmpv);
        resln_inblock(&sm, m, n3g + li * 256, n3b + li * 256, nullptr);
        grid_sync();
    }

    // epilogue: final traj head
    for (int tile = blockIdx.x * 2 + half; tile < 64; tile += 256)
        gemm_tile<1,0>(sg, tl, barid, g_q, tw1, tb1, g_h, 256, 512,
                       (tile & 7) * 16, (tile >> 3) * 64);
    grid_sync();
    traj2_stage(&sm, m, tw2, tb2, out + 6 * 1408);
}

// ---------------- host: one launch ----------------
extern "C" void kernel_launch(void* const* d_in, const int* in_sizes, int n_in,
                              void* d_out, int out_size)
{
    const float* features = (const float*)d_in[0];
    const float* calib    = (const float*)d_in[1];
    const float* ego      = (const float*)d_in[2];
    const float* queries  = (const float*)d_in[3];
    const float* tw1  = (const float*)d_in[5];
    const float* tb1  = (const float*)d_in[6];
    const float* tw2  = (const float*)d_in[7];
    const float* tb2  = (const float*)d_in[8];
    const float* fmw1 = (const float*)d_in[9];
    const float* fmb1 = (const float*)d_in[10];
    const float* fmw2 = (const float*)d_in[11];
    const float* fmb2 = (const float*)d_in[12];
    const float* saiw = (const float*)d_in[13];
    const float* saib = (const float*)d_in[14];
    const float* saow = (const float*)d_in[15];
    const float* saob = (const float*)d_in[16];
    const float* caiw = (const float*)d_in[17];
    const float* caib = (const float*)d_in[18];
    const float* caow = (const float*)d_in[19];
    const float* caob = (const float*)d_in[20];
    const float* l1w  = (const float*)d_in[21];
    const float* l1b  = (const float*)d_in[22];
    const float* l2w  = (const float*)d_in[23];
    const float* l2b  = (const float*)d_in[24];
    const float* n1g  = (const float*)d_in[25];
    const float* n1b  = (const float*)d_in[26];
    const float* n2g  = (const float*)d_in[27];
    const float* n2b  = (const float*)d_in[28];
    const float* n3g  = (const float*)d_in[29];
    const float* n3b  = (const float*)d_in[30];
    float* out = (float*)d_out;

    decoder_kernel<<<NB, NT>>>(features, calib, ego, queries,
                               tw1, tb1, tw2, tb2,
                               fmw1, fmb1, fmw2, fmb2,
                               saiw, saib, saow, saob,
                               caiw, caib, caow, caob,
                               l1w, l1b, l2w, l2b,
                               n1g, n1b, n2g, n2b, n3g, n3b,
                               out);
}

// round 10
// speedup vs baseline: 2.9347x; 1.0666x over previous
#include <cuda_runtime.h>
#include <cuda_fp16.h>
#include <math.h>

#define NQ    128
#define ED    256
#define DFFD  512
#define CAMSN 6
#define TSTEP 2
#define CFCH  256
#define HGT   64
#define WID   160
#define PLANE (HGT*WID)           /* 10240 */
#define NPTS  150
#define NTAPS (NPTS*CAMSN*TSTEP)  /* 1800 */
#define NB    128
#define NT    512

// ---------------- device scratch ----------------
__device__ float  g_q    [NQ*ED];
__device__ float  g_h    [NQ*DFFD];
__device__ float  g_mem  [NQ*ED];
__device__ float  g_qh   [NQ*ED];
__device__ float  g_kT   [ED*NQ];     // transposed K: [256 dims][128 queries]
__device__ float  g_vh   [NQ*ED];
__device__ __half g_featT[(size_t)CAMSN*TSTEP*PLANE*CFCH];  // 63 MB pixel-major fp16

// transposed matvec weights: WT[k][c]
__device__ float  g_fmw1T[256*512];
__device__ float  g_fmw2T[512*256];
__device__ float  g_l1wT [6*256*512];
__device__ float  g_l2wT [6*512*256];
__device__ float  g_saowT[6*256*256];
__device__ float  g_caowT[6*256*256];

__device__ unsigned g_bar_arrive;
__device__ unsigned g_bar_gen;

// ---------------- shared memory union ----------------
struct SmemGemm   { float As[2][32][20]; float Ws[2][32][68]; };   // 22528 B
struct SmemGemm2  { SmemGemm h[2]; };                              // 45056 B
struct SmemS2 {                       // per-query stage scratch
    uint4  w[NTAPS];                  // 28800 B (4x duplicated half2 weights)
    float4 buf[8][64];                // 8192 B (sample partials)
    int    row[NTAPS];                // 7200 B
    float  agg[256];                  // sampled agg / qrow save
    float  h[512];                    // MLP hidden
    float  tp[11];
    float  cs[2];
    float  ctc[12][14];
};                                    // ~47.0 KB
struct SmemAttn {
    float  q[256];
    float  Ps[8*128];
    float  mxp[16];
    float  sump[16];
    float  ovp[256];
    float  ao[256];
    float  tmpv[256];
    float  red[16];
    float4 pbuf[448];                 // 7168 B matvec partials
};                                    // ~15.2 KB (aliases low part of SmemS2.w)
struct SmemTrans  { float tile[32][33]; };
union __align__(16) Smem {
    SmemGemm2  g2;
    SmemS2     s;
    SmemAttn   a;
    SmemTrans  t;
};

// ---------------- named barrier for 256-thread half-CTA ----------------
__device__ __forceinline__ void half_bar(int id)
{
    asm volatile("bar.sync %0, 256;" :: "r"(id) : "memory");
}

// ---------------- software grid barrier (128 CTAs co-resident) ----------------
__device__ __forceinline__ void grid_sync()
{
    __syncthreads();
    if (threadIdx.x == 0) {
        __threadfence();
        unsigned gen = *((volatile unsigned*)&g_bar_gen);
        unsigned t = atomicAdd(&g_bar_arrive, 1u);
        if (t == (unsigned)(gridDim.x - 1)) {
            g_bar_arrive = 0u;
            __threadfence();
            *((volatile unsigned*)&g_bar_gen) = gen + 1u;
        } else {
            while (*((volatile unsigned*)&g_bar_gen) == gen) { }
        }
        __threadfence();
    }
    __syncthreads();
}

__device__ __forceinline__ float warp_red(float v)
{
    #pragma unroll
    for (int o = 16; o; o >>= 1) v += __shfl_xor_sync(0xffffffffu, v, o);
    return v;
}

__device__ __forceinline__ float dot4(float4 a, float4 b)
{
    return fmaf(a.x, b.x, fmaf(a.y, b.y, fmaf(a.z, b.z, a.w * b.w)));
}

// ---------------- generic 32x32-tiled transpose: dst[C][R] = src[R][C]^T ----------------
__device__ void wtrans(Smem* sm, const float* __restrict__ src, float* __restrict__ dst,
                       int R, int C)
{
    int t = threadIdx.x;
    int tx = t & 31, ty = t >> 5;     // 32 x 16
    int rt = R >> 5;
    int nt = rt * (C >> 5);
    for (int tile = blockIdx.x; tile < nt; tile += NB) {
        int r0 = (tile % rt) << 5;
        int c0 = (tile / rt) << 5;
        #pragma unroll
        for (int i = 0; i < 32; i += 16)
            sm->t.tile[ty + i][tx] = src[(size_t)(r0 + ty + i) * C + c0 + tx];
        __syncthreads();
        #pragma unroll
        for (int i = 0; i < 32; i += 16)
            dst[(size_t)(c0 + ty + i) * R + r0 + tx] = sm->t.tile[tx][ty + i];
        __syncthreads();
    }
}

// ---------------- one 16x64 GEMM tile on a 256-thread half, dbuf K=32 ----------------
template <int ACT, int QKV>
__device__ void gemm_tile(SmemGemm* sg, int tl, int barid,
                          const float* __restrict__ A,
                          const float* __restrict__ W, const float* __restrict__ Bb,
                          float* __restrict__ C, int K, int ldc, int m0, int n0)
{
    int tx = tl & 15;
    int ty = tl >> 4;
    float acc[4] = {0.f, 0.f, 0.f, 0.f};

#define LOAD_CHUNK(k0, b) do {                                                  \
        if (tl < 128) {                                                         \
            int r = tl >> 3, kq = tl & 7;                                       \
            float4 v = *(const float4*)&A[(m0 + r) * K + (k0) + kq * 4];        \
            sg->As[b][kq*4+0][r] = v.x; sg->As[b][kq*4+1][r] = v.y;             \
            sg->As[b][kq*4+2][r] = v.z; sg->As[b][kq*4+3][r] = v.w;             \
        }                                                                        \
        {                                                                        \
            int r = tl >> 2, kq = tl & 3;                                       \
            float4 v0 = *(const float4*)&W[(n0 + r) * K + (k0) + kq * 4];       \
            float4 v1 = *(const float4*)&W[(n0 + r) * K + (k0) + 16 + kq * 4];  \
            sg->Ws[b][kq*4+0][r] = v0.x; sg->Ws[b][kq*4+1][r] = v0.y;           \
            sg->Ws[b][kq*4+2][r] = v0.z; sg->Ws[b][kq*4+3][r] = v0.w;           \
            sg->Ws[b][16+kq*4+0][r] = v1.x; sg->Ws[b][16+kq*4+1][r] = v1.y;     \
            sg->Ws[b][16+kq*4+2][r] = v1.z; sg->Ws[b][16+kq*4+3][r] = v1.w;     \
        }                                                                        \
    } while (0)

    LOAD_CHUNK(0, 0);
    half_bar(barid);
    int p = 0;
    for (int k0 = 0; k0 < K; k0 += 32) {
        if (k0 + 32 < K) LOAD_CHUNK(k0 + 32, p ^ 1);
        #pragma unroll
        for (int k = 0; k < 32; k++) {
            float a  = sg->As[p][k][ty];
            float4 w = *(const float4*)&sg->Ws[p][k][tx*4];
            acc[0] = fmaf(a, w.x, acc[0]);
            acc[1] = fmaf(a, w.y, acc[1]);
            acc[2] = fmaf(a, w.z, acc[2]);
            acc[3] = fmaf(a, w.w, acc[3]);
        }
        half_bar(barid);
        p ^= 1;
    }
#undef LOAD_CHUNK

    int row = m0 + ty;
    int col = n0 + tx * 4;
    float4 bv = *(const float4*)&Bb[col];
    float4 r;
    r.x = acc[0] + bv.x;
    r.y = acc[1] + bv.y;
    r.z = acc[2] + bv.z;
    r.w = acc[3] + bv.w;
    if (ACT) {
        r.x = fmaxf(r.x, 0.f); r.y = fmaxf(r.y, 0.f);
        r.z = fmaxf(r.z, 0.f); r.w = fmaxf(r.w, 0.f);
    }
    if (QKV) {
        if (col < 256) {
            *(float4*)&g_qh[row * 256 + col] = r;
        } else if (col < 512) {
            int kd = col - 256;
            g_kT[(kd+0)*NQ + row] = r.x;
            g_kT[(kd+1)*NQ + row] = r.y;
            g_kT[(kd+2)*NQ + row] = r.z;
            g_kT[(kd+3)*NQ + row] = r.w;
        } else {
            *(float4*)&g_vh[row * 256 + (col - 512)] = r;
        }
    } else {
        *(float4*)&C[row * ldc + col] = r;
    }
}

// ---------------- shuffle-free matvecs on transposed weights WT[k][c] ----------------
// out[512] = relu(WT^T x[256] + b); 128 col-quads x 4 k-splits of 64
__device__ void mvT_256to512(const float* __restrict__ xs, const float* __restrict__ WT,
                             const float* __restrict__ Bb, float* __restrict__ hs,
                             float4* pbuf)
{
    int t = threadIdx.x;
    int quad = t & 127;
    int ks = t >> 7;
    const float4* wt = (const float4*)WT;   // row stride 128 float4
    float4 acc = {0.f, 0.f, 0.f, 0.f};
    int kb = ks * 64;
    #pragma unroll 8
    for (int k = 0; k < 64; k++) {
        float xk = xs[kb + k];
        float4 w = wt[(size_t)(kb + k) * 128 + quad];
        acc.x = fmaf(xk, w.x, acc.x);
        acc.y = fmaf(xk, w.y, acc.y);
        acc.z = fmaf(xk, w.z, acc.z);
        acc.w = fmaf(xk, w.w, acc.w);
    }
    if (ks > 0) pbuf[(ks - 1) * 128 + quad] = acc;
    __syncthreads();
    if (ks == 0) {
        #pragma unroll
        for (int p = 0; p < 3; p++) {
            float4 b = pbuf[p * 128 + quad];
            acc.x += b.x; acc.y += b.y; acc.z += b.z; acc.w += b.w;
        }
        float4 bb = *(const float4*)&Bb[quad * 4];
        acc.x = fmaxf(acc.x + bb.x, 0.f);
        acc.y = fmaxf(acc.y + bb.y, 0.f);
        acc.z = fmaxf(acc.z + bb.z, 0.f);
        acc.w = fmaxf(acc.w + bb.w, 0.f);
        *(float4*)&hs[quad * 4] = acc;
    }
    __syncthreads();
}

// out[256] = WT^T x[512] + b; 64 col-quads x 8 k-splits of 64
__device__ void mvT_512to256(const float* __restrict__ xs, const float* __restrict__ WT,
                             const float* __restrict__ Bb, float* __restrict__ outv,
                             float4* pbuf)
{
    int t = threadIdx.x;
    int quad = t & 63;
    int ks = t >> 6;
    const float4* wt = (const float4*)WT;   // row stride 64 float4
    float4 acc = {0.f, 0.f, 0.f, 0.f};
    int kb = ks * 64;
    #pragma unroll 8
    for (int k = 0; k < 64; k++) {
        float xk = xs[kb + k];
        float4 w = wt[(size_t)(kb + k) * 64 + quad];
        acc.x = fmaf(xk, w.x, acc.x);
        acc.y = fmaf(xk, w.y, acc.y);
        acc.z = fmaf(xk, w.z, acc.z);
        acc.w = fmaf(xk, w.w, acc.w);
    }
    if (ks > 0) pbuf[(ks - 1) * 64 + quad] = acc;
    __syncthreads();
    if (ks == 0) {
        #pragma unroll
        for (int p = 0; p < 7; p++) {
            float4 b = pbuf[p * 64 + quad];
            acc.x += b.x; acc.y += b.y; acc.z += b.z; acc.w += b.w;
        }
        float4 bb = *(const float4*)&Bb[quad * 4];
        acc.x += bb.x; acc.y += bb.y; acc.z += bb.z; acc.w += bb.w;
        *(float4*)&outv[quad * 4] = acc;
    }
    __syncthreads();
}

// out[256] = WT^T x[256] + b; 64 col-quads x 8 k-splits of 32
__device__ void mvT_256to256(const float* __restrict__ xs, const float* __restrict__ WT,
                             const float* __restrict__ Bb, float* __restrict__ outv,
                             float4* pbuf)
{
    int t = threadIdx.x;
    int quad = t & 63;
    int ks = t >> 6;
    const float4* wt = (const float4*)WT;   // row stride 64 float4
    float4 acc = {0.f, 0.f, 0.f, 0.f};
    int kb = ks * 32;
    #pragma unroll 8
    for (int k = 0; k < 32; k++) {
        float xk = xs[kb + k];
        float4 w = wt[(size_t)(kb + k) * 64 + quad];
        acc.x = fmaf(xk, w.x, acc.x);
        acc.y = fmaf(xk, w.y, acc.y);
        acc.z = fmaf(xk, w.z, acc.z);
        acc.w = fmaf(xk, w.w, acc.w);
    }
    if (ks > 0) pbuf[(ks - 1) * 64 + quad] = acc;
    __syncthreads();
    if (ks == 0) {
        #pragma unroll
        for (int p = 0; p < 7; p++) {
            float4 b = pbuf[p * 64 + quad];
            acc.x += b.x; acc.y += b.y; acc.z += b.z; acc.w += b.w;
        }
        float4 bb = *(const float4*)&Bb[quad * 4];
        acc.x += bb.x; acc.y += bb.y; acc.z += bb.z; acc.w += bb.w;
        *(float4*)&outv[quad * 4] = acc;
    }
    __syncthreads();
}

// ---------------- residual add + LayerNorm (tmpv in smem); optional smem save ----------------
__device__ void resln_inblock(Smem* sm, int m, const float* __restrict__ lng,
                              const float* __restrict__ lnb, float* qsave)
{
    int t = threadIdx.x, lane = t & 31, w = t >> 5;
    float x = 0.f;
    if (t < 256) x = g_q[m * 256 + t] + sm->a.tmpv[t];

    float v = warp_red(x);
    if (lane == 0) sm->a.red[w] = v;
    __syncthreads();
    float tot = 0.f;
    #pragma unroll
    for (int kk = 0; kk < 8; kk++) tot += sm->a.red[kk];
    float mean = tot * (1.0f / 256.0f);
    float xm = x - mean;
    __syncthreads();
    float v2 = warp_red((t < 256) ? xm * xm : 0.f);
    if (lane == 0) sm->a.red[w] = v2;
    __syncthreads();
    float tv = 0.f;
    #pragma unroll
    for (int kk = 0; kk < 8; kk++) tv += sm->a.red[kk];
    float var = tv * (1.0f / 256.0f);
    if (t < 256) {
        float r = xm * rsqrtf(var + 1e-5f) * lng[t] + lnb[t];
        g_q[m * 256 + t] = r;
        if (qsave) qsave[t] = r;
    }
    __syncthreads();
}

// ---------------- full attention for query m ----------------
__device__ void attn_full(Smem* sm, int m,
                          const float* __restrict__ WoT, const float* __restrict__ bo,
                          const float* __restrict__ lng, const float* __restrict__ lnb,
                          float* qsave)
{
    int t = threadIdx.x, lane = t & 31, w = t >> 5;
    int h = w >> 1, part = w & 1;
    int jb = part * 64;

    if (t < 256) sm->a.q[t] = g_qh[m * 256 + t];
    __syncthreads();

    const float* kTh = g_kT + (h * 32) * NQ;
    float s0 = 0.f, s1 = 0.f;
    #pragma unroll
    for (int d = 0; d < 32; d++) {
        float qd = sm->a.q[h * 32 + d];
        s0 = fmaf(qd, kTh[d * NQ + jb + lane], s0);
        s1 = fmaf(qd, kTh[d * NQ + jb + 32 + lane], s1);
    }
    s0 *= 0.17677669529663687f;   // 1/sqrt(32)
    s1 *= 0.17677669529663687f;

    float mx = fmaxf(s0, s1);
    #pragma unroll
    for (int o = 16; o; o >>= 1) mx = fmaxf(mx, __shfl_xor_sync(0xffffffffu, mx, o));
    if (lane == 0) sm->a.mxp[w] = mx;
    __syncthreads();
    mx = fmaxf(sm->a.mxp[h * 2], sm->a.mxp[h * 2 + 1]);

    float e0 = expf(s0 - mx), e1 = expf(s1 - mx);
    float ps = warp_red(e0 + e1);
    if (lane == 0) sm->a.sump[w] = ps;
    __syncthreads();
    float inv = 1.0f / (sm->a.sump[h * 2] + sm->a.sump[h * 2 + 1]);

    sm->a.Ps[h * 128 + jb + lane]      = e0 * inv;
    sm->a.Ps[h * 128 + jb + 32 + lane] = e1 * inv;
    __syncthreads();

    float ov = 0.f;
    for (int j = jb; j < jb + 64; j++)
        ov = fmaf(sm->a.Ps[h * 128 + j], g_vh[j * 256 + h * 32 + lane], ov);
    if (part == 1) sm->a.ovp[h * 32 + lane] = ov;
    __syncthreads();
    if (part == 0) sm->a.ao[h * 32 + lane] = ov + sm->a.ovp[h * 32 + lane];
    __syncthreads();

    // out-projection on transposed weights (shuffle-free)
    mvT_256to256(sm->a.ao, WoT, bo, sm->a.tmpv, sm->a.pbuf);

    resln_inblock(sm, m, lng, lnb, qsave);
}

// ---------------- traj head stage 2 ----------------
__device__ void traj2_stage(Smem* sm, int m, const float* __restrict__ w2,
                            const float* __restrict__ b2, float* __restrict__ outp)
{
    int t = threadIdx.x, lane = t & 31, w = t >> 5;
    const float* hr = g_h + m * 512;
    if (w < 11) {
        const float4* h4 = (const float4*)hr;
        const float4* w4 = (const float4*)(w2 + w * 512);
        float s = dot4(h4[lane], w4[lane]) + dot4(h4[lane + 32], w4[lane + 32]) +
                  dot4(h4[lane + 64], w4[lane + 64]) + dot4(h4[lane + 96], w4[lane + 96]);
        s = warp_red(s);
        if (lane == 0) {
            float v = s + b2[w];
            sm->s.tp[w]      = v;
            outp[m * 11 + w] = v;
        }
    }
    __syncthreads();
}

// ---------------- sampling for query m -> sm->s.agg ----------------
__device__ void sample_stage(Smem* sm, int m, const float* __restrict__ calib,
                             const float* __restrict__ ego)
{
    int t = threadIdx.x;

    if (t < 12) {
        int ci = t % CAMSN, tt = t / CAMSN;
        float* d = sm->s.ctc[t];
        d[0] = ego[tt * 4 + 3] - ego[1 * 4 + 3];
        d[1] = ego[tt * 4 + 0];
        d[2] = ego[tt * 4 + 1];
        float eyaw = ego[tt * 4 + 2];
        d[3] = cosf(eyaw);
        d[4] = sinf(eyaw);
        const float* cal = calib + ci * 8;
        d[5]  = cal[0]; d[6]  = cal[1]; d[7]  = cal[2]; d[8] = cal[3];
        d[9]  = cal[4]; d[10] = cal[5]; d[11] = cal[6];
        d[12] = cosf(cal[7]);
        d[13] = sinf(cal[7]);
    } else if (t == 12) {
        float yaw = sm->s.tp[7];
        sm->s.cs[0] = cosf(yaw);
        sm->s.cs[1] = sinf(yaw);
    }
    __syncthreads();

    // Phase A: project 1800 taps (invalid -> row 0, weight 0); weights as dup'd half2
    for (int idx = t; idx < NTAPS; idx += NT) {
        int pt  = idx % NPTS;
        int ctc = idx / NPTS;
        int ci  = ctc % CAMSN;
        int tt  = ctc / CAMSN;
        const float* d = sm->s.ctc[tt * CAMSN + ci];
        float dt = d[0], ex = d[1], ey = d[2], ce = d[3], se = d[4];
        float fx = d[5], fy = d[6], cx0 = d[7], cy0 = d[8];
        float txc = d[9], tyc = d[10], tzc = d[11], cc = d[12], sc = d[13];

        int face = pt / 25, sub = pt % 25, dim = face >> 1;
        float sign = (face & 1) ? 1.0f : -1.0f;
        float a = -1.0f + 0.5f * (float)(sub / 5);
        float b = -1.0f + 0.5f * (float)(sub % 5);
        float ux, uy, uz;
        if (dim == 0)      { ux = sign; uy = a;    uz = b; }
        else if (dim == 1) { ux = a;    uy = sign; uz = b; }
        else               { ux = a;    uy = b;    uz = sign; }

        float lx = ux * sm->s.tp[8], ly = uy * sm->s.tp[9], lz = uz * sm->s.tp[10];
        float cyw = sm->s.cs[0], syw = sm->s.cs[1];
        float rx = lx * cyw - ly * syw;
        float ry = lx * syw + ly * cyw;
        float cx = sm->s.tp[0] + sm->s.tp[3] * dt + 0.5f * sm->s.tp[5] * dt * dt;
        float cy = sm->s.tp[1] + sm->s.tp[4] * dt + 0.5f * sm->s.tp[6] * dt * dt;
        float wx = rx + cx, wy = ry + cy, wz = lz + sm->s.tp[2];
        float pxr = wx - ex, pyr = wy - ey;
        float gx =  pxr * ce + pyr * se;
        float gy = -pxr * se + pyr * ce;

        float px = gx - txc, py = gy - tyc, pz = wz - tzc;
        float fwd  =  px * cc + py * sc;
        float left = -px * sc + py * cc;
        float zc = fwd, xc = -left, yc = -pz;
        float zs = fmaxf(zc, 0.1f);
        float u = fx * xc / zs + cx0;
        float v = fy * yc / zs + cy0;
        bool valid = (zc > 0.1f) && (u >= 0.f) && (u < 1.f) && (v >= 0.f) && (v < 1.f);

        uint4 wq = make_uint4(0u, 0u, 0u, 0u);
        int rowv = 0;
        if (valid) {
            float pxi = u * 159.0f;
            float pyi = v * 63.0f;
            float x0f = floorf(pxi), y0f = floorf(pyi);
            int x0 = (int)x0f, y0 = (int)y0f;
            float wxk = pxi - x0f, wyk = pyi - y0f;
            rowv = (ci * TSTEP + tt) * PLANE + y0 * WID + x0;
            __half2 h00 = __float2half2_rn((1.f - wxk) * (1.f - wyk));
            __half2 h01 = __float2half2_rn(wxk * (1.f - wyk));
            __half2 h10 = __float2half2_rn((1.f - wxk) * wyk);
            __half2 h11 = __float2half2_rn(wxk * wyk);
            wq.x = *(unsigned*)&h00;
            wq.y = *(unsigned*)&h01;
            wq.z = *(unsigned*)&h10;
            wq.w = *(unsigned*)&h11;
        }
        sm->s.row[idx] = rowv;
        sm->s.w[idx]   = wq;
    }
    __syncthreads();

    // Phase B: 16 groups of 32 threads; thread = 8 channels via uint4 (LDG.128),
    // bilinear combine in half2, one convert per tap.
    int g = t >> 5;            // 0..15
    int j = t & 31;            // channel octet: channels 8j..8j+7
    float2 a4[4] = {{0.f,0.f},{0.f,0.f},{0.f,0.f},{0.f,0.f}};
    const uint4* fb = (const uint4*)g_featT;   // row stride = 256ch*2B/16B = 32
    #pragma unroll 2
    for (int i = g; i < NTAPS; i += 16) {
        int row = sm->s.row[i];
        uint4 wq = sm->s.w[i];
        __half2 w00 = *(__half2*)&wq.x;
        __half2 w01 = *(__half2*)&wq.y;
        __half2 w10 = *(__half2*)&wq.z;
        __half2 w11 = *(__half2*)&wq.w;
        const uint4* p = fb + (size_t)row * 32 + j;
        uint4 q00 = p[0];
        uint4 q01 = p[32];
        uint4 q10 = p[WID * 32];
        uint4 q11 = p[WID * 32 + 32];
        {
            __half2 v = __hmul2(*(__half2*)&q00.x, w00);
            v = __hfma2(*(__half2*)&q01.x, w01, v);
            v = __hfma2(*(__half2*)&q10.x, w10, v);
            v = __hfma2(*(__half2*)&q11.x, w11, v);
            float2 f = __half22float2(v);
            a4[0].x += f.x; a4[0].y += f.y;
        }
        {
            __half2 v = __hmul2(*(__half2*)&q00.y, w00);
            v = __hfma2(*(__half2*)&q01.y, w01, v);
            v = __hfma2(*(__half2*)&q10.y, w10, v);
            v = __hfma2(*(__half2*)&q11.y, w11, v);
            float2 f = __half22float2(v);
            a4[1].x += f.x; a4[1].y += f.y;
        }
        {
            __half2 v = __hmul2(*(__half2*)&q00.z, w00);
            v = __hfma2(*(__half2*)&q01.z, w01, v);
            v = __hfma2(*(__half2*)&q10.z, w10, v);
            v = __hfma2(*(__half2*)&q11.z, w11, v);
            float2 f = __half22float2(v);
            a4[2].x += f.x; a4[2].y += f.y;
        }
        {
            __half2 v = __hmul2(*(__half2*)&q00.w, w00);
            v = __hfma2(*(__half2*)&q01.w, w01, v);
            v = __hfma2(*(__half2*)&q10.w, w10, v);
            v = __hfma2(*(__half2*)&q11.w, w11, v);
            float2 f = __half22float2(v);
            a4[3].x += f.x; a4[3].y += f.y;
        }
    }
    // two-step deterministic reduction: 16 -> 8 -> 1
    if (g >= 8) {
        sm->s.buf[g - 8][j * 2 + 0] = make_float4(a4[0].x, a4[0].y, a4[1].x, a4[1].y);
        sm->s.buf[g - 8][j * 2 + 1] = make_float4(a4[2].x, a4[2].y, a4[3].x, a4[3].y);
    }
    __syncthreads();
    if (g < 8) {
        float4 b0 = sm->s.buf[g][j * 2 + 0];
        float4 b1 = sm->s.buf[g][j * 2 + 1];
        a4[0].x += b0.x; a4[0].y += b0.y; a4[1].x += b0.z; a4[1].y += b0.w;
        a4[2].x += b1.x; a4[2].y += b1.y; a4[3].x += b1.z; a4[3].y += b1.w;
    }
    __syncthreads();
    if (g >= 1 && g < 8) {
        sm->s.buf[g - 1][j * 2 + 0] = make_float4(a4[0].x, a4[0].y, a4[1].x, a4[1].y);
        sm->s.buf[g - 1][j * 2 + 1] = make_float4(a4[2].x, a4[2].y, a4[3].x, a4[3].y);
    }
    __syncthreads();
    if (g == 0) {
        #pragma unroll
        for (int gg = 0; gg < 7; gg++) {
            float4 b0 = sm->s.buf[gg][j * 2 + 0];
            float4 b1 = sm->s.buf[gg][j * 2 + 1];
            a4[0].x += b0.x; a4[0].y += b0.y; a4[1].x += b0.z; a4[1].y += b0.w;
            a4[2].x += b1.x; a4[2].y += b1.y; a4[3].x += b1.z; a4[3].y += b1.w;
        }
        const float sc = 1.0f / 1800.0f;
        *(float4*)&sm->s.agg[8 * j]     = make_float4(a4[0].x * sc, a4[0].y * sc, a4[1].x * sc, a4[1].y * sc);
        *(float4*)&sm->s.agg[8 * j + 4] = make_float4(a4[2].x * sc, a4[2].y * sc, a4[3].x * sc, a4[3].y * sc);
    }
    __syncthreads();
}

// ---------------- persistent mega-kernel ----------------
__global__ void __launch_bounds__(NT, 1)
decoder_kernel(const float* __restrict__ features, const float* __restrict__ calib,
               const float* __restrict__ ego, const float* __restrict__ queries,
               const float* __restrict__ tw1, const float* __restrict__ tb1,
               const float* __restrict__ tw2, const float* __restrict__ tb2,
               const float* __restrict__ fmw1, const float* __restrict__ fmb1,
               const float* __restrict__ fmw2, const float* __restrict__ fmb2,
               const float* __restrict__ saiw, const float* __restrict__ saib,
               const float* __restrict__ saow, const float* __restrict__ saob,
               const float* __restrict__ caiw, const float* __restrict__ caib,
               const float* __restrict__ caow, const float* __restrict__ caob,
               const float* __restrict__ l1w,  const float* __restrict__ l1b,
               const float* __restrict__ l2w,  const float* __restrict__ l2b,
               const float* __restrict__ n1g,  const float* __restrict__ n1b,
               const float* __restrict__ n2g,  const float* __restrict__ n2b,
               const float* __restrict__ n3g,  const float* __restrict__ n3b,
               float* __restrict__ out)
{
    __shared__ Smem sm;
    int m = blockIdx.x;
    int t = threadIdx.x;
    int half = t >> 8;
    int tl   = t & 255;
    int barid = half + 1;
    SmemGemm* sg = &sm.g2.h[half];

    // prologue: copy queries; transpose features -> fp16 pixel-major; transpose weights
    if (t < 256) g_q[m * 256 + t] = queries[m * 256 + t];
    {
        const int PT = PLANE / 32;                   // 320
        const int CT = CFCH / 32;                    // 8
        const int NTILE = CAMSN * TSTEP * PT * CT;   // 30720
        int tx = t & 31, ty = t >> 5;                // 32 x 16
        for (int tile = blockIdx.x; tile < NTILE; tile += NB) {
            int ct  = tile / (PT * CT);
            int rem = tile % (PT * CT);
            int p0 = (rem % PT) * 32;
            int c0 = (rem / PT) * 32;
            const float* in = features + (size_t)ct * CFCH * PLANE;
            __half*      op = g_featT  + (size_t)ct * CFCH * PLANE;
            #pragma unroll
            for (int i = 0; i < 32; i += 16)
                sm.t.tile[ty + i][tx] = in[(size_t)(c0 + ty + i) * PLANE + p0 + tx];
            __syncthreads();
            #pragma unroll
            for (int i = 0; i < 32; i += 16)
                op[(size_t)(p0 + ty + i) * CFCH + c0 + tx] = __float2half_rn(sm.t.tile[tx][ty + i]);
            __syncthreads();
        }
    }
    wtrans(&sm, fmw1, g_fmw1T, 512, 256);
    wtrans(&sm, fmw2, g_fmw2T, 256, 512);
    for (int li = 0; li < 6; li++) {
        wtrans(&sm, saow + li * 65536,  g_saowT + li * 65536,  256, 256);
        wtrans(&sm, caow + li * 65536,  g_caowT + li * 65536,  256, 256);
        wtrans(&sm, l1w  + li * 131072, g_l1wT  + li * 131072, 512, 256);
        wtrans(&sm, l2w  + li * 131072, g_l2wT  + li * 131072, 256, 512);
    }
    grid_sync();

    for (int li = 0; li < 6; li++) {
        const float* saiw_l = saiw + li * 768 * 256;
        const float* saib_l = saib + li * 768;
        const float* caiw_l = caiw + li * 768 * 256;
        const float* caib_l = caib + li * 768;

        // ---- S1: GEMM: traj1 (64 tiles) + SA QKV (96 tiles), both read pre-SA g_q
        for (int tile = blockIdx.x * 2 + half; tile < 160; tile += 256) {
            if (tile < 64)
                gemm_tile<1,0>(sg, tl, barid, g_q, tw1, tb1, g_h, 256, 512,
                               (tile & 7) * 16, (tile >> 3) * 64);
            else {
                int u = tile - 64;
                gemm_tile<0,1>(sg, tl, barid, g_q, saiw_l, saib_l, nullptr, 256, 768,
                               (u & 7) * 16, (u >> 3) * 64);
            }
        }
        grid_sync();

        // ---- S2 per-query: SA attn + traj2 + sampling + feature MLP -> g_mem[m]
        attn_full(&sm, m, g_saowT + li * 65536, saob + li * 256,
                  n1g + li * 256, n1b + li * 256, nullptr);
        traj2_stage(&sm, m, tw2, tb2, out + li * 1408);
        sample_stage(&sm, m, calib, ego);
        mvT_256to512(sm.s.agg, g_fmw1T, fmb1, sm.s.h, sm.a.pbuf);
        mvT_512to256(sm.s.h, g_fmw2T, fmb2, g_mem + m * 256, sm.a.pbuf);
        grid_sync();

        // ---- S3: GEMM: CA q-proj (32 tiles, g_q) + CA kv-proj (64 tiles, g_mem)
        for (int tile = blockIdx.x * 2 + half; tile < 96; tile += 256) {
            if (tile < 32)
                gemm_tile<0,1>(sg, tl, barid, g_q, caiw_l, caib_l, nullptr, 256, 768,
                               (tile & 7) * 16, (tile >> 3) * 64);
            else {
                int u = tile - 32;
                gemm_tile<0,1>(sg, tl, barid, g_mem, caiw_l, caib_l, nullptr, 256, 768,
                               (u & 7) * 16, 256 + (u >> 3) * 64);
            }
        }
        grid_sync();

        // ---- S4 per-query: CA attn (+resln2, save qrow) + FFN + resln3
        attn_full(&sm, m, g_caowT + li * 65536, caob + li * 256,
                  n2g + li * 256, n2b + li * 256, sm.s.agg);
        mvT_256to512(sm.s.agg, g_l1wT + li * 131072, l1b + li * 512, sm.s.h, sm.a.pbuf);
        mvT_512to256(sm.s.h, g_l2wT + li * 131072, l2b + li * 256, sm.a.tmpv, sm.a.pbuf);
        resln_inblock(&sm, m, n3g + li * 256, n3b + li * 256, nullptr);
        grid_sync();
    }

    // epilogue: final traj head
    for (int tile = blockIdx.x * 2 + half; tile < 64; tile += 256)
        gemm_tile<1,0>(sg, tl, barid, g_q, tw1, tb1, g_h, 256, 512,
                       (tile & 7) * 16, (tile >> 3) * 64);
    grid_sync();
    traj2_stage(&sm, m, tw2, tb2, out + 6 * 1408);
}

// ---------------- host: one launch ----------------
extern "C" void kernel_launch(void* const* d_in, const int* in_sizes, int n_in,
                              void* d_out, int out_size)
{
    const float* features = (const float*)d_in[0];
    const float* calib    = (const float*)d_in[1];
    const float* ego      = (const float*)d_in[2];
    const float* queries  = (const float*)d_in[3];
    const float* tw1  = (const float*)d_in[5];
    const float* tb1  = (const float*)d_in[6];
    const float* tw2  = (const float*)d_in[7];
    const float* tb2  = (const float*)d_in[8];
    const float* fmw1 = (const float*)d_in[9];
    const float* fmb1 = (const float*)d_in[10];
    const float* fmw2 = (const float*)d_in[11];
    const float* fmb2 = (const float*)d_in[12];
    const float* saiw = (const float*)d_in[13];
    const float* saib = (const float*)d_in[14];
    const float* saow = (const float*)d_in[15];
    const float* saob = (const float*)d_in[16];
    const float* caiw = (const float*)d_in[17];
    const float* caib = (const float*)d_in[18];
    const float* caow = (const float*)d_in[19];
    const float* caob = (const float*)d_in[20];
    const float* l1w  = (const float*)d_in[21];
    const float* l1b  = (const float*)d_in[22];
    const float* l2w  = (const float*)d_in[23];
    const float* l2b  = (const float*)d_in[24];
    const float* n1g  = (const float*)d_in[25];
    const float* n1b  = (const float*)d_in[26];
    const float* n2g  = (const float*)d_in[27];
    const float* n2b  = (const float*)d_in[28];
    const float* n3g  = (const float*)d_in[29];
    const float* n3b  = (const float*)d_in[30];
    float* out = (float*)d_out;

    decoder_kernel<<<NB, NT>>>(features, calib, ego, queries,
                               tw1, tb1, tw2, tb2,
                               fmw1, fmb1, fmw2, fmb2,
                               saiw, saib, saow, saob,
                               caiw, caib, caow, caob,
                               l1w, l1b, l2w, l2b,
                               n1g, n1b, n2g, n2b, n3g, n3b,
                               out);
}

// round 11
// speedup vs baseline: 3.0497x; 1.0392x over previous
#include <cuda_runtime.h>
#include <cuda_fp16.h>
#include <math.h>

#define NQ    128
#define ED    256
#define DFFD  512
#define CAMSN 6
#define TSTEP 2
#define CFCH  256
#define HGT   64
#define WID   160
#define PLANE (HGT*WID)           /* 10240 */
#define NPTS  150
#define NTAPS (NPTS*CAMSN*TSTEP)  /* 1800 */
#define NB    128
#define NT    512

// ---------------- device scratch ----------------
__device__ float  g_q    [NQ*ED];
__device__ float  g_h    [NQ*DFFD];
__device__ float  g_mem  [NQ*ED];
__device__ float  g_qh   [NQ*ED];
__device__ float  g_kT   [ED*NQ];     // transposed K: [256 dims][128 queries]
__device__ float  g_vh   [NQ*ED];
__device__ __align__(16) unsigned char g_feat8[(size_t)CAMSN*TSTEP*PLANE*CFCH]; // 31.5 MB fp8 pixel-major

// transposed matvec weights: WT[k][c]
__device__ float  g_fmw1T[256*512];
__device__ float  g_fmw2T[512*256];
__device__ float  g_l1wT [6*256*512];
__device__ float  g_l2wT [6*512*256];
__device__ float  g_saowT[6*256*256];
__device__ float  g_caowT[6*256*256];

__device__ unsigned g_bar_arrive;
__device__ unsigned g_bar_gen;

// ---------------- shared memory union ----------------
struct SmemGemm   { float As[2][32][20]; float Ws[2][32][68]; };   // 22528 B
struct SmemGemm2  { SmemGemm h[2]; };                              // 45056 B
struct SmemS2 {                       // per-query stage scratch
    uint4  w[NTAPS];                  // 28800 B (4x duplicated half2 weights)
    float4 buf[8][64];                // 8192 B (sample partials)
    int    row[NTAPS];                // 7200 B
    float  agg[256];                  // sampled agg / qrow save
    float  h[512];                    // MLP hidden
    float  tp[11];
    float  cs[2];
    float  ctc[12][14];
};                                    // ~47.0 KB
struct SmemAttn {
    float  q[256];
    float  Ps[8*128];
    float  mxp[16];
    float  sump[16];
    float  ovp[256];
    float  ao[256];
    float  tmpv[256];
    float  red[16];
    float4 pbuf[448];                 // 7168 B matvec partials
};
struct SmemTrans  { float tile[32][33]; };
union __align__(16) Smem {
    SmemGemm2  g2;
    SmemS2     s;
    SmemAttn   a;
    SmemTrans  t;
};

// ---------------- fp8 converts ----------------
__device__ __forceinline__ __half2 cvt8(unsigned short v)
{
    unsigned r;
    asm("cvt.rn.f16x2.e4m3x2 %0, %1;" : "=r"(r) : "h"(v));
    return *(__half2*)&r;
}
__device__ __forceinline__ unsigned short pack8(float hi, float lo)
{
    unsigned short r;
    asm("cvt.rn.satfinite.e4m3x2.f32 %0, %1, %2;" : "=h"(r) : "f"(hi), "f"(lo));
    return r;
}

// ---------------- named barrier for 256-thread half-CTA ----------------
__device__ __forceinline__ void half_bar(int id)
{
    asm volatile("bar.sync %0, 256;" :: "r"(id) : "memory");
}

// ---------------- software grid barrier (128 CTAs co-resident) ----------------
__device__ __forceinline__ void grid_sync()
{
    __syncthreads();
    if (threadIdx.x == 0) {
        __threadfence();
        unsigned gen = *((volatile unsigned*)&g_bar_gen);
        unsigned t = atomicAdd(&g_bar_arrive, 1u);
        if (t == (unsigned)(gridDim.x - 1)) {
            g_bar_arrive = 0u;
            __threadfence();
            *((volatile unsigned*)&g_bar_gen) = gen + 1u;
        } else {
            while (*((volatile unsigned*)&g_bar_gen) == gen) { }
        }
        __threadfence();
    }
    __syncthreads();
}

__device__ __forceinline__ float warp_red(float v)
{
    #pragma unroll
    for (int o = 16; o; o >>= 1) v += __shfl_xor_sync(0xffffffffu, v, o);
    return v;
}

__device__ __forceinline__ float dot4(float4 a, float4 b)
{
    return fmaf(a.x, b.x, fmaf(a.y, b.y, fmaf(a.z, b.z, a.w * b.w)));
}

// ---------------- generic 32x32-tiled transpose: dst[C][R] = src[R][C]^T ----------------
__device__ void wtrans(Smem* sm, const float* __restrict__ src, float* __restrict__ dst,
                       int R, int C)
{
    int t = threadIdx.x;
    int tx = t & 31, ty = t >> 5;     // 32 x 16
    int rt = R >> 5;
    int nt = rt * (C >> 5);
    for (int tile = blockIdx.x; tile < nt; tile += NB) {
        int r0 = (tile % rt) << 5;
        int c0 = (tile / rt) << 5;
        #pragma unroll
        for (int i = 0; i < 32; i += 16)
            sm->t.tile[ty + i][tx] = src[(size_t)(r0 + ty + i) * C + c0 + tx];
        __syncthreads();
        #pragma unroll
        for (int i = 0; i < 32; i += 16)
            dst[(size_t)(c0 + ty + i) * R + r0 + tx] = sm->t.tile[tx][ty + i];
        __syncthreads();
    }
}

// ---------------- one 16x64 GEMM tile on a 256-thread half, dbuf K=32 ----------------
template <int ACT, int QKV>
__device__ void gemm_tile(SmemGemm* sg, int tl, int barid,
                          const float* __restrict__ A,
                          const float* __restrict__ W, const float* __restrict__ Bb,
                          float* __restrict__ C, int K, int ldc, int m0, int n0)
{
    int tx = tl & 15;
    int ty = tl >> 4;
    float acc[4] = {0.f, 0.f, 0.f, 0.f};

#define LOAD_CHUNK(k0, b) do {                                                  \
        if (tl < 128) {                                                         \
            int r = tl >> 3, kq = tl & 7;                                       \
            float4 v = *(const float4*)&A[(m0 + r) * K + (k0) + kq * 4];        \
            sg->As[b][kq*4+0][r] = v.x; sg->As[b][kq*4+1][r] = v.y;             \
            sg->As[b][kq*4+2][r] = v.z; sg->As[b][kq*4+3][r] = v.w;             \
        }                                                                        \
        {                                                                        \
            int r = tl >> 2, kq = tl & 3;                                       \
            float4 v0 = *(const float4*)&W[(n0 + r) * K + (k0) + kq * 4];       \
            float4 v1 = *(const float4*)&W[(n0 + r) * K + (k0) + 16 + kq * 4];  \
            sg->Ws[b][kq*4+0][r] = v0.x; sg->Ws[b][kq*4+1][r] = v0.y;           \
            sg->Ws[b][kq*4+2][r] = v0.z; sg->Ws[b][kq*4+3][r] = v0.w;           \
            sg->Ws[b][16+kq*4+0][r] = v1.x; sg->Ws[b][16+kq*4+1][r] = v1.y;     \
            sg->Ws[b][16+kq*4+2][r] = v1.z; sg->Ws[b][16+kq*4+3][r] = v1.w;     \
        }                                                                        \
    } while (0)

    LOAD_CHUNK(0, 0);
    half_bar(barid);
    int p = 0;
    for (int k0 = 0; k0 < K; k0 += 32) {
        if (k0 + 32 < K) LOAD_CHUNK(k0 + 32, p ^ 1);
        #pragma unroll
        for (int k = 0; k < 32; k++) {
            float a  = sg->As[p][k][ty];
            float4 w = *(const float4*)&sg->Ws[p][k][tx*4];
            acc[0] = fmaf(a, w.x, acc[0]);
            acc[1] = fmaf(a, w.y, acc[1]);
            acc[2] = fmaf(a, w.z, acc[2]);
            acc[3] = fmaf(a, w.w, acc[3]);
        }
        half_bar(barid);
        p ^= 1;
    }
#undef LOAD_CHUNK

    int row = m0 + ty;
    int col = n0 + tx * 4;
    float4 bv = *(const float4*)&Bb[col];
    float4 r;
    r.x = acc[0] + bv.x;
    r.y = acc[1] + bv.y;
    r.z = acc[2] + bv.z;
    r.w = acc[3] + bv.w;
    if (ACT) {
        r.x = fmaxf(r.x, 0.f); r.y = fmaxf(r.y, 0.f);
        r.z = fmaxf(r.z, 0.f); r.w = fmaxf(r.w, 0.f);
    }
    if (QKV) {
        if (col < 256) {
            *(float4*)&g_qh[row * 256 + col] = r;
        } else if (col < 512) {
            int kd = col - 256;
            g_kT[(kd+0)*NQ + row] = r.x;
            g_kT[(kd+1)*NQ + row] = r.y;
            g_kT[(kd+2)*NQ + row] = r.z;
            g_kT[(kd+3)*NQ + row] = r.w;
        } else {
            *(float4*)&g_vh[row * 256 + (col - 512)] = r;
        }
    } else {
        *(float4*)&C[row * ldc + col] = r;
    }
}

// ---------------- shuffle-free matvecs on transposed weights WT[k][c] ----------------
__device__ void mvT_256to512(const float* __restrict__ xs, const float* __restrict__ WT,
                             const float* __restrict__ Bb, float* __restrict__ hs,
                             float4* pbuf)
{
    int t = threadIdx.x;
    int quad = t & 127;
    int ks = t >> 7;
    const float4* wt = (const float4*)WT;
    float4 acc = {0.f, 0.f, 0.f, 0.f};
    int kb = ks * 64;
    #pragma unroll 8
    for (int k = 0; k < 64; k++) {
        float xk = xs[kb + k];
        float4 w = wt[(size_t)(kb + k) * 128 + quad];
        acc.x = fmaf(xk, w.x, acc.x);
        acc.y = fmaf(xk, w.y, acc.y);
        acc.z = fmaf(xk, w.z, acc.z);
        acc.w = fmaf(xk, w.w, acc.w);
    }
    if (ks > 0) pbuf[(ks - 1) * 128 + quad] = acc;
    __syncthreads();
    if (ks == 0) {
        #pragma unroll
        for (int p = 0; p < 3; p++) {
            float4 b = pbuf[p * 128 + quad];
            acc.x += b.x; acc.y += b.y; acc.z += b.z; acc.w += b.w;
        }
        float4 bb = *(const float4*)&Bb[quad * 4];
        acc.x = fmaxf(acc.x + bb.x, 0.f);
        acc.y = fmaxf(acc.y + bb.y, 0.f);
        acc.z = fmaxf(acc.z + bb.z, 0.f);
        acc.w = fmaxf(acc.w + bb.w, 0.f);
        *(float4*)&hs[quad * 4] = acc;
    }
    __syncthreads();
}

__device__ void mvT_512to256(const float* __restrict__ xs, const float* __restrict__ WT,
                             const float* __restrict__ Bb, float* __restrict__ outv,
                             float4* pbuf)
{
    int t = threadIdx.x;
    int quad = t & 63;
    int ks = t >> 6;
    const float4* wt = (const float4*)WT;
    float4 acc = {0.f, 0.f, 0.f, 0.f};
    int kb = ks * 64;
    #pragma unroll 8
    for (int k = 0; k < 64; k++) {
        float xk = xs[kb + k];
        float4 w = wt[(size_t)(kb + k) * 64 + quad];
        acc.x = fmaf(xk, w.x, acc.x);
        acc.y = fmaf(xk, w.y, acc.y);
        acc.z = fmaf(xk, w.z, acc.z);
        acc.w = fmaf(xk, w.w, acc.w);
    }
    if (ks > 0) pbuf[(ks - 1) * 64 + quad] = acc;
    __syncthreads();
    if (ks == 0) {
        #pragma unroll
        for (int p = 0; p < 7; p++) {
            float4 b = pbuf[p * 64 + quad];
            acc.x += b.x; acc.y += b.y; acc.z += b.z; acc.w += b.w;
        }
        float4 bb = *(const float4*)&Bb[quad * 4];
        acc.x += bb.x; acc.y += bb.y; acc.z += bb.z; acc.w += bb.w;
        *(float4*)&outv[quad * 4] = acc;
    }
    __syncthreads();
}

__device__ void mvT_256to256(const float* __restrict__ xs, const float* __restrict__ WT,
                             const float* __restrict__ Bb, float* __restrict__ outv,
                             float4* pbuf)
{
    int t = threadIdx.x;
    int quad = t & 63;
    int ks = t >> 6;
    const float4* wt = (const float4*)WT;
    float4 acc = {0.f, 0.f, 0.f, 0.f};
    int kb = ks * 32;
    #pragma unroll 8
    for (int k = 0; k < 32; k++) {
        float xk = xs[kb + k];
        float4 w = wt[(size_t)(kb + k) * 64 + quad];
        acc.x = fmaf(xk, w.x, acc.x);
        acc.y = fmaf(xk, w.y, acc.y);
        acc.z = fmaf(xk, w.z, acc.z);
        acc.w = fmaf(xk, w.w, acc.w);
    }
    if (ks > 0) pbuf[(ks - 1) * 64 + quad] = acc;
    __syncthreads();
    if (ks == 0) {
        #pragma unroll
        for (int p = 0; p < 7; p++) {
            float4 b = pbuf[p * 64 + quad];
            acc.x += b.x; acc.y += b.y; acc.z += b.z; acc.w += b.w;
        }
        float4 bb = *(const float4*)&Bb[quad * 4];
        acc.x += bb.x; acc.y += bb.y; acc.z += bb.z; acc.w += bb.w;
        *(float4*)&outv[quad * 4] = acc;
    }
    __syncthreads();
}

// ---------------- residual add + LayerNorm (tmpv in smem); optional smem save ----------------
__device__ void resln_inblock(Smem* sm, int m, const float* __restrict__ lng,
                              const float* __restrict__ lnb, float* qsave)
{
    int t = threadIdx.x, lane = t & 31, w = t >> 5;
    float x = 0.f;
    if (t < 256) x = g_q[m * 256 + t] + sm->a.tmpv[t];

    float v = warp_red(x);
    if (lane == 0) sm->a.red[w] = v;
    __syncthreads();
    float tot = 0.f;
    #pragma unroll
    for (int kk = 0; kk < 8; kk++) tot += sm->a.red[kk];
    float mean = tot * (1.0f / 256.0f);
    float xm = x - mean;
    __syncthreads();
    float v2 = warp_red((t < 256) ? xm * xm : 0.f);
    if (lane == 0) sm->a.red[w] = v2;
    __syncthreads();
    float tv = 0.f;
    #pragma unroll
    for (int kk = 0; kk < 8; kk++) tv += sm->a.red[kk];
    float var = tv * (1.0f / 256.0f);
    if (t < 256) {
        float r = xm * rsqrtf(var + 1e-5f) * lng[t] + lnb[t];
        g_q[m * 256 + t] = r;
        if (qsave) qsave[t] = r;
    }
    __syncthreads();
}

// ---------------- full attention for query m ----------------
__device__ void attn_full(Smem* sm, int m,
                          const float* __restrict__ WoT, const float* __restrict__ bo,
                          const float* __restrict__ lng, const float* __restrict__ lnb,
                          float* qsave)
{
    int t = threadIdx.x, lane = t & 31, w = t >> 5;
    int h = w >> 1, part = w & 1;
    int jb = part * 64;

    if (t < 256) sm->a.q[t] = g_qh[m * 256 + t];
    __syncthreads();

    const float* kTh = g_kT + (h * 32) * NQ;
    float s0 = 0.f, s1 = 0.f;
    #pragma unroll
    for (int d = 0; d < 32; d++) {
        float qd = sm->a.q[h * 32 + d];
        s0 = fmaf(qd, kTh[d * NQ + jb + lane], s0);
        s1 = fmaf(qd, kTh[d * NQ + jb + 32 + lane], s1);
    }
    s0 *= 0.17677669529663687f;   // 1/sqrt(32)
    s1 *= 0.17677669529663687f;

    float mx = fmaxf(s0, s1);
    #pragma unroll
    for (int o = 16; o; o >>= 1) mx = fmaxf(mx, __shfl_xor_sync(0xffffffffu, mx, o));
    if (lane == 0) sm->a.mxp[w] = mx;
    __syncthreads();
    mx = fmaxf(sm->a.mxp[h * 2], sm->a.mxp[h * 2 + 1]);

    float e0 = expf(s0 - mx), e1 = expf(s1 - mx);
    float ps = warp_red(e0 + e1);
    if (lane == 0) sm->a.sump[w] = ps;
    __syncthreads();
    float inv = 1.0f / (sm->a.sump[h * 2] + sm->a.sump[h * 2 + 1]);

    sm->a.Ps[h * 128 + jb + lane]      = e0 * inv;
    sm->a.Ps[h * 128 + jb + 32 + lane] = e1 * inv;
    __syncthreads();

    float ov = 0.f;
    for (int j = jb; j < jb + 64; j++)
        ov = fmaf(sm->a.Ps[h * 128 + j], g_vh[j * 256 + h * 32 + lane], ov);
    if (part == 1) sm->a.ovp[h * 32 + lane] = ov;
    __syncthreads();
    if (part == 0) sm->a.ao[h * 32 + lane] = ov + sm->a.ovp[h * 32 + lane];
    __syncthreads();

    mvT_256to256(sm->a.ao, WoT, bo, sm->a.tmpv, sm->a.pbuf);

    resln_inblock(sm, m, lng, lnb, qsave);
}

// ---------------- traj head stage 2 ----------------
__device__ void traj2_stage(Smem* sm, int m, const float* __restrict__ w2,
                            const float* __restrict__ b2, float* __restrict__ outp)
{
    int t = threadIdx.x, lane = t & 31, w = t >> 5;
    const float* hr = g_h + m * 512;
    if (w < 11) {
        const float4* h4 = (const float4*)hr;
        const float4* w4 = (const float4*)(w2 + w * 512);
        float s = dot4(h4[lane], w4[lane]) + dot4(h4[lane + 32], w4[lane + 32]) +
                  dot4(h4[lane + 64], w4[lane + 64]) + dot4(h4[lane + 96], w4[lane + 96]);
        s = warp_red(s);
        if (lane == 0) {
            float v = s + b2[w];
            sm->s.tp[w]      = v;
            outp[m * 11 + w] = v;
        }
    }
    __syncthreads();
}

// ---------------- sampling for query m -> sm->s.agg (fp8 features) ----------------
__device__ void sample_stage(Smem* sm, int m, const float* __restrict__ calib,
                             const float* __restrict__ ego)
{
    int t = threadIdx.x;

    if (t < 12) {
        int ci = t % CAMSN, tt = t / CAMSN;
        float* d = sm->s.ctc[t];
        d[0] = ego[tt * 4 + 3] - ego[1 * 4 + 3];
        d[1] = ego[tt * 4 + 0];
        d[2] = ego[tt * 4 + 1];
        float eyaw = ego[tt * 4 + 2];
        d[3] = cosf(eyaw);
        d[4] = sinf(eyaw);
        const float* cal = calib + ci * 8;
        d[5]  = cal[0]; d[6]  = cal[1]; d[7]  = cal[2]; d[8] = cal[3];
        d[9]  = cal[4]; d[10] = cal[5]; d[11] = cal[6];
        d[12] = cosf(cal[7]);
        d[13] = sinf(cal[7]);
    } else if (t == 12) {
        float yaw = sm->s.tp[7];
        sm->s.cs[0] = cosf(yaw);
        sm->s.cs[1] = sinf(yaw);
    }
    __syncthreads();

    // Phase A: project 1800 taps (invalid -> row 0, weight 0); weights as dup'd half2
    for (int idx = t; idx < NTAPS; idx += NT) {
        int pt  = idx % NPTS;
        int ctc = idx / NPTS;
        int ci  = ctc % CAMSN;
        int tt  = ctc / CAMSN;
        const float* d = sm->s.ctc[tt * CAMSN + ci];
        float dt = d[0], ex = d[1], ey = d[2], ce = d[3], se = d[4];
        float fx = d[5], fy = d[6], cx0 = d[7], cy0 = d[8];
        float txc = d[9], tyc = d[10], tzc = d[11], cc = d[12], sc = d[13];

        int face = pt / 25, sub = pt % 25, dim = face >> 1;
        float sign = (face & 1) ? 1.0f : -1.0f;
        float a = -1.0f + 0.5f * (float)(sub / 5);
        float b = -1.0f + 0.5f * (float)(sub % 5);
        float ux, uy, uz;
        if (dim == 0)      { ux = sign; uy = a;    uz = b; }
        else if (dim == 1) { ux = a;    uy = sign; uz = b; }
        else               { ux = a;    uy = b;    uz = sign; }

        float lx = ux * sm->s.tp[8], ly = uy * sm->s.tp[9], lz = uz * sm->s.tp[10];
        float cyw = sm->s.cs[0], syw = sm->s.cs[1];
        float rx = lx * cyw - ly * syw;
        float ry = lx * syw + ly * cyw;
        float cx = sm->s.tp[0] + sm->s.tp[3] * dt + 0.5f * sm->s.tp[5] * dt * dt;
        float cy = sm->s.tp[1] + sm->s.tp[4] * dt + 0.5f * sm->s.tp[6] * dt * dt;
        float wx = rx + cx, wy = ry + cy, wz = lz + sm->s.tp[2];
        float pxr = wx - ex, pyr = wy - ey;
        float gx =  pxr * ce + pyr * se;
        float gy = -pxr * se + pyr * ce;

        float px = gx - txc, py = gy - tyc, pz = wz - tzc;
        float fwd  =  px * cc + py * sc;
        float left = -px * sc + py * cc;
        float zc = fwd, xc = -left, yc = -pz;
        float zs = fmaxf(zc, 0.1f);
        float u = fx * xc / zs + cx0;
        float v = fy * yc / zs + cy0;
        bool valid = (zc > 0.1f) && (u >= 0.f) && (u < 1.f) && (v >= 0.f) && (v < 1.f);

        uint4 wq = make_uint4(0u, 0u, 0u, 0u);
        int rowv = 0;
        if (valid) {
            float pxi = u * 159.0f;
            float pyi = v * 63.0f;
            float x0f = floorf(pxi), y0f = floorf(pyi);
            int x0 = (int)x0f, y0 = (int)y0f;
            float wxk = pxi - x0f, wyk = pyi - y0f;
            rowv = (ci * TSTEP + tt) * PLANE + y0 * WID + x0;
            __half2 h00 = __float2half2_rn((1.f - wxk) * (1.f - wyk));
            __half2 h01 = __float2half2_rn(wxk * (1.f - wyk));
            __half2 h10 = __float2half2_rn((1.f - wxk) * wyk);
            __half2 h11 = __float2half2_rn(wxk * wyk);
            wq.x = *(unsigned*)&h00;
            wq.y = *(unsigned*)&h01;
            wq.z = *(unsigned*)&h10;
            wq.w = *(unsigned*)&h11;
        }
        sm->s.row[idx] = rowv;
        sm->s.w[idx]   = wq;
    }
    __syncthreads();

    // Phase B: 16 groups of 32 threads; thread = 8 channels via uint2 (LDG.64, fp8),
    // convert fp8->half2, bilinear in half2, accumulate fp32.
    int g = t >> 5;            // 0..15
    int j = t & 31;            // channel octet: channels 8j..8j+7
    float2 a4[4] = {{0.f,0.f},{0.f,0.f},{0.f,0.f},{0.f,0.f}};
    const uint2* fb = (const uint2*)g_feat8;   // row stride = 256B/8 = 32 uint2
    #pragma unroll 4
    for (int i = g; i < NTAPS; i += 16) {
        int row = sm->s.row[i];
        uint4 wq = sm->s.w[i];
        __half2 w00 = *(__half2*)&wq.x;
        __half2 w01 = *(__half2*)&wq.y;
        __half2 w10 = *(__half2*)&wq.z;
        __half2 w11 = *(__half2*)&wq.w;
        const uint2* p = fb + (size_t)row * 32 + j;
        uint2 q00 = p[0];
        uint2 q01 = p[32];
        uint2 q10 = p[WID * 32];
        uint2 q11 = p[WID * 32 + 32];
        {
            __half2 v = __hmul2(cvt8((unsigned short)q00.x), w00);
            v = __hfma2(cvt8((unsigned short)q01.x), w01, v);
            v = __hfma2(cvt8((unsigned short)q10.x), w10, v);
            v = __hfma2(cvt8((unsigned short)q11.x), w11, v);
            float2 f = __half22float2(v);
            a4[0].x += f.x; a4[0].y += f.y;
        }
        {
            __half2 v = __hmul2(cvt8((unsigned short)(q00.x >> 16)), w00);
            v = __hfma2(cvt8((unsigned short)(q01.x >> 16)), w01, v);
            v = __hfma2(cvt8((unsigned short)(q10.x >> 16)), w10, v);
            v = __hfma2(cvt8((unsigned short)(q11.x >> 16)), w11, v);
            float2 f = __half22float2(v);
            a4[1].x += f.x; a4[1].y += f.y;
        }
        {
            __half2 v = __hmul2(cvt8((unsigned short)q00.y), w00);
            v = __hfma2(cvt8((unsigned short)q01.y), w01, v);
            v = __hfma2(cvt8((unsigned short)q10.y), w10, v);
            v = __hfma2(cvt8((unsigned short)q11.y), w11, v);
            float2 f = __half22float2(v);
            a4[2].x += f.x; a4[2].y += f.y;
        }
        {
            __half2 v = __hmul2(cvt8((unsigned short)(q00.y >> 16)), w00);
            v = __hfma2(cvt8((unsigned short)(q01.y >> 16)), w01, v);
            v = __hfma2(cvt8((unsigned short)(q10.y >> 16)), w10, v);
            v = __hfma2(cvt8((unsigned short)(q11.y >> 16)), w11, v);
            float2 f = __half22float2(v);
            a4[3].x += f.x; a4[3].y += f.y;
        }
    }
    // two-step deterministic reduction: 16 -> 8 -> 1
    if (g >= 8) {
        sm->s.buf[g - 8][j * 2 + 0] = make_float4(a4[0].x, a4[0].y, a4[1].x, a4[1].y);
        sm->s.buf[g - 8][j * 2 + 1] = make_float4(a4[2].x, a4[2].y, a4[3].x, a4[3].y);
    }
    __syncthreads();
    if (g < 8) {
        float4 b0 = sm->s.buf[g][j * 2 + 0];
        float4 b1 = sm->s.buf[g][j * 2 + 1];
        a4[0].x += b0.x; a4[0].y += b0.y; a4[1].x += b0.z; a4[1].y += b0.w;
        a4[2].x += b1.x; a4[2].y += b1.y; a4[3].x += b1.z; a4[3].y += b1.w;
    }
    __syncthreads();
    if (g >= 1 && g < 8) {
        sm->s.buf[g - 1][j * 2 + 0] = make_float4(a4[0].x, a4[0].y, a4[1].x, a4[1].y);
        sm->s.buf[g - 1][j * 2 + 1] = make_float4(a4[2].x, a4[2].y, a4[3].x, a4[3].y);
    }
    __syncthreads();
    if (g == 0) {
        #pragma unroll
        for (int gg = 0; gg < 7; gg++) {
            float4 b0 = sm->s.buf[gg][j * 2 + 0];
            float4 b1 = sm->s.buf[gg][j * 2 + 1];
            a4[0].x += b0.x; a4[0].y += b0.y; a4[1].x += b0.z; a4[1].y += b0.w;
            a4[2].x += b1.x; a4[2].y += b1.y; a4[3].x += b1.z; a4[3].y += b1.w;
        }
        const float sc = 1.0f / 1800.0f;
        *(float4*)&sm->s.agg[8 * j]     = make_float4(a4[0].x * sc, a4[0].y * sc, a4[1].x * sc, a4[1].y * sc);
        *(float4*)&sm->s.agg[8 * j + 4] = make_float4(a4[2].x * sc, a4[2].y * sc, a4[3].x * sc, a4[3].y * sc);
    }
    __syncthreads();
}

// ---------------- persistent mega-kernel ----------------
__global__ void __launch_bounds__(NT, 1)
decoder_kernel(const float* __restrict__ features, const float* __restrict__ calib,
               const float* __restrict__ ego, const float* __restrict__ queries,
               const float* __restrict__ tw1, const float* __restrict__ tb1,
               const float* __restrict__ tw2, const float* __restrict__ tb2,
               const float* __restrict__ fmw1, const float* __restrict__ fmb1,
               const float* __restrict__ fmw2, const float* __restrict__ fmb2,
               const float* __restrict__ saiw, const float* __restrict__ saib,
               const float* __restrict__ saow, const float* __restrict__ saob,
               const float* __restrict__ caiw, const float* __restrict__ caib,
               const float* __restrict__ caow, const float* __restrict__ caob,
               const float* __restrict__ l1w,  const float* __restrict__ l1b,
               const float* __restrict__ l2w,  const float* __restrict__ l2b,
               const float* __restrict__ n1g,  const float* __restrict__ n1b,
               const float* __restrict__ n2g,  const float* __restrict__ n2b,
               const float* __restrict__ n3g,  const float* __restrict__ n3b,
               float* __restrict__ out)
{
    __shared__ Smem sm;
    int m = blockIdx.x;
    int t = threadIdx.x;
    int half = t >> 8;
    int tl   = t & 255;
    int barid = half + 1;
    SmemGemm* sg = &sm.g2.h[half];

    // prologue: copy queries; transpose features -> fp8 pixel-major; transpose weights
    if (t < 256) g_q[m * 256 + t] = queries[m * 256 + t];
    {
        const int PT = PLANE / 32;                   // 320
        const int CT = CFCH / 32;                    // 8
        const int NTILE = CAMSN * TSTEP * PT * CT;   // 30720
        int tx = t & 31, ty = t >> 5;                // 32 x 16
        int pc = t & 15, pp = t >> 4;                // 16 ch-pairs x 32 pixels
        for (int tile = blockIdx.x; tile < NTILE; tile += NB) {
            int ct  = tile / (PT * CT);
            int rem = tile % (PT * CT);
            int p0 = (rem % PT) * 32;
            int c0 = (rem / PT) * 32;
            const float* in = features + (size_t)ct * CFCH * PLANE;
            unsigned char* op = g_feat8 + (size_t)ct * CFCH * PLANE;
            #pragma unroll
            for (int i = 0; i < 32; i += 16)
                sm.t.tile[ty + i][tx] = in[(size_t)(c0 + ty + i) * PLANE + p0 + tx];
            __syncthreads();
            // tile[ch][pix]; each thread packs channels (2pc, 2pc+1) of pixel pp
            {
                float lo = sm.t.tile[2 * pc + 0][pp];
                float hi = sm.t.tile[2 * pc + 1][pp];
                unsigned short v = pack8(hi, lo);
                *(unsigned short*)(op + (size_t)(p0 + pp) * CFCH + c0 + 2 * pc) = v;
            }
            __syncthreads();
        }
    }
    wtrans(&sm, fmw1, g_fmw1T, 512, 256);
    wtrans(&sm, fmw2, g_fmw2T, 256, 512);
    for (int li = 0; li < 6; li++) {
        wtrans(&sm, saow + li * 65536,  g_saowT + li * 65536,  256, 256);
        wtrans(&sm, caow + li * 65536,  g_caowT + li * 65536,  256, 256);
        wtrans(&sm, l1w  + li * 131072, g_l1wT  + li * 131072, 512, 256);
        wtrans(&sm, l2w  + li * 131072, g_l2wT  + li * 131072, 256, 512);
    }
    grid_sync();

    for (int li = 0; li < 6; li++) {
        const float* saiw_l = saiw + li * 768 * 256;
        const float* saib_l = saib + li * 768;
        const float* caiw_l = caiw + li * 768 * 256;
        const float* caib_l = caib + li * 768;

        // ---- S1: GEMM: traj1 (64 tiles) + SA QKV (96 tiles), both read pre-SA g_q
        for (int tile = blockIdx.x * 2 + half; tile < 160; tile += 256) {
            if (tile < 64)
                gemm_tile<1,0>(sg, tl, barid, g_q, tw1, tb1, g_h, 256, 512,
                               (tile & 7) * 16, (tile >> 3) * 64);
            else {
                int u = tile - 64;
                gemm_tile<0,1>(sg, tl, barid, g_q, saiw_l, saib_l, nullptr, 256, 768,
                               (u & 7) * 16, (u >> 3) * 64);
            }
        }
        grid_sync();

        // ---- S2 per-query: SA attn + traj2 + sampling + feature MLP -> g_mem[m]
        attn_full(&sm, m, g_saowT + li * 65536, saob + li * 256,
                  n1g + li * 256, n1b + li * 256, nullptr);
        traj2_stage(&sm, m, tw2, tb2, out + li * 1408);
        sample_stage(&sm, m, calib, ego);
        mvT_256to512(sm.s.agg, g_fmw1T, fmb1, sm.s.h, sm.a.pbuf);
        mvT_512to256(sm.s.h, g_fmw2T, fmb2, g_mem + m * 256, sm.a.pbuf);
        grid_sync();

        // ---- S3: GEMM: CA q-proj (32 tiles, g_q) + CA kv-proj (64 tiles, g_mem)
        for (int tile = blockIdx.x * 2 + half; tile < 96; tile += 256) {
            if (tile < 32)
                gemm_tile<0,1>(sg, tl, barid, g_q, caiw_l, caib_l, nullptr, 256, 768,
                               (tile & 7) * 16, (tile >> 3) * 64);
            else {
                int u = tile - 32;
                gemm_tile<0,1>(sg, tl, barid, g_mem, caiw_l, caib_l, nullptr, 256, 768,
                               (u & 7) * 16, 256 + (u >> 3) * 64);
            }
        }
        grid_sync();

        // ---- S4 per-query: CA attn (+resln2, save qrow) + FFN + resln3
        attn_full(&sm, m, g_caowT + li * 65536, caob + li * 256,
                  n2g + li * 256, n2b + li * 256, sm.s.agg);
        mvT_256to512(sm.s.agg, g_l1wT + li * 131072, l1b + li * 512, sm.s.h, sm.a.pbuf);
        mvT_512to256(sm.s.h, g_l2wT + li * 131072, l2b + li * 256, sm.a.tmpv, sm.a.pbuf);
        resln_inblock(&sm, m, n3g + li * 256, n3b + li * 256, nullptr);
        grid_sync();
    }

    // epilogue: final traj head
    for (int tile = blockIdx.x * 2 + half; tile < 64; tile += 256)
        gemm_tile<1,0>(sg, tl, barid, g_q, tw1, tb1, g_h, 256, 512,
                       (tile & 7) * 16, (tile >> 3) * 64);
    grid_sync();
    traj2_stage(&sm, m, tw2, tb2, out + 6 * 1408);
}

// ---------------- host: one launch ----------------
extern "C" void kernel_launch(void* const* d_in, const int* in_sizes, int n_in,
                              void* d_out, int out_size)
{
    const float* features = (const float*)d_in[0];
    const float* calib    = (const float*)d_in[1];
    const float* ego      = (const float*)d_in[2];
    const float* queries  = (const float*)d_in[3];
    const float* tw1  = (const float*)d_in[5];
    const float* tb1  = (const float*)d_in[6];
    const float* tw2  = (const float*)d_in[7];
    const float* tb2  = (const float*)d_in[8];
    const float* fmw1 = (const float*)d_in[9];
    const float* fmb1 = (const float*)d_in[10];
    const float* fmw2 = (const float*)d_in[11];
    const float* fmb2 = (const float*)d_in[12];
    const float* saiw = (const float*)d_in[13];
    const float* saib = (const float*)d_in[14];
    const float* saow = (const float*)d_in[15];
    const float* saob = (const float*)d_in[16];
    const float* caiw = (const float*)d_in[17];
    const float* caib = (const float*)d_in[18];
    const float* caow = (const float*)d_in[19];
    const float* caob = (const float*)d_in[20];
    const float* l1w  = (const float*)d_in[21];
    const float* l1b  = (const float*)d_in[22];
    const float* l2w  = (const float*)d_in[23];
    const float* l2b  = (const float*)d_in[24];
    const float* n1g  = (const float*)d_in[25];
    const float* n1b  = (const float*)d_in[26];
    const float* n2g  = (const float*)d_in[27];
    const float* n2b  = (const float*)d_in[28];
    const float* n3g  = (const float*)d_in[29];
    const float* n3b  = (const float*)d_in[30];
    float* out = (float*)d_out;

    decoder_kernel<<<NB, NT>>>(features, calib, ego, queries,
                               tw1, tb1, tw2, tb2,
                               fmw1, fmb1, fmw2, fmb2,
                               saiw, saib, saow, saob,
                               caiw, caib, caow, caob,
                               l1w, l1b, l2w, l2b,
                               n1g, n1b, n2g, n2b, n3g, n3b,
                               out);
}

// round 12
// speedup vs baseline: 3.0503x; 1.0002x over previous
#include <cuda_runtime.h>
#include <cuda_fp16.h>
#include <math.h>

#define NQ    128
#define ED    256
#define DFFD  512
#define CAMSN 6
#define TSTEP 2
#define CFCH  256
#define HGT   64
#define WID   160
#define PLANE (HGT*WID)           /* 10240 */
#define NPTS  150
#define NTAPS (NPTS*CAMSN*TSTEP)  /* 1800 */
#define NB    128
#define NT    512

// ---------------- device scratch ----------------
__device__ float  g_q    [NQ*ED];
__device__ float  g_h    [NQ*DFFD];
__device__ float  g_mem  [NQ*ED];
__device__ float  g_qh   [NQ*ED];
__device__ float  g_kT   [ED*NQ];     // transposed K: [256 dims][128 queries]
__device__ float  g_vh   [NQ*ED];
__device__ __align__(16) unsigned char g_feat8[(size_t)CAMSN*TSTEP*PLANE*CFCH]; // 31.5 MB fp8 pixel-major

// transposed matvec weights, fp16: WT[k][c]
__device__ __align__(16) __half g_fmw1T[256*512];
__device__ __align__(16) __half g_fmw2T[512*256];
__device__ __align__(16) __half g_l1wT [6*256*512];
__device__ __align__(16) __half g_l2wT [6*512*256];
__device__ __align__(16) __half g_saowT[6*256*256];
__device__ __align__(16) __half g_caowT[6*256*256];

__device__ unsigned g_bar_arrive;
__device__ unsigned g_bar_gen;

// ---------------- shared memory union ----------------
struct SmemGemm   { float As[2][32][20]; float Ws[2][32][68]; };   // 22528 B
struct SmemGemm2  { SmemGemm h[2]; };                              // 45056 B
struct SmemS2 {                       // per-query stage scratch
    uint4  w[NTAPS];                  // 28800 B (4x duplicated half2 weights)
    float4 buf[8][64];                // 8192 B (sample partials)
    int    row[NTAPS];                // 7200 B
    float  agg[256];                  // sampled agg / qrow save
    float  h[512];                    // MLP hidden
    float  tp[11];
    float  cs[2];
    float  ctc[12][14];
};                                    // ~47.0 KB
struct SmemAttn {
    float  q[256];
    float  Ps[8*128];
    float  mxp[16];
    float  sump[16];
    float  ovp[256];
    float  ao[256];
    float  tmpv[256];
    float  red[16];
    float4 pbuf[960];                 // 15360 B matvec partials
};
struct SmemTrans  { float tile[32][33]; };
union __align__(16) Smem {
    SmemGemm2  g2;
    SmemS2     s;
    SmemAttn   a;
    SmemTrans  t;
};

// ---------------- fp8 converts ----------------
__device__ __forceinline__ __half2 cvt8(unsigned short v)
{
    unsigned r;
    asm("cvt.rn.f16x2.e4m3x2 %0, %1;" : "=r"(r) : "h"(v));
    return *(__half2*)&r;
}
__device__ __forceinline__ unsigned short pack8(float hi, float lo)
{
    unsigned short r;
    asm("cvt.rn.satfinite.e4m3x2.f32 %0, %1, %2;" : "=h"(r) : "f"(hi), "f"(lo));
    return r;
}

// ---------------- named barrier for 256-thread half-CTA ----------------
__device__ __forceinline__ void half_bar(int id)
{
    asm volatile("bar.sync %0, 256;" :: "r"(id) : "memory");
}

// ---------------- software grid barrier: release/acquire, replay-safe ----------------
__device__ __forceinline__ void grid_sync(unsigned bar0, unsigned& cnt)
{
    __syncthreads();
    cnt++;
    if (threadIdx.x == 0) {
        unsigned target = bar0 + cnt;
        unsigned t;
        asm volatile("atom.release.gpu.global.add.u32 %0, [%1], 1;"
                     : "=r"(t) : "l"(&g_bar_arrive) : "memory");
        if (t == (unsigned)(NB - 1)) {
            g_bar_arrive = 0u;
            asm volatile("st.release.gpu.global.u32 [%0], %1;"
                         :: "l"(&g_bar_gen), "r"(target) : "memory");
        } else {
            unsigned cur;
            do {
                asm volatile("ld.acquire.gpu.global.u32 %0, [%1];"
                             : "=r"(cur) : "l"(&g_bar_gen) : "memory");
            } while ((int)(cur - target) < 0);
        }
    }
    __syncthreads();
}

__device__ __forceinline__ float warp_red(float v)
{
    #pragma unroll
    for (int o = 16; o; o >>= 1) v += __shfl_xor_sync(0xffffffffu, v, o);
    return v;
}

__device__ __forceinline__ float dot4(float4 a, float4 b)
{
    return fmaf(a.x, b.x, fmaf(a.y, b.y, fmaf(a.z, b.z, a.w * b.w)));
}

// ---------------- fp32->fp16 transposed weight staging: dst[k][c] (dst[C][R]) ----------------
__device__ void wtransH(Smem* sm, const float* __restrict__ src, __half* __restrict__ dst,
                        int R, int C)
{
    int t = threadIdx.x;
    int tx = t & 31, ty = t >> 5;     // 32 x 16
    int rt = R >> 5;
    int nt = rt * (C >> 5);
    for (int tile = blockIdx.x; tile < nt; tile += NB) {
        int r0 = (tile % rt) << 5;
        int c0 = (tile / rt) << 5;
        #pragma unroll
        for (int i = 0; i < 32; i += 16)
            sm->t.tile[ty + i][tx] = src[(size_t)(r0 + ty + i) * C + c0 + tx];
        __syncthreads();
        #pragma unroll
        for (int i = 0; i < 32; i += 16)
            dst[(size_t)(c0 + ty + i) * R + r0 + tx] = __float2half_rn(sm->t.tile[tx][ty + i]);
        __syncthreads();
    }
}

// ---------------- one 16x64 GEMM tile on a 256-thread half, dbuf K=32 ----------------
template <int ACT, int QKV>
__device__ void gemm_tile(SmemGemm* sg, int tl, int barid,
                          const float* __restrict__ A,
                          const float* __restrict__ W, const float* __restrict__ Bb,
                          float* __restrict__ C, int K, int ldc, int m0, int n0)
{
    int tx = tl & 15;
    int ty = tl >> 4;
    float acc[4] = {0.f, 0.f, 0.f, 0.f};

#define LOAD_CHUNK(k0, b) do {                                                  \
        if (tl < 128) {                                                         \
            int r = tl >> 3, kq = tl & 7;                                       \
            float4 v = *(const float4*)&A[(m0 + r) * K + (k0) + kq * 4];        \
            sg->As[b][kq*4+0][r] = v.x; sg->As[b][kq*4+1][r] = v.y;             \
            sg->As[b][kq*4+2][r] = v.z; sg->As[b][kq*4+3][r] = v.w;             \
        }                                                                        \
        {                                                                        \
            int r = tl >> 2, kq = tl & 3;                                       \
            float4 v0 = *(const float4*)&W[(n0 + r) * K + (k0) + kq * 4];       \
            float4 v1 = *(const float4*)&W[(n0 + r) * K + (k0) + 16 + kq * 4];  \
            sg->Ws[b][kq*4+0][r] = v0.x; sg->Ws[b][kq*4+1][r] = v0.y;           \
            sg->Ws[b][kq*4+2][r] = v0.z; sg->Ws[b][kq*4+3][r] = v0.w;           \
            sg->Ws[b][16+kq*4+0][r] = v1.x; sg->Ws[b][16+kq*4+1][r] = v1.y;     \
            sg->Ws[b][16+kq*4+2][r] = v1.z; sg->Ws[b][16+kq*4+3][r] = v1.w;     \
        }                                                                        \
    } while (0)

    LOAD_CHUNK(0, 0);
    half_bar(barid);
    int p = 0;
    for (int k0 = 0; k0 < K; k0 += 32) {
        if (k0 + 32 < K) LOAD_CHUNK(k0 + 32, p ^ 1);
        #pragma unroll
        for (int k = 0; k < 32; k++) {
            float a  = sg->As[p][k][ty];
            float4 w = *(const float4*)&sg->Ws[p][k][tx*4];
            acc[0] = fmaf(a, w.x, acc[0]);
            acc[1] = fmaf(a, w.y, acc[1]);
            acc[2] = fmaf(a, w.z, acc[2]);
            acc[3] = fmaf(a, w.w, acc[3]);
        }
        half_bar(barid);
        p ^= 1;
    }
#undef LOAD_CHUNK

    int row = m0 + ty;
    int col = n0 + tx * 4;
    float4 bv = *(const float4*)&Bb[col];
    float4 r;
    r.x = acc[0] + bv.x;
    r.y = acc[1] + bv.y;
    r.z = acc[2] + bv.z;
    r.w = acc[3] + bv.w;
    if (ACT) {
        r.x = fmaxf(r.x, 0.f); r.y = fmaxf(r.y, 0.f);
        r.z = fmaxf(r.z, 0.f); r.w = fmaxf(r.w, 0.f);
    }
    if (QKV) {
        if (col < 256) {
            *(float4*)&g_qh[row * 256 + col] = r;
        } else if (col < 512) {
            int kd = col - 256;
            g_kT[(kd+0)*NQ + row] = r.x;
            g_kT[(kd+1)*NQ + row] = r.y;
            g_kT[(kd+2)*NQ + row] = r.z;
            g_kT[(kd+3)*NQ + row] = r.w;
        } else {
            *(float4*)&g_vh[row * 256 + (col - 512)] = r;
        }
    } else {
        *(float4*)&C[row * ldc + col] = r;
    }
}

// ---------------- fp16-weight split-K matvecs: WT half[k][c] ----------------
// out[512] = relu(WT^T x[256] + b); 64 col-octets x 8 k-splits of 32
__device__ void mvT_256to512_h(const float* __restrict__ xs, const __half* __restrict__ WT,
                               const float* __restrict__ Bb, float* __restrict__ hs,
                               float4* pbuf)
{
    int t = threadIdx.x;
    int oct = t & 63;
    int ks  = t >> 6;               // 0..7
    const uint4* wt = (const uint4*)WT;   // row stride 512/8 = 64 uint4
    float4 a0 = {0.f,0.f,0.f,0.f}, a1 = {0.f,0.f,0.f,0.f};
    int kb = ks * 32;
    #pragma unroll 8
    for (int k = 0; k < 32; k++) {
        float xk = xs[kb + k];
        uint4 w = wt[(size_t)(kb + k) * 64 + oct];
        float2 f0 = __half22float2(*(const __half2*)&w.x);
        float2 f1 = __half22float2(*(const __half2*)&w.y);
        float2 f2 = __half22float2(*(const __half2*)&w.z);
        float2 f3 = __half22float2(*(const __half2*)&w.w);
        a0.x = fmaf(xk, f0.x, a0.x); a0.y = fmaf(xk, f0.y, a0.y);
        a0.z = fmaf(xk, f1.x, a0.z); a0.w = fmaf(xk, f1.y, a0.w);
        a1.x = fmaf(xk, f2.x, a1.x); a1.y = fmaf(xk, f2.y, a1.y);
        a1.z = fmaf(xk, f3.x, a1.z); a1.w = fmaf(xk, f3.y, a1.w);
    }
    if (ks > 0) {
        pbuf[(ks - 1) * 128 + oct * 2 + 0] = a0;
        pbuf[(ks - 1) * 128 + oct * 2 + 1] = a1;
    }
    __syncthreads();
    if (ks == 0) {
        #pragma unroll
        for (int p = 0; p < 7; p++) {
            float4 b0 = pbuf[p * 128 + oct * 2 + 0];
            float4 b1 = pbuf[p * 128 + oct * 2 + 1];
            a0.x += b0.x; a0.y += b0.y; a0.z += b0.z; a0.w += b0.w;
            a1.x += b1.x; a1.y += b1.y; a1.z += b1.z; a1.w += b1.w;
        }
        float4 bb0 = *(const float4*)&Bb[oct * 8];
        float4 bb1 = *(const float4*)&Bb[oct * 8 + 4];
        a0.x = fmaxf(a0.x + bb0.x, 0.f); a0.y = fmaxf(a0.y + bb0.y, 0.f);
        a0.z = fmaxf(a0.z + bb0.z, 0.f); a0.w = fmaxf(a0.w + bb0.w, 0.f);
        a1.x = fmaxf(a1.x + bb1.x, 0.f); a1.y = fmaxf(a1.y + bb1.y, 0.f);
        a1.z = fmaxf(a1.z + bb1.z, 0.f); a1.w = fmaxf(a1.w + bb1.w, 0.f);
        *(float4*)&hs[oct * 8]     = a0;
        *(float4*)&hs[oct * 8 + 4] = a1;
    }
    __syncthreads();
}

// out[256] = WT^T x[512] + b; 32 col-octets x 16 k-splits of 32
__device__ void mvT_512to256_h(const float* __restrict__ xs, const __half* __restrict__ WT,
                               const float* __restrict__ Bb, float* __restrict__ outv,
                               float4* pbuf)
{
    int t = threadIdx.x;
    int oct = t & 31;
    int ks  = t >> 5;               // 0..15
    const uint4* wt = (const uint4*)WT;   // row stride 256/8 = 32 uint4
    float4 a0 = {0.f,0.f,0.f,0.f}, a1 = {0.f,0.f,0.f,0.f};
    int kb = ks * 32;
    #pragma unroll 8
    for (int k = 0; k < 32; k++) {
        float xk = xs[kb + k];
        uint4 w = wt[(size_t)(kb + k) * 32 + oct];
        float2 f0 = __half22float2(*(const __half2*)&w.x);
        float2 f1 = __half22float2(*(const __half2*)&w.y);
        float2 f2 = __half22float2(*(const __half2*)&w.z);
        float2 f3 = __half22float2(*(const __half2*)&w.w);
        a0.x = fmaf(xk, f0.x, a0.x); a0.y = fmaf(xk, f0.y, a0.y);
        a0.z = fmaf(xk, f1.x, a0.z); a0.w = fmaf(xk, f1.y, a0.w);
        a1.x = fmaf(xk, f2.x, a1.x); a1.y = fmaf(xk, f2.y, a1.y);
        a1.z = fmaf(xk, f3.x, a1.z); a1.w = fmaf(xk, f3.y, a1.w);
    }
    if (ks > 0) {
        pbuf[(ks - 1) * 64 + oct * 2 + 0] = a0;
        pbuf[(ks - 1) * 64 + oct * 2 + 1] = a1;
    }
    __syncthreads();
    if (ks == 0) {
        #pragma unroll
        for (int p = 0; p < 15; p++) {
            float4 b0 = pbuf[p * 64 + oct * 2 + 0];
            float4 b1 = pbuf[p * 64 + oct * 2 + 1];
            a0.x += b0.x; a0.y += b0.y; a0.z += b0.z; a0.w += b0.w;
            a1.x += b1.x; a1.y += b1.y; a1.z += b1.z; a1.w += b1.w;
        }
        float4 bb0 = *(const float4*)&Bb[oct * 8];
        float4 bb1 = *(const float4*)&Bb[oct * 8 + 4];
        a0.x += bb0.x; a0.y += bb0.y; a0.z += bb0.z; a0.w += bb0.w;
        a1.x += bb1.x; a1.y += bb1.y; a1.z += bb1.z; a1.w += bb1.w;
        *(float4*)&outv[oct * 8]     = a0;
        *(float4*)&outv[oct * 8 + 4] = a1;
    }
    __syncthreads();
}

// out[256] = WT^T x[256] + b; 32 col-octets x 16 k-splits of 16
__device__ void mvT_256to256_h(const float* __restrict__ xs, const __half* __restrict__ WT,
                               const float* __restrict__ Bb, float* __restrict__ outv,
                               float4* pbuf)
{
    int t = threadIdx.x;
    int oct = t & 31;
    int ks  = t >> 5;               // 0..15
    const uint4* wt = (const uint4*)WT;   // row stride 32 uint4
    float4 a0 = {0.f,0.f,0.f,0.f}, a1 = {0.f,0.f,0.f,0.f};
    int kb = ks * 16;
    #pragma unroll 8
    for (int k = 0; k < 16; k++) {
        float xk = xs[kb + k];
        uint4 w = wt[(size_t)(kb + k) * 32 + oct];
        float2 f0 = __half22float2(*(const __half2*)&w.x);
        float2 f1 = __half22float2(*(const __half2*)&w.y);
        float2 f2 = __half22float2(*(const __half2*)&w.z);
        float2 f3 = __half22float2(*(const __half2*)&w.w);
        a0.x = fmaf(xk, f0.x, a0.x); a0.y = fmaf(xk, f0.y, a0.y);
        a0.z = fmaf(xk, f1.x, a0.z); a0.w = fmaf(xk, f1.y, a0.w);
        a1.x = fmaf(xk, f2.x, a1.x); a1.y = fmaf(xk, f2.y, a1.y);
        a1.z = fmaf(xk, f3.x, a1.z); a1.w = fmaf(xk, f3.y, a1.w);
    }
    if (ks > 0) {
        pbuf[(ks - 1) * 64 + oct * 2 + 0] = a0;
        pbuf[(ks - 1) * 64 + oct * 2 + 1] = a1;
    }
    __syncthreads();
    if (ks == 0) {
        #pragma unroll
        for (int p = 0; p < 15; p++) {
            float4 b0 = pbuf[p * 64 + oct * 2 + 0];
            float4 b1 = pbuf[p * 64 + oct * 2 + 1];
            a0.x += b0.x; a0.y += b0.y; a0.z += b0.z; a0.w += b0.w;
            a1.x += b1.x; a1.y += b1.y; a1.z += b1.z; a1.w += b1.w;
        }
        float4 bb0 = *(const float4*)&Bb[oct * 8];
        float4 bb1 = *(const float4*)&Bb[oct * 8 + 4];
        a0.x += bb0.x; a0.y += bb0.y; a0.z += bb0.z; a0.w += bb0.w;
        a1.x += bb1.x; a1.y += bb1.y; a1.z += bb1.z; a1.w += bb1.w;
        *(float4*)&outv[oct * 8]     = a0;
        *(float4*)&outv[oct * 8 + 4] = a1;
    }
    __syncthreads();
}

// ---------------- residual add + LayerNorm (tmpv in smem); optional smem save ----------------
__device__ void resln_inblock(Smem* sm, int m, const float* __restrict__ lng,
                              const float* __restrict__ lnb, float* qsave)
{
    int t = threadIdx.x, lane = t & 31, w = t >> 5;
    float x = 0.f;
    if (t < 256) x = g_q[m * 256 + t] + sm->a.tmpv[t];

    float v = warp_red(x);
    if (lane == 0) sm->a.red[w] = v;
    __syncthreads();
    float tot = 0.f;
    #pragma unroll
    for (int kk = 0; kk < 8; kk++) tot += sm->a.red[kk];
    float mean = tot * (1.0f / 256.0f);
    float xm = x - mean;
    __syncthreads();
    float v2 = warp_red((t < 256) ? xm * xm : 0.f);
    if (lane == 0) sm->a.red[w] = v2;
    __syncthreads();
    float tv = 0.f;
    #pragma unroll
    for (int kk = 0; kk < 8; kk++) tv += sm->a.red[kk];
    float var = tv * (1.0f / 256.0f);
    if (t < 256) {
        float r = xm * rsqrtf(var + 1e-5f) * lng[t] + lnb[t];
        g_q[m * 256 + t] = r;
        if (qsave) qsave[t] = r;
    }
    __syncthreads();
}

// ---------------- full attention for query m ----------------
__device__ void attn_full(Smem* sm, int m,
                          const __half* __restrict__ WoT, const float* __restrict__ bo,
                          const float* __restrict__ lng, const float* __restrict__ lnb,
                          float* qsave)
{
    int t = threadIdx.x, lane = t & 31, w = t >> 5;
    int h = w >> 1, part = w & 1;
    int jb = part * 64;

    if (t < 256) sm->a.q[t] = g_qh[m * 256 + t];
    __syncthreads();

    const float* kTh = g_kT + (h * 32) * NQ;
    float s0 = 0.f, s1 = 0.f;
    #pragma unroll
    for (int d = 0; d < 32; d++) {
        float qd = sm->a.q[h * 32 + d];
        s0 = fmaf(qd, kTh[d * NQ + jb + lane], s0);
        s1 = fmaf(qd, kTh[d * NQ + jb + 32 + lane], s1);
    }
    s0 *= 0.17677669529663687f;   // 1/sqrt(32)
    s1 *= 0.17677669529663687f;

    float mx = fmaxf(s0, s1);
    #pragma unroll
    for (int o = 16; o; o >>= 1) mx = fmaxf(mx, __shfl_xor_sync(0xffffffffu, mx, o));
    if (lane == 0) sm->a.mxp[w] = mx;
    __syncthreads();
    mx = fmaxf(sm->a.mxp[h * 2], sm->a.mxp[h * 2 + 1]);

    float e0 = expf(s0 - mx), e1 = expf(s1 - mx);
    float ps = warp_red(e0 + e1);
    if (lane == 0) sm->a.sump[w] = ps;
    __syncthreads();
    float inv = 1.0f / (sm->a.sump[h * 2] + sm->a.sump[h * 2 + 1]);

    sm->a.Ps[h * 128 + jb + lane]      = e0 * inv;
    sm->a.Ps[h * 128 + jb + 32 + lane] = e1 * inv;
    __syncthreads();

    float ov = 0.f;
    #pragma unroll 4
    for (int j = jb; j < jb + 64; j++)
        ov = fmaf(sm->a.Ps[h * 128 + j], g_vh[j * 256 + h * 32 + lane], ov);
    if (part == 1) sm->a.ovp[h * 32 + lane] = ov;
    __syncthreads();
    if (part == 0) sm->a.ao[h * 32 + lane] = ov + sm->a.ovp[h * 32 + lane];
    __syncthreads();

    mvT_256to256_h(sm->a.ao, WoT, bo, sm->a.tmpv, sm->a.pbuf);

    resln_inblock(sm, m, lng, lnb, qsave);
}

// ---------------- traj head stage 2 ----------------
__device__ void traj2_stage(Smem* sm, int m, const float* __restrict__ w2,
                            const float* __restrict__ b2, float* __restrict__ outp)
{
    int t = threadIdx.x, lane = t & 31, w = t >> 5;
    const float* hr = g_h + m * 512;
    if (w < 11) {
        const float4* h4 = (const float4*)hr;
        const float4* w4 = (const float4*)(w2 + w * 512);
        float s = dot4(h4[lane], w4[lane]) + dot4(h4[lane + 32], w4[lane + 32]) +
                  dot4(h4[lane + 64], w4[lane + 64]) + dot4(h4[lane + 96], w4[lane + 96]);
        s = warp_red(s);
        if (lane == 0) {
            float v = s + b2[w];
            sm->s.tp[w]      = v;
            outp[m * 11 + w] = v;
        }
    }
    __syncthreads();
}

// ---------------- sampling for query m -> sm->s.agg (fp8 features) ----------------
__device__ void sample_stage(Smem* sm, int m, const float* __restrict__ calib,
                             const float* __restrict__ ego)
{
    int t = threadIdx.x;

    if (t < 12) {
        int ci = t % CAMSN, tt = t / CAMSN;
        float* d = sm->s.ctc[t];
        d[0] = ego[tt * 4 + 3] - ego[1 * 4 + 3];
        d[1] = ego[tt * 4 + 0];
        d[2] = ego[tt * 4 + 1];
        float eyaw = ego[tt * 4 + 2];
        d[3] = cosf(eyaw);
        d[4] = sinf(eyaw);
        const float* cal = calib + ci * 8;
        d[5]  = cal[0]; d[6]  = cal[1]; d[7]  = cal[2]; d[8] = cal[3];
        d[9]  = cal[4]; d[10] = cal[5]; d[11] = cal[6];
        d[12] = cosf(cal[7]);
        d[13] = sinf(cal[7]);
    } else if (t == 12) {
        float yaw = sm->s.tp[7];
        sm->s.cs[0] = cosf(yaw);
        sm->s.cs[1] = sinf(yaw);
    }
    __syncthreads();

    // Phase A: project 1800 taps (invalid -> row 0, weight 0); weights as dup'd half2
    for (int idx = t; idx < NTAPS; idx += NT) {
        int pt  = idx % NPTS;
        int ctc = idx / NPTS;
        int ci  = ctc % CAMSN;
        int tt  = ctc / CAMSN;
        const float* d = sm->s.ctc[tt * CAMSN + ci];
        float dt = d[0], ex = d[1], ey = d[2], ce = d[3], se = d[4];
        float fx = d[5], fy = d[6], cx0 = d[7], cy0 = d[8];
        float txc = d[9], tyc = d[10], tzc = d[11], cc = d[12], sc = d[13];

        int face = pt / 25, sub = pt % 25, dim = face >> 1;
        float sign = (face & 1) ? 1.0f : -1.0f;
        float a = -1.0f + 0.5f * (float)(sub / 5);
        float b = -1.0f + 0.5f * (float)(sub % 5);
        float ux, uy, uz;
        if (dim == 0)      { ux = sign; uy = a;    uz = b; }
        else if (dim == 1) { ux = a;    uy = sign; uz = b; }
        else               { ux = a;    uy = b;    uz = sign; }

        float lx = ux * sm->s.tp[8], ly = uy * sm->s.tp[9], lz = uz * sm->s.tp[10];
        float cyw = sm->s.cs[0], syw = sm->s.cs[1];
        float rx = lx * cyw - ly * syw;
        float ry = lx * syw + ly * cyw;
        float cx = sm->s.tp[0] + sm->s.tp[3] * dt + 0.5f * sm->s.tp[5] * dt * dt;
        float cy = sm->s.tp[1] + sm->s.tp[4] * dt + 0.5f * sm->s.tp[6] * dt * dt;
        float wx = rx + cx, wy = ry + cy, wz = lz + sm->s.tp[2];
        float pxr = wx - ex, pyr = wy - ey;
        float gx =  pxr * ce + pyr * se;
        float gy = -pxr * se + pyr * ce;

        float px = gx - txc, py = gy - tyc, pz = wz - tzc;
        float fwd  =  px * cc + py * sc;
        float left = -px * sc + py * cc;
        float zc = fwd, xc = -left, yc = -pz;
        float zs = fmaxf(zc, 0.1f);
        float u = fx * xc / zs + cx0;
        float v = fy * yc / zs + cy0;
        bool valid = (zc > 0.1f) && (u >= 0.f) && (u < 1.f) && (v >= 0.f) && (v < 1.f);

        uint4 wq = make_uint4(0u, 0u, 0u, 0u);
        int rowv = 0;
        if (valid) {
            float pxi = u * 159.0f;
            float pyi = v * 63.0f;
            float x0f = floorf(pxi), y0f = floorf(pyi);
            int x0 = (int)x0f, y0 = (int)y0f;
            float wxk = pxi - x0f, wyk = pyi - y0f;
            rowv = (ci * TSTEP + tt) * PLANE + y0 * WID + x0;
            __half2 h00 = __float2half2_rn((1.f - wxk) * (1.f - wyk));
            __half2 h01 = __float2half2_rn(wxk * (1.f - wyk));
            __half2 h10 = __float2half2_rn((1.f - wxk) * wyk);
            __half2 h11 = __float2half2_rn(wxk * wyk);
            wq.x = *(unsigned*)&h00;
            wq.y = *(unsigned*)&h01;
            wq.z = *(unsigned*)&h10;
            wq.w = *(unsigned*)&h11;
        }
        sm->s.row[idx] = rowv;
        sm->s.w[idx]   = wq;
    }
    __syncthreads();

    // Phase B: 16 groups of 32 threads; thread = 8 channels via uint2 (LDG.64, fp8)
    int g = t >> 5;            // 0..15
    int j = t & 31;            // channel octet: channels 8j..8j+7
    float2 a4[4] = {{0.f,0.f},{0.f,0.f},{0.f,0.f},{0.f,0.f}};
    const uint2* fb = (const uint2*)g_feat8;   // row stride = 256B/8 = 32 uint2
    #pragma unroll 4
    for (int i = g; i < NTAPS; i += 16) {
        int row = sm->s.row[i];
        uint4 wq = sm->s.w[i];
        __half2 w00 = *(__half2*)&wq.x;
        __half2 w01 = *(__half2*)&wq.y;
        __half2 w10 = *(__half2*)&wq.z;
        __half2 w11 = *(__half2*)&wq.w;
        const uint2* p = fb + (size_t)row * 32 + j;
        uint2 q00 = p[0];
        uint2 q01 = p[32];
        uint2 q10 = p[WID * 32];
        uint2 q11 = p[WID * 32 + 32];
        {
            __half2 v = __hmul2(cvt8((unsigned short)q00.x), w00);
            v = __hfma2(cvt8((unsigned short)q01.x), w01, v);
            v = __hfma2(cvt8((unsigned short)q10.x), w10, v);
            v = __hfma2(cvt8((unsigned short)q11.x), w11, v);
            float2 f = __half22float2(v);
            a4[0].x += f.x; a4[0].y += f.y;
        }
        {
            __half2 v = __hmul2(cvt8((unsigned short)(q00.x >> 16)), w00);
            v = __hfma2(cvt8((unsigned short)(q01.x >> 16)), w01, v);
            v = __hfma2(cvt8((unsigned short)(q10.x >> 16)), w10, v);
            v = __hfma2(cvt8((unsigned short)(q11.x >> 16)), w11, v);
            float2 f = __half22float2(v);
            a4[1].x += f.x; a4[1].y += f.y;
        }
        {
            __half2 v = __hmul2(cvt8((unsigned short)q00.y), w00);
            v = __hfma2(cvt8((unsigned short)q01.y), w01, v);
            v = __hfma2(cvt8((unsigned short)q10.y), w10, v);
            v = __hfma2(cvt8((unsigned short)q11.y), w11, v);
            float2 f = __half22float2(v);
            a4[2].x += f.x; a4[2].y += f.y;
        }
        {
            __half2 v = __hmul2(cvt8((unsigned short)(q00.y >> 16)), w00);
            v = __hfma2(cvt8((unsigned short)(q01.y >> 16)), w01, v);
            v = __hfma2(cvt8((unsigned short)(q10.y >> 16)), w10, v);
            v = __hfma2(cvt8((unsigned short)(q11.y >> 16)), w11, v);
            float2 f = __half22float2(v);
            a4[3].x += f.x; a4[3].y += f.y;
        }
    }
    // two-step deterministic reduction: 16 -> 8 -> 1
    if (g >= 8) {
        sm->s.buf[g - 8][j * 2 + 0] = make_float4(a4[0].x, a4[0].y, a4[1].x, a4[1].y);
        sm->s.buf[g - 8][j * 2 + 1] = make_float4(a4[2].x, a4[2].y, a4[3].x, a4[3].y);
    }
    __syncthreads();
    if (g < 8) {
        float4 b0 = sm->s.buf[g][j * 2 + 0];
        float4 b1 = sm->s.buf[g][j * 2 + 1];
        a4[0].x += b0.x; a4[0].y += b0.y; a4[1].x += b0.z; a4[1].y += b0.w;
        a4[2].x += b1.x; a4[2].y += b1.y; a4[3].x += b1.z; a4[3].y += b1.w;
    }
    __syncthreads();
    if (g >= 1 && g < 8) {
        sm->s.buf[g - 1][j * 2 + 0] = make_float4(a4[0].x, a4[0].y, a4[1].x, a4[1].y);
        sm->s.buf[g - 1][j * 2 + 1] = make_float4(a4[2].x, a4[2].y, a4[3].x, a4[3].y);
    }
    __syncthreads();
    if (g == 0) {
        #pragma unroll
        for (int gg = 0; gg < 7; gg++) {
            float4 b0 = sm->s.buf[gg][j * 2 + 0];
            float4 b1 = sm->s.buf[gg][j * 2 + 1];
            a4[0].x += b0.x; a4[0].y += b0.y; a4[1].x += b0.z; a4[1].y += b0.w;
            a4[2].x += b1.x; a4[2].y += b1.y; a4[3].x += b1.z; a4[3].y += b1.w;
        }
        const float sc = 1.0f / 1800.0f;
        *(float4*)&sm->s.agg[8 * j]     = make_float4(a4[0].x * sc, a4[0].y * sc, a4[1].x * sc, a4[1].y * sc);
        *(float4*)&sm->s.agg[8 * j + 4] = make_float4(a4[2].x * sc, a4[2].y * sc, a4[3].x * sc, a4[3].y * sc);
    }
    __syncthreads();
}

// ---------------- persistent mega-kernel ----------------
__global__ void __launch_bounds__(NT, 1)
decoder_kernel(const float* __restrict__ features, const float* __restrict__ calib,
               const float* __restrict__ ego, const float* __restrict__ queries,
               const float* __restrict__ tw1, const float* __restrict__ tb1,
               const float* __restrict__ tw2, const float* __restrict__ tb2,
               const float* __restrict__ fmw1, const float* __restrict__ fmb1,
               const float* __restrict__ fmw2, const float* __restrict__ fmb2,
               const float* __restrict__ saiw, const float* __restrict__ saib,
               const float* __restrict__ saow, const float* __restrict__ saob,
               const float* __restrict__ caiw, const float* __restrict__ caib,
               const float* __restrict__ caow, const float* __restrict__ caob,
               const float* __restrict__ l1w,  const float* __restrict__ l1b,
               const float* __restrict__ l2w,  const float* __restrict__ l2b,
               const float* __restrict__ n1g,  const float* __restrict__ n1b,
               const float* __restrict__ n2g,  const float* __restrict__ n2b,
               const float* __restrict__ n3g,  const float* __restrict__ n3b,
               float* __restrict__ out)
{
    __shared__ Smem sm;
    int m = blockIdx.x;
    int t = threadIdx.x;
    int half = t >> 8;
    int tl   = t & 255;
    int barid = half + 1;
    SmemGemm* sg = &sm.g2.h[half];

    // replay-safe relative barrier generation base
    unsigned bar0 = 0;
    if (t == 0)
        asm volatile("ld.acquire.gpu.global.u32 %0, [%1];" : "=r"(bar0) : "l"(&g_bar_gen));
    unsigned barcnt = 0;

    // prologue: copy queries; transpose features -> fp8 pixel-major; fp16 weight transposes
    if (t < 256) g_q[m * 256 + t] = queries[m * 256 + t];
    {
        const int PT = PLANE / 32;                   // 320
        const int CT = CFCH / 32;                    // 8
        const int NTILE = CAMSN * TSTEP * PT * CT;   // 30720
        int tx = t & 31, ty = t >> 5;                // 32 x 16
        int pc = t & 15, pp = t >> 4;                // 16 ch-pairs x 32 pixels
        for (int tile = blockIdx.x; tile < NTILE; tile += NB) {
            int ct  = tile / (PT * CT);
            int rem = tile % (PT * CT);
            int p0 = (rem % PT) * 32;
            int c0 = (rem / PT) * 32;
            const float* in = features + (size_t)ct * CFCH * PLANE;
            unsigned char* op = g_feat8 + (size_t)ct * CFCH * PLANE;
            #pragma unroll
            for (int i = 0; i < 32; i += 16)
                sm.t.tile[ty + i][tx] = in[(size_t)(c0 + ty + i) * PLANE + p0 + tx];
            __syncthreads();
            {
                float lo = sm.t.tile[2 * pc + 0][pp];
                float hi = sm.t.tile[2 * pc + 1][pp];
                unsigned short v = pack8(hi, lo);
                *(unsigned short*)(op + (size_t)(p0 + pp) * CFCH + c0 + 2 * pc) = v;
            }
            __syncthreads();
        }
    }
    wtransH(&sm, fmw1, g_fmw1T, 512, 256);
    wtransH(&sm, fmw2, g_fmw2T, 256, 512);
    for (int li = 0; li < 6; li++) {
        wtransH(&sm, saow + li * 65536,  g_saowT + li * 65536,  256, 256);
        wtransH(&sm, caow + li * 65536,  g_caowT + li * 65536,  256, 256);
        wtransH(&sm, l1w  + li * 131072, g_l1wT  + li * 131072, 512, 256);
        wtransH(&sm, l2w  + li * 131072, g_l2wT  + li * 131072, 256, 512);
    }
    grid_sync(bar0, barcnt);

    for (int li = 0; li < 6; li++) {
        const float* saiw_l = saiw + li * 768 * 256;
        const float* saib_l = saib + li * 768;
        const float* caiw_l = caiw + li * 768 * 256;
        const float* caib_l = caib + li * 768;

        // ---- S1: GEMM: traj1 (64 tiles) + SA QKV (96 tiles), both read pre-SA g_q
        for (int tile = blockIdx.x * 2 + half; tile < 160; tile += 256) {
            if (tile < 64)
                gemm_tile<1,0>(sg, tl, barid, g_q, tw1, tb1, g_h, 256, 512,
                               (tile & 7) * 16, (tile >> 3) * 64);
            else {
                int u = tile - 64;
                gemm_tile<0,1>(sg, tl, barid, g_q, saiw_l, saib_l, nullptr, 256, 768,
                               (u & 7) * 16, (u >> 3) * 64);
            }
        }
        grid_sync(bar0, barcnt);

        // ---- S2 per-query: SA attn + traj2 + sampling + feature MLP -> g_mem[m]
        attn_full(&sm, m, g_saowT + li * 65536, saob + li * 256,
                  n1g + li * 256, n1b + li * 256, nullptr);
        traj2_stage(&sm, m, tw2, tb2, out + li * 1408);
        sample_stage(&sm, m, calib, ego);
        mvT_256to512_h(sm.s.agg, g_fmw1T, fmb1, sm.s.h, sm.a.pbuf);
        mvT_512to256_h(sm.s.h, g_fmw2T, fmb2, g_mem + m * 256, sm.a.pbuf);
        grid_sync(bar0, barcnt);

        // ---- S3: GEMM: CA q-proj (32 tiles, g_q) + CA kv-proj (64 tiles, g_mem)
        for (int tile = blockIdx.x * 2 + half; tile < 96; tile += 256) {
            if (tile < 32)
                gemm_tile<0,1>(sg, tl, barid, g_q, caiw_l, caib_l, nullptr, 256, 768,
                               (tile & 7) * 16, (tile >> 3) * 64);
            else {
                int u = tile - 32;
                gemm_tile<0,1>(sg, tl, barid, g_mem, caiw_l, caib_l, nullptr, 256, 768,
                               (u & 7) * 16, 256 + (u >> 3) * 64);
            }
        }
        grid_sync(bar0, barcnt);

        // ---- S4 per-query: CA attn (+resln2, save qrow) + FFN + resln3
        attn_full(&sm, m, g_caowT + li * 65536, caob + li * 256,
                  n2g + li * 256, n2b + li * 256, sm.s.agg);
        mvT_256to512_h(sm.s.agg, g_l1wT + li * 131072, l1b + li * 512, sm.s.h, sm.a.pbuf);
        mvT_512to256_h(sm.s.h, g_l2wT + li * 131072, l2b + li * 256, sm.a.tmpv, sm.a.pbuf);
        resln_inblock(&sm, m, n3g + li * 256, n3b + li * 256, nullptr);
        grid_sync(bar0, barcnt);
    }

    // epilogue: final traj head
    for (int tile = blockIdx.x * 2 + half; tile < 64; tile += 256)
        gemm_tile<1,0>(sg, tl, barid, g_q, tw1, tb1, g_h, 256, 512,
                       (tile & 7) * 16, (tile >> 3) * 64);
    grid_sync(bar0, barcnt);
    traj2_stage(&sm, m, tw2, tb2, out + 6 * 1408);
}

// ---------------- host: one launch ----------------
extern "C" void kernel_launch(void* const* d_in, const int* in_sizes, int n_in,
                              void* d_out, int out_size)
{
    const float* features = (const float*)d_in[0];
    const float* calib    = (const float*)d_in[1];
    const float* ego      = (const float*)d_in[2];
    const float* queries  = (const float*)d_in[3];
    const float* tw1  = (const float*)d_in[5];
    const float* tb1  = (const float*)d_in[6];
    const float* tw2  = (const float*)d_in[7];
    const float* tb2  = (const float*)d_in[8];
    const float* fmw1 = (const float*)d_in[9];
    const float* fmb1 = (const float*)d_in[10];
    const float* fmw2 = (const float*)d_in[11];
    const float* fmb2 = (const float*)d_in[12];
    const float* saiw = (const float*)d_in[13];
    const float* saib = (const float*)d_in[14];
    const float* saow = (const float*)d_in[15];
    const float* saob = (const float*)d_in[16];
    const float* caiw = (const float*)d_in[17];
    const float* caib = (const float*)d_in[18];
    const float* caow = (const float*)d_in[19];
    const float* caob = (const float*)d_in[20];
    const float* l1w  = (const float*)d_in[21];
    const float* l1b  = (const float*)d_in[22];
    const float* l2w  = (const float*)d_in[23];
    const float* l2b  = (const float*)d_in[24];
    const float* n1g  = (const float*)d_in[25];
    const float* n1b  = (const float*)d_in[26];
    const float* n2g  = (const float*)d_in[27];
    const float* n2b  = (const float*)d_in[28];
    const float* n3g  = (const float*)d_in[29];
    const float* n3b  = (const float*)d_in[30];
    float* out = (float*)d_out;

    decoder_kernel<<<NB, NT>>>(features, calib, ego, queries,
                               tw1, tb1, tw2, tb2,
                               fmw1, fmb1, fmw2, fmb2,
                               saiw, saib, saow, saob,
                               caiw, caib, caow, caob,
                               l1w, l1b, l2w, l2b,
                               n1g, n1b, n2g, n2b, n3g, n3b,
                               out);
}

// round 13
// speedup vs baseline: 3.1344x; 1.0275x over previous
#include <cuda_runtime.h>
#include <cuda_fp16.h>
#include <math.h>

#define NQ    128
#define ED    256
#define DFFD  512
#define CAMSN 6
#define TSTEP 2
#define CFCH  256
#define HGT   64
#define WID   160
#define PLANE (HGT*WID)           /* 10240 */
#define NPTS  150
#define NTAPS (NPTS*CAMSN*TSTEP)  /* 1800 */
#define NB    128
#define NT    512

// ---------------- device scratch ----------------
__device__ float  g_q    [NQ*ED];
__device__ float  g_h    [NQ*DFFD];
__device__ float  g_mem  [NQ*ED];
__device__ float  g_qh   [NQ*ED];
__device__ float  g_kT   [ED*NQ];     // transposed K: [256 dims][128 queries]
__device__ float  g_vh   [NQ*ED];
__device__ __align__(16) unsigned char g_feat8[(size_t)CAMSN*TSTEP*PLANE*CFCH]; // 31.5 MB fp8 pixel-major

// transposed matvec weights, fp16: WT[k][c]
__device__ __align__(16) __half g_fmw1T[256*512];
__device__ __align__(16) __half g_fmw2T[512*256];
__device__ __align__(16) __half g_l1wT [6*256*512];
__device__ __align__(16) __half g_l2wT [6*512*256];
__device__ __align__(16) __half g_saowT[6*256*256];
__device__ __align__(16) __half g_caowT[6*256*256];

__device__ unsigned g_bar_arrive;
__device__ unsigned g_bar_gen;

// ---------------- shared memory union ----------------
struct SmemGemm   { float As[2][32][20]; float Ws[2][32][68]; };   // 22528 B
struct SmemGemm2  { SmemGemm h[2]; };                              // 45056 B
struct SmemS2 {                       // per-query stage scratch
    uint4  w[NTAPS];                  // 28800 B (4x duplicated half2 weights); reused as reduce buf
    int    row[NTAPS];                // 7200 B (contiguous after w; reduce buf spills here when dead)
    float  agg[256];
    float  h[512];
    float  tp[11];
    float  cs[2];
    float  ctc[12][14];
};
struct SmemAttn {
    float  q[256];
    float  Ps[8*128];
    float  mxp[16];
    float  sump[16];
    float  ovp[256];
    float  ao[256];
    float  tmpv[256];
    float  red[16];
    float4 pbuf[960];                 // matvec partials
};
struct SmemTrans  { float tile[32][33]; };
union __align__(16) Smem {
    SmemGemm2  g2;
    SmemS2     s;
    SmemAttn   a;
    SmemTrans  t;
};

// ---------------- fp8 converts ----------------
__device__ __forceinline__ __half2 cvt8(unsigned short v)
{
    unsigned r;
    asm("cvt.rn.f16x2.e4m3x2 %0, %1;" : "=r"(r) : "h"(v));
    return *(__half2*)&r;
}
__device__ __forceinline__ unsigned short pack8(float hi, float lo)
{
    unsigned short r;
    asm("cvt.rn.satfinite.e4m3x2.f32 %0, %1, %2;" : "=h"(r) : "f"(hi), "f"(lo));
    return r;
}

// ---------------- named barrier for 256-thread half-CTA ----------------
__device__ __forceinline__ void half_bar(int id)
{
    asm volatile("bar.sync %0, 256;" :: "r"(id) : "memory");
}

// ---------------- software grid barrier: release/acquire, replay-safe ----------------
__device__ __forceinline__ void grid_sync(unsigned bar0, unsigned& cnt)
{
    __syncthreads();
    cnt++;
    if (threadIdx.x == 0) {
        unsigned target = bar0 + cnt;
        unsigned t;
        asm volatile("atom.release.gpu.global.add.u32 %0, [%1], 1;"
                     : "=r"(t) : "l"(&g_bar_arrive) : "memory");
        if (t == (unsigned)(NB - 1)) {
            g_bar_arrive = 0u;
            asm volatile("st.release.gpu.global.u32 [%0], %1;"
                         :: "l"(&g_bar_gen), "r"(target) : "memory");
        } else {
            unsigned cur;
            do {
                asm volatile("ld.acquire.gpu.global.u32 %0, [%1];"
                             : "=r"(cur) : "l"(&g_bar_gen) : "memory");
            } while ((int)(cur - target) < 0);
        }
    }
    __syncthreads();
}

__device__ __forceinline__ float warp_red(float v)
{
    #pragma unroll
    for (int o = 16; o; o >>= 1) v += __shfl_xor_sync(0xffffffffu, v, o);
    return v;
}

__device__ __forceinline__ float dot4(float4 a, float4 b)
{
    return fmaf(a.x, b.x, fmaf(a.y, b.y, fmaf(a.z, b.z, a.w * b.w)));
}

// ---------------- fp32->fp16 transposed weight staging ----------------
__device__ void wtransH(Smem* sm, const float* __restrict__ src, __half* __restrict__ dst,
                        int R, int C)
{
    int t = threadIdx.x;
    int tx = t & 31, ty = t >> 5;     // 32 x 16
    int rt = R >> 5;
    int nt = rt * (C >> 5);
    for (int tile = blockIdx.x; tile < nt; tile += NB) {
        int r0 = (tile % rt) << 5;
        int c0 = (tile / rt) << 5;
        #pragma unroll
        for (int i = 0; i < 32; i += 16)
            sm->t.tile[ty + i][tx] = src[(size_t)(r0 + ty + i) * C + c0 + tx];
        __syncthreads();
        #pragma unroll
        for (int i = 0; i < 32; i += 16)
            dst[(size_t)(c0 + ty + i) * R + r0 + tx] = __float2half_rn(sm->t.tile[tx][ty + i]);
        __syncthreads();
    }
}

// ---------------- one 16x64 GEMM tile on a 256-thread half, dbuf K=32 ----------------
template <int ACT, int QKV>
__device__ void gemm_tile(SmemGemm* sg, int tl, int barid,
                          const float* __restrict__ A,
                          const float* __restrict__ W, const float* __restrict__ Bb,
                          float* __restrict__ C, int K, int ldc, int m0, int n0)
{
    int tx = tl & 15;
    int ty = tl >> 4;
    float acc[4] = {0.f, 0.f, 0.f, 0.f};

#define LOAD_CHUNK(k0, b) do {                                                  \
        if (tl < 128) {                                                         \
            int r = tl >> 3, kq = tl & 7;                                       \
            float4 v = *(const float4*)&A[(m0 + r) * K + (k0) + kq * 4];        \
            sg->As[b][kq*4+0][r] = v.x; sg->As[b][kq*4+1][r] = v.y;             \
            sg->As[b][kq*4+2][r] = v.z; sg->As[b][kq*4+3][r] = v.w;             \
        }                                                                        \
        {                                                                        \
            int r = tl >> 2, kq = tl & 3;                                       \
            float4 v0 = *(const float4*)&W[(n0 + r) * K + (k0) + kq * 4];       \
            float4 v1 = *(const float4*)&W[(n0 + r) * K + (k0) + 16 + kq * 4];  \
            sg->Ws[b][kq*4+0][r] = v0.x; sg->Ws[b][kq*4+1][r] = v0.y;           \
            sg->Ws[b][kq*4+2][r] = v0.z; sg->Ws[b][kq*4+3][r] = v0.w;           \
            sg->Ws[b][16+kq*4+0][r] = v1.x; sg->Ws[b][16+kq*4+1][r] = v1.y;     \
            sg->Ws[b][16+kq*4+2][r] = v1.z; sg->Ws[b][16+kq*4+3][r] = v1.w;     \
        }                                                                        \
    } while (0)

    LOAD_CHUNK(0, 0);
    half_bar(barid);
    int p = 0;
    for (int k0 = 0; k0 < K; k0 += 32) {
        if (k0 + 32 < K) LOAD_CHUNK(k0 + 32, p ^ 1);
        #pragma unroll
        for (int k = 0; k < 32; k++) {
            float a  = sg->As[p][k][ty];
            float4 w = *(const float4*)&sg->Ws[p][k][tx*4];
            acc[0] = fmaf(a, w.x, acc[0]);
            acc[1] = fmaf(a, w.y, acc[1]);
            acc[2] = fmaf(a, w.z, acc[2]);
            acc[3] = fmaf(a, w.w, acc[3]);
        }
        half_bar(barid);
        p ^= 1;
    }
#undef LOAD_CHUNK

    int row = m0 + ty;
    int col = n0 + tx * 4;
    float4 bv = *(const float4*)&Bb[col];
    float4 r;
    r.x = acc[0] + bv.x;
    r.y = acc[1] + bv.y;
    r.z = acc[2] + bv.z;
    r.w = acc[3] + bv.w;
    if (ACT) {
        r.x = fmaxf(r.x, 0.f); r.y = fmaxf(r.y, 0.f);
        r.z = fmaxf(r.z, 0.f); r.w = fmaxf(r.w, 0.f);
    }
    if (QKV) {
        if (col < 256) {
            *(float4*)&g_qh[row * 256 + col] = r;
        } else if (col < 512) {
            int kd = col - 256;
            g_kT[(kd+0)*NQ + row] = r.x;
            g_kT[(kd+1)*NQ + row] = r.y;
            g_kT[(kd+2)*NQ + row] = r.z;
            g_kT[(kd+3)*NQ + row] = r.w;
        } else {
            *(float4*)&g_vh[row * 256 + (col - 512)] = r;
        }
    } else {
        *(float4*)&C[row * ldc + col] = r;
    }
}

// ---------------- fp16-weight split-K matvecs: WT half[k][c] ----------------
__device__ void mvT_256to512_h(const float* __restrict__ xs, const __half* __restrict__ WT,
                               const float* __restrict__ Bb, float* __restrict__ hs,
                               float4* pbuf)
{
    int t = threadIdx.x;
    int oct = t & 63;
    int ks  = t >> 6;               // 0..7
    const uint4* wt = (const uint4*)WT;   // row stride 64 uint4
    float4 a0 = {0.f,0.f,0.f,0.f}, a1 = {0.f,0.f,0.f,0.f};
    int kb = ks * 32;
    #pragma unroll 8
    for (int k = 0; k < 32; k++) {
        float xk = xs[kb + k];
        uint4 w = wt[(size_t)(kb + k) * 64 + oct];
        float2 f0 = __half22float2(*(const __half2*)&w.x);
        float2 f1 = __half22float2(*(const __half2*)&w.y);
        float2 f2 = __half22float2(*(const __half2*)&w.z);
        float2 f3 = __half22float2(*(const __half2*)&w.w);
        a0.x = fmaf(xk, f0.x, a0.x); a0.y = fmaf(xk, f0.y, a0.y);
        a0.z = fmaf(xk, f1.x, a0.z); a0.w = fmaf(xk, f1.y, a0.w);
        a1.x = fmaf(xk, f2.x, a1.x); a1.y = fmaf(xk, f2.y, a1.y);
        a1.z = fmaf(xk, f3.x, a1.z); a1.w = fmaf(xk, f3.y, a1.w);
    }
    if (ks > 0) {
        pbuf[(ks - 1) * 128 + oct * 2 + 0] = a0;
        pbuf[(ks - 1) * 128 + oct * 2 + 1] = a1;
    }
    __syncthreads();
    if (ks == 0) {
        #pragma unroll
        for (int p = 0; p < 7; p++) {
            float4 b0 = pbuf[p * 128 + oct * 2 + 0];
            float4 b1 = pbuf[p * 128 + oct * 2 + 1];
            a0.x += b0.x; a0.y += b0.y; a0.z += b0.z; a0.w += b0.w;
            a1.x += b1.x; a1.y += b1.y; a1.z += b1.z; a1.w += b1.w;
        }
        float4 bb0 = *(const float4*)&Bb[oct * 8];
        float4 bb1 = *(const float4*)&Bb[oct * 8 + 4];
        a0.x = fmaxf(a0.x + bb0.x, 0.f); a0.y = fmaxf(a0.y + bb0.y, 0.f);
        a0.z = fmaxf(a0.z + bb0.z, 0.f); a0.w = fmaxf(a0.w + bb0.w, 0.f);
        a1.x = fmaxf(a1.x + bb1.x, 0.f); a1.y = fmaxf(a1.y + bb1.y, 0.f);
        a1.z = fmaxf(a1.z + bb1.z, 0.f); a1.w = fmaxf(a1.w + bb1.w, 0.f);
        *(float4*)&hs[oct * 8]     = a0;
        *(float4*)&hs[oct * 8 + 4] = a1;
    }
    __syncthreads();
}

__device__ void mvT_512to256_h(const float* __restrict__ xs, const __half* __restrict__ WT,
                               const float* __restrict__ Bb, float* __restrict__ outv,
                               float4* pbuf)
{
    int t = threadIdx.x;
    int oct = t & 31;
    int ks  = t >> 5;               // 0..15
    const uint4* wt = (const uint4*)WT;   // row stride 32 uint4
    float4 a0 = {0.f,0.f,0.f,0.f}, a1 = {0.f,0.f,0.f,0.f};
    int kb = ks * 32;
    #pragma unroll 8
    for (int k = 0; k < 32; k++) {
        float xk = xs[kb + k];
        uint4 w = wt[(size_t)(kb + k) * 32 + oct];
        float2 f0 = __half22float2(*(const __half2*)&w.x);
        float2 f1 = __half22float2(*(const __half2*)&w.y);
        float2 f2 = __half22float2(*(const __half2*)&w.z);
        float2 f3 = __half22float2(*(const __half2*)&w.w);
        a0.x = fmaf(xk, f0.x, a0.x); a0.y = fmaf(xk, f0.y, a0.y);
        a0.z = fmaf(xk, f1.x, a0.z); a0.w = fmaf(xk, f1.y, a0.w);
        a1.x = fmaf(xk, f2.x, a1.x); a1.y = fmaf(xk, f2.y, a1.y);
        a1.z = fmaf(xk, f3.x, a1.z); a1.w = fmaf(xk, f3.y, a1.w);
    }
    if (ks > 0) {
        pbuf[(ks - 1) * 64 + oct * 2 + 0] = a0;
        pbuf[(ks - 1) * 64 + oct * 2 + 1] = a1;
    }
    __syncthreads();
    if (ks == 0) {
        #pragma unroll
        for (int p = 0; p < 15; p++) {
            float4 b0 = pbuf[p * 64 + oct * 2 + 0];
            float4 b1 = pbuf[p * 64 + oct * 2 + 1];
            a0.x += b0.x; a0.y += b0.y; a0.z += b0.z; a0.w += b0.w;
            a1.x += b1.x; a1.y += b1.y; a1.z += b1.z; a1.w += b1.w;
        }
        float4 bb0 = *(const float4*)&Bb[oct * 8];
        float4 bb1 = *(const float4*)&Bb[oct * 8 + 4];
        a0.x += bb0.x; a0.y += bb0.y; a0.z += bb0.z; a0.w += bb0.w;
        a1.x += bb1.x; a1.y += bb1.y; a1.z += bb1.z; a1.w += bb1.w;
        *(float4*)&outv[oct * 8]     = a0;
        *(float4*)&outv[oct * 8 + 4] = a1;
    }
    __syncthreads();
}

__device__ void mvT_256to256_h(const float* __restrict__ xs, const __half* __restrict__ WT,
                               const float* __restrict__ Bb, float* __restrict__ outv,
                               float4* pbuf)
{
    int t = threadIdx.x;
    int oct = t & 31;
    int ks  = t >> 5;               // 0..15
    const uint4* wt = (const uint4*)WT;   // row stride 32 uint4
    float4 a0 = {0.f,0.f,0.f,0.f}, a1 = {0.f,0.f,0.f,0.f};
    int kb = ks * 16;
    #pragma unroll 8
    for (int k = 0; k < 16; k++) {
        float xk = xs[kb + k];
        uint4 w = wt[(size_t)(kb + k) * 32 + oct];
        float2 f0 = __half22float2(*(const __half2*)&w.x);
        float2 f1 = __half22float2(*(const __half2*)&w.y);
        float2 f2 = __half22float2(*(const __half2*)&w.z);
        float2 f3 = __half22float2(*(const __half2*)&w.w);
        a0.x = fmaf(xk, f0.x, a0.x); a0.y = fmaf(xk, f0.y, a0.y);
        a0.z = fmaf(xk, f1.x, a0.z); a0.w = fmaf(xk, f1.y, a0.w);
        a1.x = fmaf(xk, f2.x, a1.x); a1.y = fmaf(xk, f2.y, a1.y);
        a1.z = fmaf(xk, f3.x, a1.z); a1.w = fmaf(xk, f3.y, a1.w);
    }
    if (ks > 0) {
        pbuf[(ks - 1) * 64 + oct * 2 + 0] = a0;
        pbuf[(ks - 1) * 64 + oct * 2 + 1] = a1;
    }
    __syncthreads();
    if (ks == 0) {
        #pragma unroll
        for (int p = 0; p < 15; p++) {
            float4 b0 = pbuf[p * 64 + oct * 2 + 0];
            float4 b1 = pbuf[p * 64 + oct * 2 + 1];
            a0.x += b0.x; a0.y += b0.y; a0.z += b0.z; a0.w += b0.w;
            a1.x += b1.x; a1.y += b1.y; a1.z += b1.z; a1.w += b1.w;
        }
        float4 bb0 = *(const float4*)&Bb[oct * 8];
        float4 bb1 = *(const float4*)&Bb[oct * 8 + 4];
        a0.x += bb0.x; a0.y += bb0.y; a0.z += bb0.z; a0.w += bb0.w;
        a1.x += bb1.x; a1.y += bb1.y; a1.z += bb1.z; a1.w += bb1.w;
        *(float4*)&outv[oct * 8]     = a0;
        *(float4*)&outv[oct * 8 + 4] = a1;
    }
    __syncthreads();
}

// ---------------- residual add + LayerNorm (single-pass mean/var) ----------------
__device__ void resln_inblock(Smem* sm, int m, const float* __restrict__ lng,
                              const float* __restrict__ lnb, float* qsave)
{
    int t = threadIdx.x, lane = t & 31, w = t >> 5;
    float x = 0.f;
    if (t < 256) x = g_q[m * 256 + t] + sm->a.tmpv[t];

    float v1 = x, v2 = x * x;
    #pragma unroll
    for (int o = 16; o; o >>= 1) {
        v1 += __shfl_xor_sync(0xffffffffu, v1, o);
        v2 += __shfl_xor_sync(0xffffffffu, v2, o);
    }
    if (lane == 0) { sm->a.red[w] = v1; sm->a.red[w + 8] = v2; }
    __syncthreads();
    float s1 = 0.f, s2 = 0.f;
    #pragma unroll
    for (int kk = 0; kk < 8; kk++) { s1 += sm->a.red[kk]; s2 += sm->a.red[kk + 8]; }
    float mean = s1 * (1.0f / 256.0f);
    float var  = fmaxf(s2 * (1.0f / 256.0f) - mean * mean, 0.f);
    if (t < 256) {
        float r = (x - mean) * rsqrtf(var + 1e-5f) * lng[t] + lnb[t];
        g_q[m * 256 + t] = r;
        if (qsave) qsave[t] = r;
    }
    __syncthreads();
}

// ---------------- full attention for query m ----------------
__device__ void attn_full(Smem* sm, int m,
                          const __half* __restrict__ WoT, const float* __restrict__ bo,
                          const float* __restrict__ lng, const float* __restrict__ lnb,
                          float* qsave)
{
    int t = threadIdx.x, lane = t & 31, w = t >> 5;
    int h = w >> 1, part = w & 1;
    int jb = part * 64;

    if (t < 256) sm->a.q[t] = g_qh[m * 256 + t];
    __syncthreads();

    const float* kTh = g_kT + (h * 32) * NQ;
    float s0 = 0.f, s1 = 0.f;
    #pragma unroll
    for (int d = 0; d < 32; d++) {
        float qd = sm->a.q[h * 32 + d];
        s0 = fmaf(qd, kTh[d * NQ + jb + lane], s0);
        s1 = fmaf(qd, kTh[d * NQ + jb + 32 + lane], s1);
    }
    s0 *= 0.17677669529663687f;   // 1/sqrt(32)
    s1 *= 0.17677669529663687f;

    float mx = fmaxf(s0, s1);
    #pragma unroll
    for (int o = 16; o; o >>= 1) mx = fmaxf(mx, __shfl_xor_sync(0xffffffffu, mx, o));
    if (lane == 0) sm->a.mxp[w] = mx;
    __syncthreads();
    mx = fmaxf(sm->a.mxp[h * 2], sm->a.mxp[h * 2 + 1]);

    float e0 = expf(s0 - mx), e1 = expf(s1 - mx);
    float ps = warp_red(e0 + e1);
    if (lane == 0) sm->a.sump[w] = ps;
    __syncthreads();
    float inv = 1.0f / (sm->a.sump[h * 2] + sm->a.sump[h * 2 + 1]);

    sm->a.Ps[h * 128 + jb + lane]      = e0 * inv;
    sm->a.Ps[h * 128 + jb + 32 + lane] = e1 * inv;
    __syncthreads();

    float ov = 0.f;
    #pragma unroll 4
    for (int j = jb; j < jb + 64; j++)
        ov = fmaf(sm->a.Ps[h * 128 + j], g_vh[j * 256 + h * 32 + lane], ov);
    if (part == 1) sm->a.ovp[h * 32 + lane] = ov;
    __syncthreads();
    if (part == 0) sm->a.ao[h * 32 + lane] = ov + sm->a.ovp[h * 32 + lane];
    __syncthreads();

    mvT_256to256_h(sm->a.ao, WoT, bo, sm->a.tmpv, sm->a.pbuf);

    resln_inblock(sm, m, lng, lnb, qsave);
}

// ---------------- traj head stage 2 ----------------
__device__ void traj2_stage(Smem* sm, int m, const float* __restrict__ w2,
                            const float* __restrict__ b2, float* __restrict__ outp)
{
    int t = threadIdx.x, lane = t & 31, w = t >> 5;
    const float* hr = g_h + m * 512;
    if (w < 11) {
        const float4* h4 = (const float4*)hr;
        const float4* w4 = (const float4*)(w2 + w * 512);
        float s = dot4(h4[lane], w4[lane]) + dot4(h4[lane + 32], w4[lane + 32]) +
                  dot4(h4[lane + 64], w4[lane + 64]) + dot4(h4[lane + 96], w4[lane + 96]);
        s = warp_red(s);
        if (lane == 0) {
            float v = s + b2[w];
            sm->s.tp[w]      = v;
            outp[m * 11 + w] = v;
        }
    }
    __syncthreads();
}

// accumulate 16 fp8 channels (uint4) * dup'd half2 weight into 8 half2 accumulators
#define ACC16(va, q, wh) do {                                                   \
    va[0] = __hfma2(cvt8((unsigned short)(q).x),         (wh), va[0]);          \
    va[1] = __hfma2(cvt8((unsigned short)((q).x >> 16)), (wh), va[1]);          \
    va[2] = __hfma2(cvt8((unsigned short)(q).y),         (wh), va[2]);          \
    va[3] = __hfma2(cvt8((unsigned short)((q).y >> 16)), (wh), va[3]);          \
    va[4] = __hfma2(cvt8((unsigned short)(q).z),         (wh), va[4]);          \
    va[5] = __hfma2(cvt8((unsigned short)((q).z >> 16)), (wh), va[5]);          \
    va[6] = __hfma2(cvt8((unsigned short)(q).w),         (wh), va[6]);          \
    va[7] = __hfma2(cvt8((unsigned short)((q).w >> 16)), (wh), va[7]);          \
} while (0)

// ---------------- sampling for query m -> sm->s.agg (fp8 features) ----------------
__device__ void sample_stage(Smem* sm, int m, const float* __restrict__ calib,
                             const float* __restrict__ ego)
{
    int t = threadIdx.x;

    if (t < 12) {
        int ci = t % CAMSN, tt = t / CAMSN;
        float* d = sm->s.ctc[t];
        d[0] = ego[tt * 4 + 3] - ego[1 * 4 + 3];
        d[1] = ego[tt * 4 + 0];
        d[2] = ego[tt * 4 + 1];
        float eyaw = ego[tt * 4 + 2];
        d[3] = cosf(eyaw);
        d[4] = sinf(eyaw);
        const float* cal = calib + ci * 8;
        d[5]  = cal[0]; d[6]  = cal[1]; d[7]  = cal[2]; d[8] = cal[3];
        d[9]  = cal[4]; d[10] = cal[5]; d[11] = cal[6];
        d[12] = cosf(cal[7]);
        d[13] = sinf(cal[7]);
    } else if (t == 12) {
        float yaw = sm->s.tp[7];
        sm->s.cs[0] = cosf(yaw);
        sm->s.cs[1] = sinf(yaw);
    }
    __syncthreads();

    // Phase A: project 1800 taps (invalid -> row 0, weight 0); weights as dup'd half2
    for (int idx = t; idx < NTAPS; idx += NT) {
        int pt  = idx % NPTS;
        int ctc = idx / NPTS;
        int ci  = ctc % CAMSN;
        int tt  = ctc / CAMSN;
        const float* d = sm->s.ctc[tt * CAMSN + ci];
        float dt = d[0], ex = d[1], ey = d[2], ce = d[3], se = d[4];
        float fx = d[5], fy = d[6], cx0 = d[7], cy0 = d[8];
        float txc = d[9], tyc = d[10], tzc = d[11], cc = d[12], sc = d[13];

        int face = pt / 25, sub = pt % 25, dim = face >> 1;
        float sign = (face & 1) ? 1.0f : -1.0f;
        float a = -1.0f + 0.5f * (float)(sub / 5);
        float b = -1.0f + 0.5f * (float)(sub % 5);
        float ux, uy, uz;
        if (dim == 0)      { ux = sign; uy = a;    uz = b; }
        else if (dim == 1) { ux = a;    uy = sign; uz = b; }
        else               { ux = a;    uy = b;    uz = sign; }

        float lx = ux * sm->s.tp[8], ly = uy * sm->s.tp[9], lz = uz * sm->s.tp[10];
        float cyw = sm->s.cs[0], syw = sm->s.cs[1];
        float rx = lx * cyw - ly * syw;
        float ry = lx * syw + ly * cyw;
        float cx = sm->s.tp[0] + sm->s.tp[3] * dt + 0.5f * sm->s.tp[5] * dt * dt;
        float cy = sm->s.tp[1] + sm->s.tp[4] * dt + 0.5f * sm->s.tp[6] * dt * dt;
        float wx = rx + cx, wy = ry + cy, wz = lz + sm->s.tp[2];
        float pxr = wx - ex, pyr = wy - ey;
        float gx =  pxr * ce + pyr * se;
        float gy = -pxr * se + pyr * ce;

        float px = gx - txc, py = gy - tyc, pz = wz - tzc;
        float fwd  =  px * cc + py * sc;
        float left = -px * sc + py * cc;
        float zc = fwd, xc = -left, yc = -pz;
        float zs = fmaxf(zc, 0.1f);
        float u = fx * xc / zs + cx0;
        float v = fy * yc / zs + cy0;
        bool valid = (zc > 0.1f) && (u >= 0.f) && (u < 1.f) && (v >= 0.f) && (v < 1.f);

        uint4 wq = make_uint4(0u, 0u, 0u, 0u);
        int rowv = 0;
        if (valid) {
            float pxi = u * 159.0f;
            float pyi = v * 63.0f;
            float x0f = floorf(pxi), y0f = floorf(pyi);
            int x0 = (int)x0f, y0 = (int)y0f;
            float wxk = pxi - x0f, wyk = pyi - y0f;
            rowv = (ci * TSTEP + tt) * PLANE + y0 * WID + x0;
            __half2 h00 = __float2half2_rn((1.f - wxk) * (1.f - wyk));
            __half2 h01 = __float2half2_rn(wxk * (1.f - wyk));
            __half2 h10 = __float2half2_rn((1.f - wxk) * wyk);
            __half2 h11 = __float2half2_rn(wxk * wyk);
            wq.x = *(unsigned*)&h00;
            wq.y = *(unsigned*)&h01;
            wq.z = *(unsigned*)&h10;
            wq.w = *(unsigned*)&h11;
        }
        sm->s.row[idx] = rowv;
        sm->s.w[idx]   = wq;
    }
    __syncthreads();

    // Phase B: 32 half-warp groups; lane = 16 channels via uint4 (LDG.128, fp8),
    // half2 accumulation flushed to fp32 every 8 taps.
    int g = t >> 4;            // 0..31
    int l = t & 15;            // 16 channels: 16l .. 16l+15
    __half2 vacc[8];
    float   facc[16];
    #pragma unroll
    for (int j = 0; j < 8; j++)  vacc[j] = __float2half2_rn(0.f);
    #pragma unroll
    for (int j = 0; j < 16; j++) facc[j] = 0.f;

    const uint4* fb = (const uint4*)g_feat8;   // row stride = 256B/16 = 16 uint4
    int it = 0;
    #pragma unroll 2
    for (int i = g; i < NTAPS; i += 32, it++) {
        int row = sm->s.row[i];
        uint4 wq = sm->s.w[i];
        __half2 w00 = *(__half2*)&wq.x;
        __half2 w01 = *(__half2*)&wq.y;
        __half2 w10 = *(__half2*)&wq.z;
        __half2 w11 = *(__half2*)&wq.w;
        const uint4* p = fb + (size_t)row * 16 + l;
        uint4 q00 = p[0];
        uint4 q01 = p[16];
        uint4 q10 = p[WID * 16];
        uint4 q11 = p[WID * 16 + 16];
        ACC16(vacc, q00, w00);
        ACC16(vacc, q01, w01);
        ACC16(vacc, q10, w10);
        ACC16(vacc, q11, w11);
        if ((it & 7) == 7) {
            #pragma unroll
            for (int j = 0; j < 8; j++) {
                float2 f = __half22float2(vacc[j]);
                facc[2*j]   += f.x;
                facc[2*j+1] += f.y;
                vacc[j] = __float2half2_rn(0.f);
            }
        }
    }
    #pragma unroll
    for (int j = 0; j < 8; j++) {
        float2 f = __half22float2(vacc[j]);
        facc[2*j]   += f.x;
        facc[2*j+1] += f.y;
    }
    __syncthreads();   // all reads of w/row complete; safe to reuse as reduce buffer

    // deterministic tree reduce 32 -> 1 over the dead w/row smem region
    {
        float4* rbuf = (float4*)sm->s.w;
        const int offs[5] = {0, 1024, 1536, 1792, 1920};
        const int stp[5]  = {16, 8, 4, 2, 1};
        #pragma unroll
        for (int s = 0; s < 5; s++) {
            int st = stp[s];
            if (g >= st && g < 2 * st) {
                float4* dp = rbuf + offs[s] + (g - st) * 64 + l * 4;
                dp[0] = make_float4(facc[0],  facc[1],  facc[2],  facc[3]);
                dp[1] = make_float4(facc[4],  facc[5],  facc[6],  facc[7]);
                dp[2] = make_float4(facc[8],  facc[9],  facc[10], facc[11]);
                dp[3] = make_float4(facc[12], facc[13], facc[14], facc[15]);
            }
            __syncthreads();
            if (g < st) {
                const float4* sp = rbuf + offs[s] + g * 64 + l * 4;
                float4 b0 = sp[0], b1 = sp[1], b2 = sp[2], b3 = sp[3];
                facc[0]+=b0.x;  facc[1]+=b0.y;  facc[2]+=b0.z;  facc[3]+=b0.w;
                facc[4]+=b1.x;  facc[5]+=b1.y;  facc[6]+=b1.z;  facc[7]+=b1.w;
                facc[8]+=b2.x;  facc[9]+=b2.y;  facc[10]+=b2.z; facc[11]+=b2.w;
                facc[12]+=b3.x; facc[13]+=b3.y; facc[14]+=b3.z; facc[15]+=b3.w;
            }
        }
    }
    if (g == 0) {
        const float sc = 1.0f / 1800.0f;
        *(float4*)&sm->s.agg[l*16 + 0]  = make_float4(facc[0]*sc,  facc[1]*sc,  facc[2]*sc,  facc[3]*sc);
        *(float4*)&sm->s.agg[l*16 + 4]  = make_float4(facc[4]*sc,  facc[5]*sc,  facc[6]*sc,  facc[7]*sc);
        *(float4*)&sm->s.agg[l*16 + 8]  = make_float4(facc[8]*sc,  facc[9]*sc,  facc[10]*sc, facc[11]*sc);
        *(float4*)&sm->s.agg[l*16 + 12] = make_float4(facc[12]*sc, facc[13]*sc, facc[14]*sc, facc[15]*sc);
    }
    __syncthreads();
}

// ---------------- persistent mega-kernel ----------------
__global__ void __launch_bounds__(NT, 1)
decoder_kernel(const float* __restrict__ features, const float* __restrict__ calib,
               const float* __restrict__ ego, const float* __restrict__ queries,
               const float* __restrict__ tw1, const float* __restrict__ tb1,
               const float* __restrict__ tw2, const float* __restrict__ tb2,
               const float* __restrict__ fmw1, const float* __restrict__ fmb1,
               const float* __restrict__ fmw2, const float* __restrict__ fmb2,
               const float* __restrict__ saiw, const float* __restrict__ saib,
               const float* __restrict__ saow, const float* __restrict__ saob,
               const float* __restrict__ caiw, const float* __restrict__ caib,
               const float* __restrict__ caow, const float* __restrict__ caob,
               const float* __restrict__ l1w,  const float* __restrict__ l1b,
               const float* __restrict__ l2w,  const float* __restrict__ l2b,
               const float* __restrict__ n1g,  const float* __restrict__ n1b,
               const float* __restrict__ n2g,  const float* __restrict__ n2b,
               const float* __restrict__ n3g,  const float* __restrict__ n3b,
               float* __restrict__ out)
{
    __shared__ Smem sm;
    int m = blockIdx.x;
    int t = threadIdx.x;
    int half = t >> 8;
    int tl   = t & 255;
    int barid = half + 1;
    SmemGemm* sg = &sm.g2.h[half];

    // replay-safe relative barrier generation base
    unsigned bar0 = 0;
    if (t == 0)
        asm volatile("ld.acquire.gpu.global.u32 %0, [%1];" : "=r"(bar0) : "l"(&g_bar_gen));
    unsigned barcnt = 0;

    // prologue: copy queries (own row only); transpose features -> fp8; fp16 weight transposes
    if (t < 256) g_q[m * 256 + t] = queries[m * 256 + t];
    {
        const int PT = PLANE / 32;                   // 320
        const int CT = CFCH / 32;                    // 8
        const int NTILE = CAMSN * TSTEP * PT * CT;   // 30720
        int tx = t & 31, ty = t >> 5;                // 32 x 16
        int pc = t & 15, pp = t >> 4;                // 16 ch-pairs x 32 pixels
        for (int tile = blockIdx.x; tile < NTILE; tile += NB) {
            int ct  = tile / (PT * CT);
            int rem = tile % (PT * CT);
            int p0 = (rem % PT) * 32;
            int c0 = (rem / PT) * 32;
            const float* in = features + (size_t)ct * CFCH * PLANE;
            unsigned char* op = g_feat8 + (size_t)ct * CFCH * PLANE;
            #pragma unroll
            for (int i = 0; i < 32; i += 16)
                sm.t.tile[ty + i][tx] = in[(size_t)(c0 + ty + i) * PLANE + p0 + tx];
            __syncthreads();
            {
                float lo = sm.t.tile[2 * pc + 0][pp];
                float hi = sm.t.tile[2 * pc + 1][pp];
                unsigned short v = pack8(hi, lo);
                *(unsigned short*)(op + (size_t)(p0 + pp) * CFCH + c0 + 2 * pc) = v;
            }
            __syncthreads();
        }
    }
    wtransH(&sm, fmw1, g_fmw1T, 512, 256);
    wtransH(&sm, fmw2, g_fmw2T, 256, 512);
    for (int li = 0; li < 6; li++) {
        wtransH(&sm, saow + li * 65536,  g_saowT + li * 65536,  256, 256);
        wtransH(&sm, caow + li * 65536,  g_caowT + li * 65536,  256, 256);
        wtransH(&sm, l1w  + li * 131072, g_l1wT  + li * 131072, 512, 256);
        wtransH(&sm, l2w  + li * 131072, g_l2wT  + li * 131072, 256, 512);
    }
    // No grid sync here: layer-0 S1 reads `queries` + input weights only;
    // the post-S1 grid sync orders all prologue writes before S2.

    for (int li = 0; li < 6; li++) {
        const float* saiw_l = saiw + li * 768 * 256;
        const float* saib_l = saib + li * 768;
        const float* caiw_l = caiw + li * 768 * 256;
        const float* caib_l = caib + li * 768;
        const float* qsrc = (li == 0) ? queries : g_q;

        // ---- S1: GEMM: traj1 (64 tiles) + SA QKV (96 tiles), both read pre-SA q
        for (int tile = blockIdx.x * 2 + half; tile < 160; tile += 256) {
            if (tile < 64)
                gemm_tile<1,0>(sg, tl, barid, qsrc, tw1, tb1, g_h, 256, 512,
                               (tile & 7) * 16, (tile >> 3) * 64);
            else {
                int u = tile - 64;
                gemm_tile<0,1>(sg, tl, barid, qsrc, saiw_l, saib_l, nullptr, 256, 768,
                               (u & 7) * 16, (u >> 3) * 64);
            }
        }
        grid_sync(bar0, barcnt);

        // ---- S2 per-query: SA attn + traj2 + sampling + feature MLP -> g_mem[m]
        attn_full(&sm, m, g_saowT + li * 65536, saob + li * 256,
                  n1g + li * 256, n1b + li * 256, nullptr);
        traj2_stage(&sm, m, tw2, tb2, out + li * 1408);
        sample_stage(&sm, m, calib, ego);
        mvT_256to512_h(sm.s.agg, g_fmw1T, fmb1, sm.s.h, sm.a.pbuf);
        mvT_512to256_h(sm.s.h, g_fmw2T, fmb2, g_mem + m * 256, sm.a.pbuf);
        grid_sync(bar0, barcnt);

        // ---- S3: GEMM: CA q-proj (32 tiles, g_q) + CA kv-proj (64 tiles, g_mem)
        for (int tile = blockIdx.x * 2 + half; tile < 96; tile += 256) {
            if (tile < 32)
                gemm_tile<0,1>(sg, tl, barid, g_q, caiw_l, caib_l, nullptr, 256, 768,
                               (tile & 7) * 16, (tile >> 3) * 64);
            else {
                int u = tile - 32;
                gemm_tile<0,1>(sg, tl, barid, g_mem, caiw_l, caib_l, nullptr, 256, 768,
                               (u & 7) * 16, 256 + (u >> 3) * 64);
            }
        }
        grid_sync(bar0, barcnt);

        // ---- S4 per-query: CA attn (+resln2, save qrow) + FFN + resln3
        attn_full(&sm, m, g_caowT + li * 65536, caob + li * 256,
                  n2g + li * 256, n2b + li * 256, sm.s.agg);
        mvT_256to512_h(sm.s.agg, g_l1wT + li * 131072, l1b + li * 512, sm.s.h, sm.a.pbuf);
        mvT_512to256_h(sm.s.h, g_l2wT + li * 131072, l2b + li * 256, sm.a.tmpv, sm.a.pbuf);
        resln_inblock(&sm, m, n3g + li * 256, n3b + li * 256, nullptr);
        grid_sync(bar0, barcnt);
    }

    // epilogue: final traj head
    for (int tile = blockIdx.x * 2 + half; tile < 64; tile += 256)
        gemm_tile<1,0>(sg, tl, barid, g_q, tw1, tb1, g_h, 256, 512,
                       (tile & 7) * 16, (tile >> 3) * 64);
    grid_sync(bar0, barcnt);
    traj2_stage(&sm, m, tw2, tb2, out + 6 * 1408);
}

// ---------------- host: one launch ----------------
extern "C" void kernel_launch(void* const* d_in, const int* in_sizes, int n_in,
                              void* d_out, int out_size)
{
    const float* features = (const float*)d_in[0];
    const float* calib    = (const float*)d_in[1];
    const float* ego      = (const float*)d_in[2];
    const float* queries  = (const float*)d_in[3];
    const float* tw1  = (const float*)d_in[5];
    const float* tb1  = (const float*)d_in[6];
    const float* tw2  = (const float*)d_in[7];
    const float* tb2  = (const float*)d_in[8];
    const float* fmw1 = (const float*)d_in[9];
    const float* fmb1 = (const float*)d_in[10];
    const float* fmw2 = (const float*)d_in[11];
    const float* fmb2 = (const float*)d_in[12];
    const float* saiw = (const float*)d_in[13];
    const float* saib = (const float*)d_in[14];
    const float* saow = (const float*)d_in[15];
    const float* saob = (const float*)d_in[16];
    const float* caiw = (const float*)d_in[17];
    const float* caib = (const float*)d_in[18];
    const float* caow = (const float*)d_in[19];
    const float* caob = (const float*)d_in[20];
    const float* l1w  = (const float*)d_in[21];
    const float* l1b  = (const float*)d_in[22];
    const float* l2w  = (const float*)d_in[23];
    const float* l2b  = (const float*)d_in[24];
    const float* n1g  = (const float*)d_in[25];
    const float* n1b  = (const float*)d_in[26];
    const float* n2g  = (const float*)d_in[27];
    const float* n2b  = (const float*)d_in[28];
    const float* n3g  = (const float*)d_in[29];
    const float* n3b  = (const float*)d_in[30];
    float* out = (float*)d_out;

    decoder_kernel<<<NB, NT>>>(features, calib, ego, queries,
                               tw1, tb1, tw2, tb2,
                               fmw1, fmb1, fmw2, fmb2,
                               saiw, saib, saow, saob,
                               caiw, caib, caow, caob,
                               l1w, l1b, l2w, l2b,
                               n1g, n1b, n2g, n2b, n3g, n3b,
                               out);
}